// round 8
// baseline (speedup 1.0000x reference)
#include <cuda_runtime.h>
#include <cuda_bf16.h>
#include <cstdint>

#define EMB  1024
#define NH   16
#define DH   64
#define BSZ  4
#define SEQ  2048
#define MROWS (BSZ*SEQ)   // 8192
#define NCOLS (NH*DH)     // 1024

// ---------------- scratch (allocation-guard safe) ----------------
__device__ __nv_bfloat16 g_xq_hi[(size_t)MROWS*EMB];
__device__ __nv_bfloat16 g_xq_lo[(size_t)MROWS*EMB];
__device__ __nv_bfloat16 g_xkv_hi[(size_t)MROWS*EMB];
__device__ __nv_bfloat16 g_xkv_lo[(size_t)MROWS*EMB];
__device__ __nv_bfloat16 g_wq_hi[(size_t)NCOLS*EMB];
__device__ __nv_bfloat16 g_wq_lo[(size_t)NCOLS*EMB];
__device__ __nv_bfloat16 g_wk_hi[(size_t)NCOLS*EMB];
__device__ __nv_bfloat16 g_wk_lo[(size_t)NCOLS*EMB];
__device__ __nv_bfloat16 g_wv_hi[(size_t)NCOLS*EMB];
__device__ __nv_bfloat16 g_wv_lo[(size_t)NCOLS*EMB];

// projected Q/K/V as bf16 hi/lo, layout [b,h,s,d]
__device__ __nv_bfloat16 g_qh[(size_t)BSZ*NH*SEQ*DH];
__device__ __nv_bfloat16 g_ql[(size_t)BSZ*NH*SEQ*DH];
__device__ __nv_bfloat16 g_kh[(size_t)BSZ*NH*SEQ*DH];
__device__ __nv_bfloat16 g_kl[(size_t)BSZ*NH*SEQ*DH];
__device__ __nv_bfloat16 g_vh[(size_t)BSZ*NH*SEQ*DH];
__device__ __nv_bfloat16 g_vl[(size_t)BSZ*NH*SEQ*DH];

// ---------------- helpers (base sm_103-safe ISA only) ----------------
__device__ __forceinline__ uint32_t smem_u32(const void* p) {
    uint32_t a;
    asm("{ .reg .u64 t; cvta.to.shared.u64 t, %1; cvt.u32.u64 %0, t; }" : "=r"(a) : "l"(p));
    return a;
}
__device__ __forceinline__ void ldsm4(uint32_t* r, uint32_t addr) {
    asm volatile("ldmatrix.sync.aligned.m8n8.x4.shared.b16 {%0,%1,%2,%3}, [%4];"
                 : "=r"(r[0]), "=r"(r[1]), "=r"(r[2]), "=r"(r[3]) : "r"(addr));
}
__device__ __forceinline__ void ldsm4t(uint32_t* r, uint32_t addr) {
    asm volatile("ldmatrix.sync.aligned.m8n8.x4.trans.shared.b16 {%0,%1,%2,%3}, [%4];"
                 : "=r"(r[0]), "=r"(r[1]), "=r"(r[2]), "=r"(r[3]) : "r"(addr));
}
__device__ __forceinline__ void mma_bf16(float* c, const uint32_t* a, uint32_t b0, uint32_t b1) {
    asm volatile("mma.sync.aligned.m16n8k16.row.col.f32.bf16.bf16.f32 "
                 "{%0,%1,%2,%3}, {%4,%5,%6,%7}, {%8,%9}, {%0,%1,%2,%3};"
                 : "+f"(c[0]), "+f"(c[1]), "+f"(c[2]), "+f"(c[3])
                 : "r"(a[0]), "r"(a[1]), "r"(a[2]), "r"(a[3]), "r"(b0), "r"(b1));
}
__device__ __forceinline__ void cp_async16(uint32_t saddr, const void* gptr) {
    asm volatile("cp.async.cg.shared.global [%0], [%1], 16;" :: "r"(saddr), "l"(gptr) : "memory");
}
#define CP_COMMIT() asm volatile("cp.async.commit_group;" ::: "memory")
#define CP_WAIT1()  asm volatile("cp.async.wait_group 1;" ::: "memory")
#define CP_WAIT0()  asm volatile("cp.async.wait_group 0;" ::: "memory")

// split a float pair into packed bf16x2 hi and lo words
__device__ __forceinline__ void split2(float a, float b, uint32_t& hi, uint32_t& lo) {
    __nv_bfloat162 H, L;
    H.x = __float2bfloat16(a);
    H.y = __float2bfloat16(b);
    L.x = __float2bfloat16(a - __bfloat162float(H.x));
    L.y = __float2bfloat16(b - __bfloat162float(H.y));
    hi = *reinterpret_cast<uint32_t*>(&H);
    lo = *reinterpret_cast<uint32_t*>(&L);
}

// ---------------- split fp32 -> bf16 hi/lo (inputs) ----------------
__global__ __launch_bounds__(256) void split_kernel(const float* __restrict__ src,
                                                    __nv_bfloat16* __restrict__ hi,
                                                    __nv_bfloat16* __restrict__ lo,
                                                    int n4)
{
    int i = blockIdx.x * blockDim.x + threadIdx.x;
    if (i >= n4) return;
    float4 x = ((const float4*)src)[i];
    uint32_t h0, l0, h1, l1;
    split2(x.x, x.y, h0, l0);
    split2(x.z, x.w, h1, l1);
    ((uint32_t*)hi)[i * 2 + 0] = h0;
    ((uint32_t*)hi)[i * 2 + 1] = h1;
    ((uint32_t*)lo)[i * 2 + 0] = l0;
    ((uint32_t*)lo)[i * 2 + 1] = l1;
}

// ---------------- HMMA projection GEMM ----------------
// C[128x128] = X*W^T (split bf16, 3 passes), 2-stage cp.async double buffer.
// 512 threads, 16 warps, warp tile 32x32 -> ~90 regs/thread, 4 warps/SMSP.
#define BK      32
#define SKB     80
#define MAT_B   (128 * SKB)
#define OFF_AHI 0
#define OFF_ALO (MAT_B)
#define OFF_BHI (2 * MAT_B)
#define OFF_BLO (3 * MAT_B)
#define STAGE_B (4 * MAT_B)
#define PROJ_SMEM (2 * STAGE_B)       // 81920

__global__ __launch_bounds__(512) void proj_hmma(const __nv_bfloat16* __restrict__ Ahi,
                                                 const __nv_bfloat16* __restrict__ Alo,
                                                 const __nv_bfloat16* __restrict__ Bhi,
                                                 const __nv_bfloat16* __restrict__ Blo,
                                                 const float* __restrict__ bias,
                                                 __nv_bfloat16* __restrict__ DstH,
                                                 __nv_bfloat16* __restrict__ DstL,
                                                 float scale)
{
    extern __shared__ char smem[];
    const uint32_t sb = smem_u32(smem);
    const int t    = threadIdx.x;
    const int lane = t & 31;
    const int wid  = t >> 5;          // 0..15
    const int wm   = wid & 3;         // 4 warps along M (32 rows each)
    const int wn   = wid >> 2;        // 4 warps along N (32 cols each)
    const int n0   = blockIdx.x * 128;
    const int m0   = blockIdx.y * 128;

    // loader: 512 threads, one 16B chunk per matrix per thread: row=t>>2, part=t&3
    const int cr = t >> 2, cp = t & 3;

    const uint32_t aRow = (uint32_t)((wm * 32 + (lane & 15)) * SKB + (lane >> 4) * 16);
    const uint32_t bRow = (uint32_t)((wn * 32 + (((lane >> 4) << 3) | (lane & 7))) * SKB
                                     + ((lane >> 3) & 1) * 16);

    float acc[2][4][4] = {};
    const int NSTAGE = EMB / BK;

    auto issue = [&](int s) {
        const int k0 = s * BK;
        const uint32_t buf = sb + (uint32_t)(s & 1) * STAGE_B;
        uint32_t so = (uint32_t)(cr * SKB + cp * 16);
        size_t ga = (size_t)(m0 + cr) * EMB + k0 + cp * 8;
        size_t gb = (size_t)(n0 + cr) * EMB + k0 + cp * 8;
        cp_async16(buf + OFF_AHI + so, Ahi + ga);
        cp_async16(buf + OFF_ALO + so, Alo + ga);
        cp_async16(buf + OFF_BHI + so, Bhi + gb);
        cp_async16(buf + OFF_BLO + so, Blo + gb);
        CP_COMMIT();
    };

    issue(0);
    issue(1);

    for (int s = 0; s < NSTAGE; s++) {
        if (s + 1 < NSTAGE) { CP_WAIT1(); } else { CP_WAIT0(); }
        __syncthreads();
        const uint32_t buf = sb + (uint32_t)(s & 1) * STAGE_B;

#pragma unroll
        for (int kc = 0; kc < BK; kc += 16) {
            uint32_t aH[2][4], aL[2][4], bH[2][4], bL[2][4];
#pragma unroll
            for (int mt = 0; mt < 2; mt++) {
                uint32_t off = aRow + (uint32_t)(mt * 16 * SKB + kc * 2);
                ldsm4(aH[mt], buf + OFF_AHI + off);
                ldsm4(aL[mt], buf + OFF_ALO + off);
            }
#pragma unroll
            for (int g = 0; g < 2; g++) {
                uint32_t off = bRow + (uint32_t)(g * 16 * SKB + kc * 2);
                ldsm4(bH[g], buf + OFF_BHI + off);
                ldsm4(bL[g], buf + OFF_BLO + off);
            }
#pragma unroll
            for (int mt = 0; mt < 2; mt++)
#pragma unroll
                for (int nt = 0; nt < 4; nt++)
                    mma_bf16(acc[mt][nt], aH[mt], bH[nt >> 1][(nt & 1) * 2], bH[nt >> 1][(nt & 1) * 2 + 1]);
#pragma unroll
            for (int mt = 0; mt < 2; mt++)
#pragma unroll
                for (int nt = 0; nt < 4; nt++)
                    mma_bf16(acc[mt][nt], aH[mt], bL[nt >> 1][(nt & 1) * 2], bL[nt >> 1][(nt & 1) * 2 + 1]);
#pragma unroll
            for (int mt = 0; mt < 2; mt++)
#pragma unroll
                for (int nt = 0; nt < 4; nt++)
                    mma_bf16(acc[mt][nt], aL[mt], bH[nt >> 1][(nt & 1) * 2], bH[nt >> 1][(nt & 1) * 2 + 1]);
        }

        __syncthreads();
        if (s + 2 < NSTAGE) issue(s + 2);
    }

    // epilogue: (acc + bias) * scale -> bf16 hi/lo into [b,h,s,d]
    const int rbase = lane >> 2;
    const int cbase = (lane & 3) * 2;
#pragma unroll
    for (int mt = 0; mt < 2; mt++) {
#pragma unroll
        for (int half = 0; half < 2; half++) {
            const int m = m0 + wm * 32 + mt * 16 + rbase + half * 8;
            const int b = m >> 11;
            const int sdx = m & (SEQ - 1);
#pragma unroll
            for (int nt = 0; nt < 4; nt++) {
                const int n = n0 + wn * 32 + nt * 8 + cbase;
                const int h = n >> 6;
                const int d = n & 63;
                float fx = (acc[mt][nt][half * 2 + 0] + bias[n + 0]) * scale;
                float fy = (acc[mt][nt][half * 2 + 1] + bias[n + 1]) * scale;
                uint32_t hw, lw;
                split2(fx, fy, hw, lw);
                size_t o = (((size_t)(b * NH + h)) * SEQ + sdx) * DH + d;
                *(uint32_t*)(DstH + o) = hw;
                *(uint32_t*)(DstL + o) = lw;
            }
        }
    }
}

// ---------------- HMMA causal flash attention (R5 config) ----------------
#define ASTR   144
#define AQ_B   (128 * ASTR)
#define AKV_B  (64 * ASTR)
#define AOFF_KH 0
#define AOFF_KL (AKV_B)
#define AOFF_VH (2 * AKV_B)
#define AOFF_VL (3 * AKV_B)
#define AKV_STAGE (4 * AKV_B)
#define AKV_OFF (2 * AQ_B)
#define ATTN_SMEM (2 * AQ_B + 2 * AKV_STAGE)  // 110592

__global__ __launch_bounds__(256) void attn_hmma(const __nv_bfloat16* __restrict__ Qh,
                                                 const __nv_bfloat16* __restrict__ Ql,
                                                 const __nv_bfloat16* __restrict__ Kh,
                                                 const __nv_bfloat16* __restrict__ Kl,
                                                 const __nv_bfloat16* __restrict__ Vh,
                                                 const __nv_bfloat16* __restrict__ Vl,
                                                 float* __restrict__ out)
{
    extern __shared__ char smem[];
    const uint32_t sb = smem_u32(smem);
    const int t    = threadIdx.x;
    const int lane = t & 31;
    const int wid  = t >> 5;
    const int qb   = blockIdx.x;
    const int bh   = blockIdx.y;
    const int q0   = qb * 128;

    const size_t base = (size_t)bh * SEQ * DH;
    const __nv_bfloat16* qh = Qh + base;
    const __nv_bfloat16* ql = Ql + base;
    const __nv_bfloat16* kh = Kh + base;
    const __nv_bfloat16* kl = Kl + base;
    const __nv_bfloat16* vh = Vh + base;
    const __nv_bfloat16* vl = Vl + base;

    // Q tiles -> smem
#pragma unroll
    for (int i = 0; i < 4; i++) {
        int id = t + i * 256;
        int row = id >> 3, part = id & 7;
        size_t g = (size_t)(q0 + row) * DH + part * 8;
        uint32_t so = (uint32_t)(row * ASTR + part * 16);
        cp_async16(sb + so, qh + g);
        cp_async16(sb + AQ_B + so, ql + g);
    }
    CP_COMMIT();

    auto issueKV = [&](int kb) {
        const uint32_t buf = sb + AKV_OFF + (uint32_t)(kb & 1) * AKV_STAGE;
        const int k0 = kb * 64;
#pragma unroll
        for (int i = 0; i < 2; i++) {
            int id = t + i * 256;
            int row = id >> 3, part = id & 7;
            size_t g = (size_t)(k0 + row) * DH + part * 8;
            uint32_t so = (uint32_t)(row * ASTR + part * 16);
            cp_async16(buf + AOFF_KH + so, kh + g);
            cp_async16(buf + AOFF_KL + so, kl + g);
            cp_async16(buf + AOFF_VH + so, vh + g);
            cp_async16(buf + AOFF_VL + so, vl + g);
        }
        CP_COMMIT();
    };

    const int nkb = 2 * qb + 2;
    issueKV(0);
    issueKV(1);

    CP_WAIT1();
    __syncthreads();
    uint32_t qhF[4][4], qlF[4][4];
    {
        const uint32_t aRow = (uint32_t)((wid * 16 + (lane & 15)) * ASTR + (lane >> 4) * 16);
#pragma unroll
        for (int kt = 0; kt < 4; kt++) {
            ldsm4(qhF[kt], sb + aRow + kt * 32);
            ldsm4(qlF[kt], sb + AQ_B + aRow + kt * 32);
        }
    }

    float m0r = -1e30f, m1r = -1e30f, l0r = 0.f, l1r = 0.f;
    float o[8][4] = {};

    const uint32_t kLane = (uint32_t)(((((lane >> 4) << 3) | (lane & 7)) * ASTR) + ((lane >> 3) & 1) * 16);
    const uint32_t vLane = (uint32_t)(((((lane >> 3) & 1) * 8 + (lane & 7)) * ASTR) + ((lane >> 4) & 1) * 16);

    for (int kb = 0; kb < nkb; kb++) {
        if (kb + 1 < nkb) { CP_WAIT1(); } else { CP_WAIT0(); }
        __syncthreads();
        const uint32_t buf = sb + AKV_OFF + (uint32_t)(kb & 1) * AKV_STAGE;
        const int k0 = kb * 64;

        // ---- S = Q K^T (split, 3 passes) ----
        float s[8][4] = {};
#pragma unroll
        for (int kt = 0; kt < 4; kt++) {
            uint32_t kh4[4][4], kl4[4][4];
#pragma unroll
            for (int g = 0; g < 4; g++) {
                uint32_t off = kLane + (uint32_t)(g * 16 * ASTR + kt * 32);
                ldsm4(kh4[g], buf + AOFF_KH + off);
                ldsm4(kl4[g], buf + AOFF_KL + off);
            }
#pragma unroll
            for (int g = 0; g < 4; g++)
#pragma unroll
                for (int hf = 0; hf < 2; hf++) {
                    int nt = g * 2 + hf;
                    mma_bf16(s[nt], qhF[kt], kh4[g][hf * 2], kh4[g][hf * 2 + 1]);
                    mma_bf16(s[nt], qhF[kt], kl4[g][hf * 2], kl4[g][hf * 2 + 1]);
                    mma_bf16(s[nt], qlF[kt], kh4[g][hf * 2], kh4[g][hf * 2 + 1]);
                }
        }

        // ---- causal mask ----
        if (k0 + 63 > q0 + wid * 16) {
            const int r0 = q0 + wid * 16 + (lane >> 2);
            const int r1 = r0 + 8;
#pragma unroll
            for (int nt = 0; nt < 8; nt++) {
                const int c = k0 + nt * 8 + (lane & 3) * 2;
                if (c > r0)     s[nt][0] = -1e30f;
                if (c + 1 > r0) s[nt][1] = -1e30f;
                if (c > r1)     s[nt][2] = -1e30f;
                if (c + 1 > r1) s[nt][3] = -1e30f;
            }
        }

        // ---- online softmax ----
        float mx0 = s[0][0], mx1 = s[0][2];
#pragma unroll
        for (int nt = 0; nt < 8; nt++) {
            mx0 = fmaxf(mx0, fmaxf(s[nt][0], s[nt][1]));
            mx1 = fmaxf(mx1, fmaxf(s[nt][2], s[nt][3]));
        }
        mx0 = fmaxf(mx0, __shfl_xor_sync(0xffffffff, mx0, 1));
        mx0 = fmaxf(mx0, __shfl_xor_sync(0xffffffff, mx0, 2));
        mx1 = fmaxf(mx1, __shfl_xor_sync(0xffffffff, mx1, 1));
        mx1 = fmaxf(mx1, __shfl_xor_sync(0xffffffff, mx1, 2));
        const float mn0 = fmaxf(m0r, mx0), mn1 = fmaxf(m1r, mx1);
        const float a0 = __expf(m0r - mn0), a1 = __expf(m1r - mn1);
        m0r = mn0; m1r = mn1;
        float sum0 = 0.f, sum1 = 0.f;
#pragma unroll
        for (int nt = 0; nt < 8; nt++) {
            s[nt][0] = __expf(s[nt][0] - mn0); sum0 += s[nt][0];
            s[nt][1] = __expf(s[nt][1] - mn0); sum0 += s[nt][1];
            s[nt][2] = __expf(s[nt][2] - mn1); sum1 += s[nt][2];
            s[nt][3] = __expf(s[nt][3] - mn1); sum1 += s[nt][3];
        }
        sum0 += __shfl_xor_sync(0xffffffff, sum0, 1);
        sum0 += __shfl_xor_sync(0xffffffff, sum0, 2);
        sum1 += __shfl_xor_sync(0xffffffff, sum1, 1);
        sum1 += __shfl_xor_sync(0xffffffff, sum1, 2);
        l0r = l0r * a0 + sum0;
        l1r = l1r * a1 + sum1;
#pragma unroll
        for (int n = 0; n < 8; n++) {
            o[n][0] *= a0; o[n][1] *= a0;
            o[n][2] *= a1; o[n][3] *= a1;
        }

        // ---- O += P V (split, 3 passes) ----
#pragma unroll
        for (int kt = 0; kt < 4; kt++) {
            uint32_t ph[4], pl[4];
            const int nt0 = kt * 2, nt1 = kt * 2 + 1;
            split2(s[nt0][0], s[nt0][1], ph[0], pl[0]);
            split2(s[nt0][2], s[nt0][3], ph[1], pl[1]);
            split2(s[nt1][0], s[nt1][1], ph[2], pl[2]);
            split2(s[nt1][2], s[nt1][3], ph[3], pl[3]);
#pragma unroll
            for (int g = 0; g < 4; g++) {
                uint32_t vh4[4], vl4[4];
                uint32_t off = vLane + (uint32_t)(kt * 16 * ASTR + g * 32);
                ldsm4t(vh4, buf + AOFF_VH + off);
                ldsm4t(vl4, buf + AOFF_VL + off);
#pragma unroll
                for (int hf = 0; hf < 2; hf++) {
                    int n = g * 2 + hf;
                    mma_bf16(o[n], ph, vh4[hf * 2], vh4[hf * 2 + 1]);
                    mma_bf16(o[n], ph, vl4[hf * 2], vl4[hf * 2 + 1]);
                    mma_bf16(o[n], pl, vh4[hf * 2], vh4[hf * 2 + 1]);
                }
            }
        }

        __syncthreads();
        if (kb + 2 < nkb) issueKV(kb + 2);
    }

    // ---- epilogue ----
    const int b  = bh >> 4;
    const int h  = bh & 15;
    const int r0 = q0 + wid * 16 + (lane >> 2);
    const int r1 = r0 + 8;
    const float i0 = 1.f / l0r, i1 = 1.f / l1r;
#pragma unroll
    for (int n = 0; n < 8; n++) {
        const int d = n * 8 + (lane & 3) * 2;
        *(float2*)(out + ((size_t)(b * SEQ + r0)) * NCOLS + h * DH + d) =
            make_float2(o[n][0] * i0, o[n][1] * i0);
        *(float2*)(out + ((size_t)(b * SEQ + r1)) * NCOLS + h * DH + d) =
            make_float2(o[n][2] * i1, o[n][3] * i1);
    }
}

// ---------------------------------------------------------------------------
extern "C" void kernel_launch(void* const* d_in, const int* in_sizes, int n_in,
                              void* d_out, int out_size)
{
    const float* x_q  = (const float*)d_in[0];
    const float* x_kv = (const float*)d_in[1];
    const float* w_q  = (const float*)d_in[3];
    const float* b_q  = (const float*)d_in[4];
    const float* w_k  = (const float*)d_in[5];
    const float* b_k  = (const float*)d_in[6];
    const float* w_v  = (const float*)d_in[7];
    const float* b_v  = (const float*)d_in[8];
    float* out = (float*)d_out;

    __nv_bfloat16 *xqh, *xql, *xkh, *xkl;
    __nv_bfloat16 *wqh, *wql, *wkh, *wkl, *wvh, *wvl;
    __nv_bfloat16 *qhp, *qlp, *khp, *klp, *vhp, *vlp;
    cudaGetSymbolAddress((void**)&xqh, g_xq_hi);
    cudaGetSymbolAddress((void**)&xql, g_xq_lo);
    cudaGetSymbolAddress((void**)&xkh, g_xkv_hi);
    cudaGetSymbolAddress((void**)&xkl, g_xkv_lo);
    cudaGetSymbolAddress((void**)&wqh, g_wq_hi);
    cudaGetSymbolAddress((void**)&wql, g_wq_lo);
    cudaGetSymbolAddress((void**)&wkh, g_wk_hi);
    cudaGetSymbolAddress((void**)&wkl, g_wk_lo);
    cudaGetSymbolAddress((void**)&wvh, g_wv_hi);
    cudaGetSymbolAddress((void**)&wvl, g_wv_lo);
    cudaGetSymbolAddress((void**)&qhp, g_qh);
    cudaGetSymbolAddress((void**)&qlp, g_ql);
    cudaGetSymbolAddress((void**)&khp, g_kh);
    cudaGetSymbolAddress((void**)&klp, g_kl);
    cudaGetSymbolAddress((void**)&vhp, g_vh);
    cudaGetSymbolAddress((void**)&vlp, g_vl);

    cudaFuncSetAttribute(proj_hmma, cudaFuncAttributeMaxDynamicSharedMemorySize, PROJ_SMEM);
    cudaFuncSetAttribute(attn_hmma, cudaFuncAttributeMaxDynamicSharedMemorySize, ATTN_SMEM);

    const int nX4 = MROWS * EMB / 4;
    const int nW4 = NCOLS * EMB / 4;
    split_kernel<<<(nX4 + 255) / 256, 256>>>(x_q,  xqh, xql, nX4);
    split_kernel<<<(nX4 + 255) / 256, 256>>>(x_kv, xkh, xkl, nX4);
    split_kernel<<<(nW4 + 255) / 256, 256>>>(w_q,  wqh, wql, nW4);
    split_kernel<<<(nW4 + 255) / 256, 256>>>(w_k,  wkh, wkl, nW4);
    split_kernel<<<(nW4 + 255) / 256, 256>>>(w_v,  wvh, wvl, nW4);

    dim3 pgrid(NCOLS / 128, MROWS / 128);   // (8, 64)
    proj_hmma<<<pgrid, 512, PROJ_SMEM>>>(xqh, xql, wqh, wql, b_q, qhp, qlp, 0.125f);
    proj_hmma<<<pgrid, 512, PROJ_SMEM>>>(xkh, xkl, wkh, wkl, b_k, khp, klp, 1.0f);
    proj_hmma<<<pgrid, 512, PROJ_SMEM>>>(xkh, xkl, wvh, wvl, b_v, vhp, vlp, 1.0f);

    dim3 agrid(SEQ / 128, BSZ * NH);        // (16, 64)
    attn_hmma<<<agrid, 256, ATTN_SMEM>>>(qhp, qlp, khp, klp, vhp, vlp, out);
}

// round 10
// speedup vs baseline: 1.6515x; 1.6515x over previous
#include <cuda_runtime.h>
#include <cuda_bf16.h>
#include <cstdint>

#define EMB  1024
#define NH   16
#define DH   64
#define BSZ  4
#define SEQ  2048
#define MROWS (BSZ*SEQ)   // 8192
#define NCOLS (NH*DH)     // 1024

// ---------------- scratch (allocation-guard safe) ----------------
__device__ __nv_bfloat16 g_xq_hi[(size_t)MROWS*EMB];
__device__ __nv_bfloat16 g_xq_lo[(size_t)MROWS*EMB];
__device__ __nv_bfloat16 g_xkv_hi[(size_t)MROWS*EMB];
__device__ __nv_bfloat16 g_xkv_lo[(size_t)MROWS*EMB];
__device__ __nv_bfloat16 g_wq_hi[(size_t)NCOLS*EMB];
__device__ __nv_bfloat16 g_wq_lo[(size_t)NCOLS*EMB];
__device__ __nv_bfloat16 g_wk_hi[(size_t)NCOLS*EMB];
__device__ __nv_bfloat16 g_wk_lo[(size_t)NCOLS*EMB];
__device__ __nv_bfloat16 g_wv_hi[(size_t)NCOLS*EMB];
__device__ __nv_bfloat16 g_wv_lo[(size_t)NCOLS*EMB];

// projected Q/K/V as bf16 hi/lo, layout [b,h,s,d]
__device__ __nv_bfloat16 g_qh[(size_t)BSZ*NH*SEQ*DH];
__device__ __nv_bfloat16 g_ql[(size_t)BSZ*NH*SEQ*DH];
__device__ __nv_bfloat16 g_kh[(size_t)BSZ*NH*SEQ*DH];
__device__ __nv_bfloat16 g_kl[(size_t)BSZ*NH*SEQ*DH];
__device__ __nv_bfloat16 g_vh[(size_t)BSZ*NH*SEQ*DH];
__device__ __nv_bfloat16 g_vl[(size_t)BSZ*NH*SEQ*DH];

// ---------------- helpers (base sm_103-safe ISA only) ----------------
__device__ __forceinline__ uint32_t smem_u32(const void* p) {
    uint32_t a;
    asm("{ .reg .u64 t; cvta.to.shared.u64 t, %1; cvt.u32.u64 %0, t; }" : "=r"(a) : "l"(p));
    return a;
}
__device__ __forceinline__ void ldsm4(uint32_t* r, uint32_t addr) {
    asm volatile("ldmatrix.sync.aligned.m8n8.x4.shared.b16 {%0,%1,%2,%3}, [%4];"
                 : "=r"(r[0]), "=r"(r[1]), "=r"(r[2]), "=r"(r[3]) : "r"(addr));
}
__device__ __forceinline__ void ldsm4t(uint32_t* r, uint32_t addr) {
    asm volatile("ldmatrix.sync.aligned.m8n8.x4.trans.shared.b16 {%0,%1,%2,%3}, [%4];"
                 : "=r"(r[0]), "=r"(r[1]), "=r"(r[2]), "=r"(r[3]) : "r"(addr));
}
__device__ __forceinline__ void mma_bf16(float* c, const uint32_t* a, uint32_t b0, uint32_t b1) {
    asm volatile("mma.sync.aligned.m16n8k16.row.col.f32.bf16.bf16.f32 "
                 "{%0,%1,%2,%3}, {%4,%5,%6,%7}, {%8,%9}, {%0,%1,%2,%3};"
                 : "+f"(c[0]), "+f"(c[1]), "+f"(c[2]), "+f"(c[3])
                 : "r"(a[0]), "r"(a[1]), "r"(a[2]), "r"(a[3]), "r"(b0), "r"(b1));
}
__device__ __forceinline__ void cp_async16(uint32_t saddr, const void* gptr) {
    asm volatile("cp.async.cg.shared.global [%0], [%1], 16;" :: "r"(saddr), "l"(gptr) : "memory");
}
#define CP_COMMIT() asm volatile("cp.async.commit_group;" ::: "memory")
#define CP_WAIT2()  asm volatile("cp.async.wait_group 2;" ::: "memory")
#define CP_WAIT1()  asm volatile("cp.async.wait_group 1;" ::: "memory")
#define CP_WAIT0()  asm volatile("cp.async.wait_group 0;" ::: "memory")

// split a float pair into packed bf16x2 hi and lo words
__device__ __forceinline__ void split2(float a, float b, uint32_t& hi, uint32_t& lo) {
    __nv_bfloat162 H, L;
    H.x = __float2bfloat16(a);
    H.y = __float2bfloat16(b);
    L.x = __float2bfloat16(a - __bfloat162float(H.x));
    L.y = __float2bfloat16(b - __bfloat162float(H.y));
    hi = *reinterpret_cast<uint32_t*>(&H);
    lo = *reinterpret_cast<uint32_t*>(&L);
}

// ---------------- split fp32 -> bf16 hi/lo (inputs) ----------------
__global__ __launch_bounds__(256) void split_kernel(const float* __restrict__ src,
                                                    __nv_bfloat16* __restrict__ hi,
                                                    __nv_bfloat16* __restrict__ lo,
                                                    int n4)
{
    int i = blockIdx.x * blockDim.x + threadIdx.x;
    if (i >= n4) return;
    float4 x = ((const float4*)src)[i];
    uint32_t h0, l0, h1, l1;
    split2(x.x, x.y, h0, l0);
    split2(x.z, x.w, h1, l1);
    ((uint32_t*)hi)[i * 2 + 0] = h0;
    ((uint32_t*)hi)[i * 2 + 1] = h1;
    ((uint32_t*)lo)[i * 2 + 0] = l0;
    ((uint32_t*)lo)[i * 2 + 1] = l1;
}

// ---------------- HMMA projection GEMM (exact R5 config) ----------------
#define BK      32
#define SKB     80
#define MAT_B   (128 * SKB)
#define OFF_AHI 0
#define OFF_ALO (MAT_B)
#define OFF_BHI (2 * MAT_B)
#define OFF_BLO (3 * MAT_B)
#define STAGE_B (4 * MAT_B)
#define PROJ_SMEM (2 * STAGE_B)       // 81920

__global__ __launch_bounds__(256) void proj_hmma(const __nv_bfloat16* __restrict__ Ahi,
                                                 const __nv_bfloat16* __restrict__ Alo,
                                                 const __nv_bfloat16* __restrict__ Bhi,
                                                 const __nv_bfloat16* __restrict__ Blo,
                                                 const float* __restrict__ bias,
                                                 __nv_bfloat16* __restrict__ DstH,
                                                 __nv_bfloat16* __restrict__ DstL,
                                                 float scale)
{
    extern __shared__ char smem[];
    const uint32_t sb = smem_u32(smem);
    const int t    = threadIdx.x;
    const int lane = t & 31;
    const int wid  = t >> 5;
    const int wm   = wid & 1;
    const int wn   = wid >> 1;
    const int n0   = blockIdx.x * 128;
    const int m0   = blockIdx.y * 128;

    const int c0r = t >> 2,         c0p = t & 3;
    const int c1r = (t + 256) >> 2, c1p = (t + 256) & 3;

    const uint32_t aRow = (uint32_t)((wm * 64 + (lane & 15)) * SKB + (lane >> 4) * 16);
    const uint32_t bRow = (uint32_t)((wn * 32 + (((lane >> 4) << 3) | (lane & 7))) * SKB
                                     + ((lane >> 3) & 1) * 16);

    float acc[4][4][4] = {};
    const int NSTAGE = EMB / BK;

    auto issue = [&](int s) {
        const int k0 = s * BK;
        const uint32_t buf = sb + (uint32_t)(s & 1) * STAGE_B;
        {
            uint32_t so = (uint32_t)(c0r * SKB + c0p * 16);
            size_t ga = (size_t)(m0 + c0r) * EMB + k0 + c0p * 8;
            size_t gb = (size_t)(n0 + c0r) * EMB + k0 + c0p * 8;
            cp_async16(buf + OFF_AHI + so, Ahi + ga);
            cp_async16(buf + OFF_ALO + so, Alo + ga);
            cp_async16(buf + OFF_BHI + so, Bhi + gb);
            cp_async16(buf + OFF_BLO + so, Blo + gb);
        }
        {
            uint32_t so = (uint32_t)(c1r * SKB + c1p * 16);
            size_t ga = (size_t)(m0 + c1r) * EMB + k0 + c1p * 8;
            size_t gb = (size_t)(n0 + c1r) * EMB + k0 + c1p * 8;
            cp_async16(buf + OFF_AHI + so, Ahi + ga);
            cp_async16(buf + OFF_ALO + so, Alo + ga);
            cp_async16(buf + OFF_BHI + so, Bhi + gb);
            cp_async16(buf + OFF_BLO + so, Blo + gb);
        }
        CP_COMMIT();
    };

    issue(0);
    issue(1);

    for (int s = 0; s < NSTAGE; s++) {
        if (s + 1 < NSTAGE) { CP_WAIT1(); } else { CP_WAIT0(); }
        __syncthreads();
        const uint32_t buf = sb + (uint32_t)(s & 1) * STAGE_B;

#pragma unroll
        for (int kc = 0; kc < BK; kc += 16) {
            uint32_t aH[4][4], aL[4][4], bH[2][4], bL[2][4];
#pragma unroll
            for (int mt = 0; mt < 4; mt++) {
                uint32_t off = aRow + (uint32_t)(mt * 16 * SKB + kc * 2);
                ldsm4(aH[mt], buf + OFF_AHI + off);
                ldsm4(aL[mt], buf + OFF_ALO + off);
            }
#pragma unroll
            for (int g = 0; g < 2; g++) {
                uint32_t off = bRow + (uint32_t)(g * 16 * SKB + kc * 2);
                ldsm4(bH[g], buf + OFF_BHI + off);
                ldsm4(bL[g], buf + OFF_BLO + off);
            }
#pragma unroll
            for (int mt = 0; mt < 4; mt++)
#pragma unroll
                for (int nt = 0; nt < 4; nt++)
                    mma_bf16(acc[mt][nt], aH[mt], bH[nt >> 1][(nt & 1) * 2], bH[nt >> 1][(nt & 1) * 2 + 1]);
#pragma unroll
            for (int mt = 0; mt < 4; mt++)
#pragma unroll
                for (int nt = 0; nt < 4; nt++)
                    mma_bf16(acc[mt][nt], aH[mt], bL[nt >> 1][(nt & 1) * 2], bL[nt >> 1][(nt & 1) * 2 + 1]);
#pragma unroll
            for (int mt = 0; mt < 4; mt++)
#pragma unroll
                for (int nt = 0; nt < 4; nt++)
                    mma_bf16(acc[mt][nt], aL[mt], bH[nt >> 1][(nt & 1) * 2], bH[nt >> 1][(nt & 1) * 2 + 1]);
        }

        __syncthreads();
        if (s + 2 < NSTAGE) issue(s + 2);
    }

    // epilogue: (acc + bias) * scale -> bf16 hi/lo into [b,h,s,d]
    const int rbase = lane >> 2;
    const int cbase = (lane & 3) * 2;
#pragma unroll
    for (int mt = 0; mt < 4; mt++) {
#pragma unroll
        for (int half = 0; half < 2; half++) {
            const int m = m0 + wm * 64 + mt * 16 + rbase + half * 8;
            const int b = m >> 11;
            const int sdx = m & (SEQ - 1);
#pragma unroll
            for (int nt = 0; nt < 4; nt++) {
                const int n = n0 + wn * 32 + nt * 8 + cbase;
                const int h = n >> 6;
                const int d = n & 63;
                float fx = (acc[mt][nt][half * 2 + 0] + bias[n + 0]) * scale;
                float fy = (acc[mt][nt][half * 2 + 1] + bias[n + 1]) * scale;
                uint32_t hw, lw;
                split2(fx, fy, hw, lw);
                size_t o = (((size_t)(b * NH + h)) * SEQ + sdx) * DH + d;
                *(uint32_t*)(DstH + o) = hw;
                *(uint32_t*)(DstL + o) = lw;
            }
        }
    }
}

// ---------------- HMMA causal flash attention ----------------
// R5 inner loop; 3-stage KV cp.async pipeline (fixed qb=0 wait); longest-first.
#define ASTR   144
#define AQ_B   (128 * ASTR)
#define AKV_B  (64 * ASTR)
#define AOFF_KH 0
#define AOFF_KL (AKV_B)
#define AOFF_VH (2 * AKV_B)
#define AOFF_VL (3 * AKV_B)
#define AKV_STAGE (4 * AKV_B)                   // 36864
#define AKV_OFF (2 * AQ_B)
#define ATTN_SMEM (2 * AQ_B + 3 * AKV_STAGE)    // 147456

__global__ __launch_bounds__(256) void attn_hmma(const __nv_bfloat16* __restrict__ Qh,
                                                 const __nv_bfloat16* __restrict__ Ql,
                                                 const __nv_bfloat16* __restrict__ Kh,
                                                 const __nv_bfloat16* __restrict__ Kl,
                                                 const __nv_bfloat16* __restrict__ Vh,
                                                 const __nv_bfloat16* __restrict__ Vl,
                                                 float* __restrict__ out)
{
    extern __shared__ char smem[];
    const uint32_t sb = smem_u32(smem);
    const int t    = threadIdx.x;
    const int lane = t & 31;
    const int wid  = t >> 5;
    const int qb   = 15 - (int)blockIdx.x;   // longest-first
    const int bh   = blockIdx.y;
    const int q0   = qb * 128;

    const size_t base = (size_t)bh * SEQ * DH;
    const __nv_bfloat16* qh = Qh + base;
    const __nv_bfloat16* ql = Ql + base;
    const __nv_bfloat16* kh = Kh + base;
    const __nv_bfloat16* kl = Kl + base;
    const __nv_bfloat16* vh = Vh + base;
    const __nv_bfloat16* vl = Vl + base;

    // Q tiles -> smem (commit group)
#pragma unroll
    for (int i = 0; i < 4; i++) {
        int id = t + i * 256;
        int row = id >> 3, part = id & 7;
        size_t g = (size_t)(q0 + row) * DH + part * 8;
        uint32_t so = (uint32_t)(row * ASTR + part * 16);
        cp_async16(sb + so, qh + g);
        cp_async16(sb + AQ_B + so, ql + g);
    }
    CP_COMMIT();

    auto issueKV = [&](int kb) {
        const uint32_t buf = sb + AKV_OFF + (uint32_t)(kb % 3) * AKV_STAGE;
        const int k0 = kb * 64;
#pragma unroll
        for (int i = 0; i < 2; i++) {
            int id = t + i * 256;
            int row = id >> 3, part = id & 7;
            size_t g = (size_t)(k0 + row) * DH + part * 8;
            uint32_t so = (uint32_t)(row * ASTR + part * 16);
            cp_async16(buf + AOFF_KH + so, kh + g);
            cp_async16(buf + AOFF_KL + so, kl + g);
            cp_async16(buf + AOFF_VH + so, vh + g);
            cp_async16(buf + AOFF_VL + so, vl + g);
        }
        CP_COMMIT();
    };

    const int nkb = 2 * qb + 2;
    issueKV(0);
    issueKV(1);
    if (nkb > 2) issueKV(2);

    // wait for Q + KV0.
    // groups issued so far: Q, KV0, KV1[, KV2]. To guarantee KV0 retired:
    //   nkb>2 (4 groups): pending <= 2  -> Q, KV0 done
    //   nkb==2 (3 groups): pending <= 1 -> Q, KV0 done   (R9 bug was wait2 here)
    if (nkb > 2) { CP_WAIT2(); } else { CP_WAIT1(); }
    __syncthreads();
    uint32_t qhF[4][4], qlF[4][4];
    {
        const uint32_t aRow = (uint32_t)((wid * 16 + (lane & 15)) * ASTR + (lane >> 4) * 16);
#pragma unroll
        for (int kt = 0; kt < 4; kt++) {
            ldsm4(qhF[kt], sb + aRow + kt * 32);
            ldsm4(qlF[kt], sb + AQ_B + aRow + kt * 32);
        }
    }

    float m0r = -1e30f, m1r = -1e30f, l0r = 0.f, l1r = 0.f;
    float o[8][4] = {};

    const uint32_t kLane = (uint32_t)(((((lane >> 4) << 3) | (lane & 7)) * ASTR) + ((lane >> 3) & 1) * 16);
    const uint32_t vLane = (uint32_t)(((((lane >> 3) & 1) * 8 + (lane & 7)) * ASTR) + ((lane >> 4) & 1) * 16);

    for (int kb = 0; kb < nkb; kb++) {
        if (kb == 0) {
            // KV0 guaranteed by the pre-loop wait
        } else if (kb + 2 < nkb)      { CP_WAIT2(); }
        else if (kb + 1 < nkb)        { CP_WAIT1(); }
        else                          { CP_WAIT0(); }
        __syncthreads();
        const uint32_t buf = sb + AKV_OFF + (uint32_t)(kb % 3) * AKV_STAGE;
        const int k0 = kb * 64;

        // ---- S = Q K^T (split, 3 passes) ----
        float s[8][4] = {};
#pragma unroll
        for (int kt = 0; kt < 4; kt++) {
            uint32_t kh4[4][4], kl4[4][4];
#pragma unroll
            for (int g = 0; g < 4; g++) {
                uint32_t off = kLane + (uint32_t)(g * 16 * ASTR + kt * 32);
                ldsm4(kh4[g], buf + AOFF_KH + off);
                ldsm4(kl4[g], buf + AOFF_KL + off);
            }
#pragma unroll
            for (int g = 0; g < 4; g++)
#pragma unroll
                for (int hf = 0; hf < 2; hf++) {
                    int nt = g * 2 + hf;
                    mma_bf16(s[nt], qhF[kt], kh4[g][hf * 2], kh4[g][hf * 2 + 1]);
                    mma_bf16(s[nt], qhF[kt], kl4[g][hf * 2], kl4[g][hf * 2 + 1]);
                    mma_bf16(s[nt], qlF[kt], kh4[g][hf * 2], kh4[g][hf * 2 + 1]);
                }
        }

        // ---- causal mask ----
        if (k0 + 63 > q0 + wid * 16) {
            const int r0 = q0 + wid * 16 + (lane >> 2);
            const int r1 = r0 + 8;
#pragma unroll
            for (int nt = 0; nt < 8; nt++) {
                const int c = k0 + nt * 8 + (lane & 3) * 2;
                if (c > r0)     s[nt][0] = -1e30f;
                if (c + 1 > r0) s[nt][1] = -1e30f;
                if (c > r1)     s[nt][2] = -1e30f;
                if (c + 1 > r1) s[nt][3] = -1e30f;
            }
        }

        // ---- online softmax ----
        float mx0 = s[0][0], mx1 = s[0][2];
#pragma unroll
        for (int nt = 0; nt < 8; nt++) {
            mx0 = fmaxf(mx0, fmaxf(s[nt][0], s[nt][1]));
            mx1 = fmaxf(mx1, fmaxf(s[nt][2], s[nt][3]));
        }
        mx0 = fmaxf(mx0, __shfl_xor_sync(0xffffffff, mx0, 1));
        mx0 = fmaxf(mx0, __shfl_xor_sync(0xffffffff, mx0, 2));
        mx1 = fmaxf(mx1, __shfl_xor_sync(0xffffffff, mx1, 1));
        mx1 = fmaxf(mx1, __shfl_xor_sync(0xffffffff, mx1, 2));
        const float mn0 = fmaxf(m0r, mx0), mn1 = fmaxf(m1r, mx1);
        const float a0 = __expf(m0r - mn0), a1 = __expf(m1r - mn1);
        m0r = mn0; m1r = mn1;
        float sum0 = 0.f, sum1 = 0.f;
#pragma unroll
        for (int nt = 0; nt < 8; nt++) {
            s[nt][0] = __expf(s[nt][0] - mn0); sum0 += s[nt][0];
            s[nt][1] = __expf(s[nt][1] - mn0); sum0 += s[nt][1];
            s[nt][2] = __expf(s[nt][2] - mn1); sum1 += s[nt][2];
            s[nt][3] = __expf(s[nt][3] - mn1); sum1 += s[nt][3];
        }
        sum0 += __shfl_xor_sync(0xffffffff, sum0, 1);
        sum0 += __shfl_xor_sync(0xffffffff, sum0, 2);
        sum1 += __shfl_xor_sync(0xffffffff, sum1, 1);
        sum1 += __shfl_xor_sync(0xffffffff, sum1, 2);
        l0r = l0r * a0 + sum0;
        l1r = l1r * a1 + sum1;
#pragma unroll
        for (int n = 0; n < 8; n++) {
            o[n][0] *= a0; o[n][1] *= a0;
            o[n][2] *= a1; o[n][3] *= a1;
        }

        // ---- O += P V (split, 3 passes) ----
#pragma unroll
        for (int kt = 0; kt < 4; kt++) {
            uint32_t ph[4], pl[4];
            const int nt0 = kt * 2, nt1 = kt * 2 + 1;
            split2(s[nt0][0], s[nt0][1], ph[0], pl[0]);
            split2(s[nt0][2], s[nt0][3], ph[1], pl[1]);
            split2(s[nt1][0], s[nt1][1], ph[2], pl[2]);
            split2(s[nt1][2], s[nt1][3], ph[3], pl[3]);
#pragma unroll
            for (int g = 0; g < 4; g++) {
                uint32_t vh4[4], vl4[4];
                uint32_t off = vLane + (uint32_t)(kt * 16 * ASTR + g * 32);
                ldsm4t(vh4, buf + AOFF_VH + off);
                ldsm4t(vl4, buf + AOFF_VL + off);
#pragma unroll
                for (int hf = 0; hf < 2; hf++) {
                    int n = g * 2 + hf;
                    mma_bf16(o[n], ph, vh4[hf * 2], vh4[hf * 2 + 1]);
                    mma_bf16(o[n], ph, vl4[hf * 2], vl4[hf * 2 + 1]);
                    mma_bf16(o[n], pl, vh4[hf * 2], vh4[hf * 2 + 1]);
                }
            }
        }

        __syncthreads();
        if (kb + 3 < nkb) issueKV(kb + 3);
    }

    // ---- epilogue ----
    const int b  = bh >> 4;
    const int h  = bh & 15;
    const int r0 = q0 + wid * 16 + (lane >> 2);
    const int r1 = r0 + 8;
    const float i0 = 1.f / l0r, i1 = 1.f / l1r;
#pragma unroll
    for (int n = 0; n < 8; n++) {
        const int d = n * 8 + (lane & 3) * 2;
        *(float2*)(out + ((size_t)(b * SEQ + r0)) * NCOLS + h * DH + d) =
            make_float2(o[n][0] * i0, o[n][1] * i0);
        *(float2*)(out + ((size_t)(b * SEQ + r1)) * NCOLS + h * DH + d) =
            make_float2(o[n][2] * i1, o[n][3] * i1);
    }
}

// ---------------------------------------------------------------------------
extern "C" void kernel_launch(void* const* d_in, const int* in_sizes, int n_in,
                              void* d_out, int out_size)
{
    const float* x_q  = (const float*)d_in[0];
    const float* x_kv = (const float*)d_in[1];
    const float* w_q  = (const float*)d_in[3];
    const float* b_q  = (const float*)d_in[4];
    const float* w_k  = (const float*)d_in[5];
    const float* b_k  = (const float*)d_in[6];
    const float* w_v  = (const float*)d_in[7];
    const float* b_v  = (const float*)d_in[8];
    float* out = (float*)d_out;

    __nv_bfloat16 *xqh, *xql, *xkh, *xkl;
    __nv_bfloat16 *wqh, *wql, *wkh, *wkl, *wvh, *wvl;
    __nv_bfloat16 *qhp, *qlp, *khp, *klp, *vhp, *vlp;
    cudaGetSymbolAddress((void**)&xqh, g_xq_hi);
    cudaGetSymbolAddress((void**)&xql, g_xq_lo);
    cudaGetSymbolAddress((void**)&xkh, g_xkv_hi);
    cudaGetSymbolAddress((void**)&xkl, g_xkv_lo);
    cudaGetSymbolAddress((void**)&wqh, g_wq_hi);
    cudaGetSymbolAddress((void**)&wql, g_wq_lo);
    cudaGetSymbolAddress((void**)&wkh, g_wk_hi);
    cudaGetSymbolAddress((void**)&wkl, g_wk_lo);
    cudaGetSymbolAddress((void**)&wvh, g_wv_hi);
    cudaGetSymbolAddress((void**)&wvl, g_wv_lo);
    cudaGetSymbolAddress((void**)&qhp, g_qh);
    cudaGetSymbolAddress((void**)&qlp, g_ql);
    cudaGetSymbolAddress((void**)&khp, g_kh);
    cudaGetSymbolAddress((void**)&klp, g_kl);
    cudaGetSymbolAddress((void**)&vhp, g_vh);
    cudaGetSymbolAddress((void**)&vlp, g_vl);

    cudaFuncSetAttribute(proj_hmma, cudaFuncAttributeMaxDynamicSharedMemorySize, PROJ_SMEM);
    cudaFuncSetAttribute(attn_hmma, cudaFuncAttributeMaxDynamicSharedMemorySize, ATTN_SMEM);

    const int nX4 = MROWS * EMB / 4;
    const int nW4 = NCOLS * EMB / 4;
    split_kernel<<<(nX4 + 255) / 256, 256>>>(x_q,  xqh, xql, nX4);
    split_kernel<<<(nX4 + 255) / 256, 256>>>(x_kv, xkh, xkl, nX4);
    split_kernel<<<(nW4 + 255) / 256, 256>>>(w_q,  wqh, wql, nW4);
    split_kernel<<<(nW4 + 255) / 256, 256>>>(w_k,  wkh, wkl, nW4);
    split_kernel<<<(nW4 + 255) / 256, 256>>>(w_v,  wvh, wvl, nW4);

    dim3 pgrid(NCOLS / 128, MROWS / 128);   // (8, 64)
    proj_hmma<<<pgrid, 256, PROJ_SMEM>>>(xqh, xql, wqh, wql, b_q, qhp, qlp, 0.125f);
    proj_hmma<<<pgrid, 256, PROJ_SMEM>>>(xkh, xkl, wkh, wkl, b_k, khp, klp, 1.0f);
    proj_hmma<<<pgrid, 256, PROJ_SMEM>>>(xkh, xkl, wvh, wvl, b_v, vhp, vlp, 1.0f);

    dim3 agrid(SEQ / 128, BSZ * NH);        // (16, 64)
    attn_hmma<<<agrid, 256, ATTN_SMEM>>>(qhp, qlp, khp, klp, vhp, vlp, out);
}

// round 11
// speedup vs baseline: 1.6537x; 1.0014x over previous
#include <cuda_runtime.h>
#include <cuda_bf16.h>
#include <cstdint>

#define EMB  1024
#define NH   16
#define DH   64
#define BSZ  4
#define SEQ  2048
#define MROWS (BSZ*SEQ)   // 8192
#define NCOLS (NH*DH)     // 1024

// ---------------- scratch (allocation-guard safe) ----------------
__device__ __nv_bfloat16 g_xq_hi[(size_t)MROWS*EMB];
__device__ __nv_bfloat16 g_xq_lo[(size_t)MROWS*EMB];
__device__ __nv_bfloat16 g_xkv_hi[(size_t)MROWS*EMB];
__device__ __nv_bfloat16 g_xkv_lo[(size_t)MROWS*EMB];
__device__ __nv_bfloat16 g_wq_hi[(size_t)NCOLS*EMB];
__device__ __nv_bfloat16 g_wq_lo[(size_t)NCOLS*EMB];
__device__ __nv_bfloat16 g_wk_hi[(size_t)NCOLS*EMB];
__device__ __nv_bfloat16 g_wk_lo[(size_t)NCOLS*EMB];
__device__ __nv_bfloat16 g_wv_hi[(size_t)NCOLS*EMB];
__device__ __nv_bfloat16 g_wv_lo[(size_t)NCOLS*EMB];

// projected Q/K/V as bf16 hi/lo, layout [b,h,s,d]
__device__ __nv_bfloat16 g_qh[(size_t)BSZ*NH*SEQ*DH];
__device__ __nv_bfloat16 g_ql[(size_t)BSZ*NH*SEQ*DH];
__device__ __nv_bfloat16 g_kh[(size_t)BSZ*NH*SEQ*DH];
__device__ __nv_bfloat16 g_kl[(size_t)BSZ*NH*SEQ*DH];
__device__ __nv_bfloat16 g_vh[(size_t)BSZ*NH*SEQ*DH];
__device__ __nv_bfloat16 g_vl[(size_t)BSZ*NH*SEQ*DH];

// ---------------- helpers (base sm_103-safe ISA only) ----------------
__device__ __forceinline__ uint32_t smem_u32(const void* p) {
    uint32_t a;
    asm("{ .reg .u64 t; cvta.to.shared.u64 t, %1; cvt.u32.u64 %0, t; }" : "=r"(a) : "l"(p));
    return a;
}
__device__ __forceinline__ void ldsm4(uint32_t* r, uint32_t addr) {
    asm volatile("ldmatrix.sync.aligned.m8n8.x4.shared.b16 {%0,%1,%2,%3}, [%4];"
                 : "=r"(r[0]), "=r"(r[1]), "=r"(r[2]), "=r"(r[3]) : "r"(addr));
}
__device__ __forceinline__ void ldsm4t(uint32_t* r, uint32_t addr) {
    asm volatile("ldmatrix.sync.aligned.m8n8.x4.trans.shared.b16 {%0,%1,%2,%3}, [%4];"
                 : "=r"(r[0]), "=r"(r[1]), "=r"(r[2]), "=r"(r[3]) : "r"(addr));
}
__device__ __forceinline__ void mma_bf16(float* c, const uint32_t* a, uint32_t b0, uint32_t b1) {
    asm volatile("mma.sync.aligned.m16n8k16.row.col.f32.bf16.bf16.f32 "
                 "{%0,%1,%2,%3}, {%4,%5,%6,%7}, {%8,%9}, {%0,%1,%2,%3};"
                 : "+f"(c[0]), "+f"(c[1]), "+f"(c[2]), "+f"(c[3])
                 : "r"(a[0]), "r"(a[1]), "r"(a[2]), "r"(a[3]), "r"(b0), "r"(b1));
}
__device__ __forceinline__ void cp_async16(uint32_t saddr, const void* gptr) {
    asm volatile("cp.async.cg.shared.global [%0], [%1], 16;" :: "r"(saddr), "l"(gptr) : "memory");
}
#define CP_COMMIT() asm volatile("cp.async.commit_group;" ::: "memory")
#define CP_WAIT2()  asm volatile("cp.async.wait_group 2;" ::: "memory")
#define CP_WAIT1()  asm volatile("cp.async.wait_group 1;" ::: "memory")
#define CP_WAIT0()  asm volatile("cp.async.wait_group 0;" ::: "memory")

// raw EX2 (exp base 2); log2e is folded into the Q scale
__device__ __forceinline__ float ex2(float x) {
    float r;
    asm("ex2.approx.f32 %0, %1;" : "=f"(r) : "f"(x));
    return r;
}

// split a float pair into packed bf16x2 hi and lo words
__device__ __forceinline__ void split2(float a, float b, uint32_t& hi, uint32_t& lo) {
    __nv_bfloat162 H, L;
    H.x = __float2bfloat16(a);
    H.y = __float2bfloat16(b);
    L.x = __float2bfloat16(a - __bfloat162float(H.x));
    L.y = __float2bfloat16(b - __bfloat162float(H.y));
    hi = *reinterpret_cast<uint32_t*>(&H);
    lo = *reinterpret_cast<uint32_t*>(&L);
}

// ---------------- split fp32 -> bf16 hi/lo (inputs) ----------------
__global__ __launch_bounds__(256) void split_kernel(const float* __restrict__ src,
                                                    __nv_bfloat16* __restrict__ hi,
                                                    __nv_bfloat16* __restrict__ lo,
                                                    int n4)
{
    int i = blockIdx.x * blockDim.x + threadIdx.x;
    if (i >= n4) return;
    float4 x = ((const float4*)src)[i];
    uint32_t h0, l0, h1, l1;
    split2(x.x, x.y, h0, l0);
    split2(x.z, x.w, h1, l1);
    ((uint32_t*)hi)[i * 2 + 0] = h0;
    ((uint32_t*)hi)[i * 2 + 1] = h1;
    ((uint32_t*)lo)[i * 2 + 0] = l0;
    ((uint32_t*)lo)[i * 2 + 1] = l1;
}

// ---------------- HMMA projection GEMM (exact R5 config) ----------------
#define BK      32
#define SKB     80
#define MAT_B   (128 * SKB)
#define OFF_AHI 0
#define OFF_ALO (MAT_B)
#define OFF_BHI (2 * MAT_B)
#define OFF_BLO (3 * MAT_B)
#define STAGE_B (4 * MAT_B)
#define PROJ_SMEM (2 * STAGE_B)       // 81920

__global__ __launch_bounds__(256) void proj_hmma(const __nv_bfloat16* __restrict__ Ahi,
                                                 const __nv_bfloat16* __restrict__ Alo,
                                                 const __nv_bfloat16* __restrict__ Bhi,
                                                 const __nv_bfloat16* __restrict__ Blo,
                                                 const float* __restrict__ bias,
                                                 __nv_bfloat16* __restrict__ DstH,
                                                 __nv_bfloat16* __restrict__ DstL,
                                                 float scale)
{
    extern __shared__ char smem[];
    const uint32_t sb = smem_u32(smem);
    const int t    = threadIdx.x;
    const int lane = t & 31;
    const int wid  = t >> 5;
    const int wm   = wid & 1;
    const int wn   = wid >> 1;
    const int n0   = blockIdx.x * 128;
    const int m0   = blockIdx.y * 128;

    const int c0r = t >> 2,         c0p = t & 3;
    const int c1r = (t + 256) >> 2, c1p = (t + 256) & 3;

    const uint32_t aRow = (uint32_t)((wm * 64 + (lane & 15)) * SKB + (lane >> 4) * 16);
    const uint32_t bRow = (uint32_t)((wn * 32 + (((lane >> 4) << 3) | (lane & 7))) * SKB
                                     + ((lane >> 3) & 1) * 16);

    float acc[4][4][4] = {};
    const int NSTAGE = EMB / BK;

    auto issue = [&](int s) {
        const int k0 = s * BK;
        const uint32_t buf = sb + (uint32_t)(s & 1) * STAGE_B;
        {
            uint32_t so = (uint32_t)(c0r * SKB + c0p * 16);
            size_t ga = (size_t)(m0 + c0r) * EMB + k0 + c0p * 8;
            size_t gb = (size_t)(n0 + c0r) * EMB + k0 + c0p * 8;
            cp_async16(buf + OFF_AHI + so, Ahi + ga);
            cp_async16(buf + OFF_ALO + so, Alo + ga);
            cp_async16(buf + OFF_BHI + so, Bhi + gb);
            cp_async16(buf + OFF_BLO + so, Blo + gb);
        }
        {
            uint32_t so = (uint32_t)(c1r * SKB + c1p * 16);
            size_t ga = (size_t)(m0 + c1r) * EMB + k0 + c1p * 8;
            size_t gb = (size_t)(n0 + c1r) * EMB + k0 + c1p * 8;
            cp_async16(buf + OFF_AHI + so, Ahi + ga);
            cp_async16(buf + OFF_ALO + so, Alo + ga);
            cp_async16(buf + OFF_BHI + so, Bhi + gb);
            cp_async16(buf + OFF_BLO + so, Blo + gb);
        }
        CP_COMMIT();
    };

    issue(0);
    issue(1);

    for (int s = 0; s < NSTAGE; s++) {
        if (s + 1 < NSTAGE) { CP_WAIT1(); } else { CP_WAIT0(); }
        __syncthreads();
        const uint32_t buf = sb + (uint32_t)(s & 1) * STAGE_B;

#pragma unroll
        for (int kc = 0; kc < BK; kc += 16) {
            uint32_t aH[4][4], aL[4][4], bH[2][4], bL[2][4];
#pragma unroll
            for (int mt = 0; mt < 4; mt++) {
                uint32_t off = aRow + (uint32_t)(mt * 16 * SKB + kc * 2);
                ldsm4(aH[mt], buf + OFF_AHI + off);
                ldsm4(aL[mt], buf + OFF_ALO + off);
            }
#pragma unroll
            for (int g = 0; g < 2; g++) {
                uint32_t off = bRow + (uint32_t)(g * 16 * SKB + kc * 2);
                ldsm4(bH[g], buf + OFF_BHI + off);
                ldsm4(bL[g], buf + OFF_BLO + off);
            }
#pragma unroll
            for (int mt = 0; mt < 4; mt++)
#pragma unroll
                for (int nt = 0; nt < 4; nt++)
                    mma_bf16(acc[mt][nt], aH[mt], bH[nt >> 1][(nt & 1) * 2], bH[nt >> 1][(nt & 1) * 2 + 1]);
#pragma unroll
            for (int mt = 0; mt < 4; mt++)
#pragma unroll
                for (int nt = 0; nt < 4; nt++)
                    mma_bf16(acc[mt][nt], aH[mt], bL[nt >> 1][(nt & 1) * 2], bL[nt >> 1][(nt & 1) * 2 + 1]);
#pragma unroll
            for (int mt = 0; mt < 4; mt++)
#pragma unroll
                for (int nt = 0; nt < 4; nt++)
                    mma_bf16(acc[mt][nt], aL[mt], bH[nt >> 1][(nt & 1) * 2], bH[nt >> 1][(nt & 1) * 2 + 1]);
        }

        __syncthreads();
        if (s + 2 < NSTAGE) issue(s + 2);
    }

    // epilogue: (acc + bias) * scale -> bf16 hi/lo into [b,h,s,d]
    const int rbase = lane >> 2;
    const int cbase = (lane & 3) * 2;
#pragma unroll
    for (int mt = 0; mt < 4; mt++) {
#pragma unroll
        for (int half = 0; half < 2; half++) {
            const int m = m0 + wm * 64 + mt * 16 + rbase + half * 8;
            const int b = m >> 11;
            const int sdx = m & (SEQ - 1);
#pragma unroll
            for (int nt = 0; nt < 4; nt++) {
                const int n = n0 + wn * 32 + nt * 8 + cbase;
                const int h = n >> 6;
                const int d = n & 63;
                float fx = (acc[mt][nt][half * 2 + 0] + bias[n + 0]) * scale;
                float fy = (acc[mt][nt][half * 2 + 1] + bias[n + 1]) * scale;
                uint32_t hw, lw;
                split2(fx, fy, hw, lw);
                size_t o = (((size_t)(b * NH + h)) * SEQ + sdx) * DH + d;
                *(uint32_t*)(DstH + o) = hw;
                *(uint32_t*)(DstL + o) = lw;
            }
        }
    }
}

// ---------------- HMMA causal flash attention ----------------
// 4-stage KV ring, ONE barrier per tile (top). ex2-based softmax
// (log2e folded into Q scale). Split-bf16 on both GEMMs.
#define ASTR   144
#define AQ_B   (128 * ASTR)
#define AKV_B  (64 * ASTR)
#define AOFF_KH 0
#define AOFF_KL (AKV_B)
#define AOFF_VH (2 * AKV_B)
#define AOFF_VL (3 * AKV_B)
#define AKV_STAGE (4 * AKV_B)                   // 36864
#define AKV_OFF (2 * AQ_B)
#define ATTN_SMEM (2 * AQ_B + 4 * AKV_STAGE)    // 184320

__global__ __launch_bounds__(256) void attn_hmma(const __nv_bfloat16* __restrict__ Qh,
                                                 const __nv_bfloat16* __restrict__ Ql,
                                                 const __nv_bfloat16* __restrict__ Kh,
                                                 const __nv_bfloat16* __restrict__ Kl,
                                                 const __nv_bfloat16* __restrict__ Vh,
                                                 const __nv_bfloat16* __restrict__ Vl,
                                                 float* __restrict__ out)
{
    extern __shared__ char smem[];
    const uint32_t sb = smem_u32(smem);
    const int t    = threadIdx.x;
    const int lane = t & 31;
    const int wid  = t >> 5;
    const int qb   = 15 - (int)blockIdx.x;   // longest-first
    const int bh   = blockIdx.y;
    const int q0   = qb * 128;

    const size_t base = (size_t)bh * SEQ * DH;
    const __nv_bfloat16* qh = Qh + base;
    const __nv_bfloat16* ql = Ql + base;
    const __nv_bfloat16* kh = Kh + base;
    const __nv_bfloat16* kl = Kl + base;
    const __nv_bfloat16* vh = Vh + base;
    const __nv_bfloat16* vl = Vl + base;

    // Q tiles -> smem (commit group)
#pragma unroll
    for (int i = 0; i < 4; i++) {
        int id = t + i * 256;
        int row = id >> 3, part = id & 7;
        size_t g = (size_t)(q0 + row) * DH + part * 8;
        uint32_t so = (uint32_t)(row * ASTR + part * 16);
        cp_async16(sb + so, qh + g);
        cp_async16(sb + AQ_B + so, ql + g);
    }
    CP_COMMIT();

    auto issueKV = [&](int kb) {
        const uint32_t buf = sb + AKV_OFF + (uint32_t)(kb & 3) * AKV_STAGE;
        const int k0 = kb * 64;
#pragma unroll
        for (int i = 0; i < 2; i++) {
            int id = t + i * 256;
            int row = id >> 3, part = id & 7;
            size_t g = (size_t)(k0 + row) * DH + part * 8;
            uint32_t so = (uint32_t)(row * ASTR + part * 16);
            cp_async16(buf + AOFF_KH + so, kh + g);
            cp_async16(buf + AOFF_KL + so, kl + g);
            cp_async16(buf + AOFF_VH + so, vh + g);
            cp_async16(buf + AOFF_VL + so, vl + g);
        }
        CP_COMMIT();
    };

    const int nkb = 2 * qb + 2;
    issueKV(0);
    issueKV(1);
    if (nkb > 2) issueKV(2);

    // wait for Q + KV0 (see R9 post-mortem: nkb==2 has only 3 groups)
    if (nkb > 2) { CP_WAIT2(); } else { CP_WAIT1(); }
    __syncthreads();
    uint32_t qhF[4][4], qlF[4][4];
    {
        const uint32_t aRow = (uint32_t)((wid * 16 + (lane & 15)) * ASTR + (lane >> 4) * 16);
#pragma unroll
        for (int kt = 0; kt < 4; kt++) {
            ldsm4(qhF[kt], sb + aRow + kt * 32);
            ldsm4(qlF[kt], sb + AQ_B + aRow + kt * 32);
        }
    }

    float m0r = -1e30f, m1r = -1e30f, l0r = 0.f, l1r = 0.f;
    float o[8][4] = {};

    const uint32_t kLane = (uint32_t)(((((lane >> 4) << 3) | (lane & 7)) * ASTR) + ((lane >> 3) & 1) * 16);
    const uint32_t vLane = (uint32_t)(((((lane >> 3) & 1) * 8 + (lane & 7)) * ASTR) + ((lane >> 4) & 1) * 16);

    for (int kb = 0; kb < nkb; kb++) {
        if (kb > 0) {
            // last issued KV index at this point = min(kb+2, nkb-1)
            const int pending = ((kb + 2 < nkb) ? kb + 2 : nkb - 1) - kb;
            if (pending >= 2)      { CP_WAIT2(); }
            else if (pending == 1) { CP_WAIT1(); }
            else                   { CP_WAIT0(); }
            __syncthreads();   // all warps done with tile kb-1 (buffer (kb-1)&3)
        }
        // safe: buffer (kb+3)&3 == (kb-1)&3, drained by the barrier above
        if (kb + 3 < nkb) issueKV(kb + 3);

        const uint32_t buf = sb + AKV_OFF + (uint32_t)(kb & 3) * AKV_STAGE;
        const int k0 = kb * 64;

        // ---- S = Q K^T (split, 3 passes) ----
        float s[8][4] = {};
#pragma unroll
        for (int kt = 0; kt < 4; kt++) {
            uint32_t kh4[4][4], kl4[4][4];
#pragma unroll
            for (int g = 0; g < 4; g++) {
                uint32_t off = kLane + (uint32_t)(g * 16 * ASTR + kt * 32);
                ldsm4(kh4[g], buf + AOFF_KH + off);
                ldsm4(kl4[g], buf + AOFF_KL + off);
            }
#pragma unroll
            for (int g = 0; g < 4; g++)
#pragma unroll
                for (int hf = 0; hf < 2; hf++) {
                    int nt = g * 2 + hf;
                    mma_bf16(s[nt], qhF[kt], kh4[g][hf * 2], kh4[g][hf * 2 + 1]);
                    mma_bf16(s[nt], qhF[kt], kl4[g][hf * 2], kl4[g][hf * 2 + 1]);
                    mma_bf16(s[nt], qlF[kt], kh4[g][hf * 2], kh4[g][hf * 2 + 1]);
                }
        }

        // ---- causal mask ----
        if (k0 + 63 > q0 + wid * 16) {
            const int r0 = q0 + wid * 16 + (lane >> 2);
            const int r1 = r0 + 8;
#pragma unroll
            for (int nt = 0; nt < 8; nt++) {
                const int c = k0 + nt * 8 + (lane & 3) * 2;
                if (c > r0)     s[nt][0] = -1e30f;
                if (c + 1 > r0) s[nt][1] = -1e30f;
                if (c > r1)     s[nt][2] = -1e30f;
                if (c + 1 > r1) s[nt][3] = -1e30f;
            }
        }

        // ---- online softmax (base-2; log2e folded into Q scale) ----
        float mx0 = s[0][0], mx1 = s[0][2];
#pragma unroll
        for (int nt = 0; nt < 8; nt++) {
            mx0 = fmaxf(mx0, fmaxf(s[nt][0], s[nt][1]));
            mx1 = fmaxf(mx1, fmaxf(s[nt][2], s[nt][3]));
        }
        mx0 = fmaxf(mx0, __shfl_xor_sync(0xffffffff, mx0, 1));
        mx0 = fmaxf(mx0, __shfl_xor_sync(0xffffffff, mx0, 2));
        mx1 = fmaxf(mx1, __shfl_xor_sync(0xffffffff, mx1, 1));
        mx1 = fmaxf(mx1, __shfl_xor_sync(0xffffffff, mx1, 2));
        const float mn0 = fmaxf(m0r, mx0), mn1 = fmaxf(m1r, mx1);
        const float a0 = ex2(m0r - mn0), a1 = ex2(m1r - mn1);
        m0r = mn0; m1r = mn1;
        float sum0 = 0.f, sum1 = 0.f;
#pragma unroll
        for (int nt = 0; nt < 8; nt++) {
            s[nt][0] = ex2(s[nt][0] - mn0); sum0 += s[nt][0];
            s[nt][1] = ex2(s[nt][1] - mn0); sum0 += s[nt][1];
            s[nt][2] = ex2(s[nt][2] - mn1); sum1 += s[nt][2];
            s[nt][3] = ex2(s[nt][3] - mn1); sum1 += s[nt][3];
        }
        sum0 += __shfl_xor_sync(0xffffffff, sum0, 1);
        sum0 += __shfl_xor_sync(0xffffffff, sum0, 2);
        sum1 += __shfl_xor_sync(0xffffffff, sum1, 1);
        sum1 += __shfl_xor_sync(0xffffffff, sum1, 2);
        l0r = l0r * a0 + sum0;
        l1r = l1r * a1 + sum1;
#pragma unroll
        for (int n = 0; n < 8; n++) {
            o[n][0] *= a0; o[n][1] *= a0;
            o[n][2] *= a1; o[n][3] *= a1;
        }

        // ---- O += P V (split, 3 passes) ----
#pragma unroll
        for (int kt = 0; kt < 4; kt++) {
            uint32_t ph[4], pl[4];
            const int nt0 = kt * 2, nt1 = kt * 2 + 1;
            split2(s[nt0][0], s[nt0][1], ph[0], pl[0]);
            split2(s[nt0][2], s[nt0][3], ph[1], pl[1]);
            split2(s[nt1][0], s[nt1][1], ph[2], pl[2]);
            split2(s[nt1][2], s[nt1][3], ph[3], pl[3]);
#pragma unroll
            for (int g = 0; g < 4; g++) {
                uint32_t vh4[4], vl4[4];
                uint32_t off = vLane + (uint32_t)(kt * 16 * ASTR + g * 32);
                ldsm4t(vh4, buf + AOFF_VH + off);
                ldsm4t(vl4, buf + AOFF_VL + off);
#pragma unroll
                for (int hf = 0; hf < 2; hf++) {
                    int n = g * 2 + hf;
                    mma_bf16(o[n], ph, vh4[hf * 2], vh4[hf * 2 + 1]);
                    mma_bf16(o[n], ph, vl4[hf * 2], vl4[hf * 2 + 1]);
                    mma_bf16(o[n], pl, vh4[hf * 2], vh4[hf * 2 + 1]);
                }
            }
        }
        // no bottom barrier: 4-stage ring + top barrier covers reuse
    }

    // ---- epilogue ----
    const int b  = bh >> 4;
    const int h  = bh & 15;
    const int r0 = q0 + wid * 16 + (lane >> 2);
    const int r1 = r0 + 8;
    const float i0 = 1.f / l0r, i1 = 1.f / l1r;
#pragma unroll
    for (int n = 0; n < 8; n++) {
        const int d = n * 8 + (lane & 3) * 2;
        *(float2*)(out + ((size_t)(b * SEQ + r0)) * NCOLS + h * DH + d) =
            make_float2(o[n][0] * i0, o[n][1] * i0);
        *(float2*)(out + ((size_t)(b * SEQ + r1)) * NCOLS + h * DH + d) =
            make_float2(o[n][2] * i1, o[n][3] * i1);
    }
}

// ---------------------------------------------------------------------------
extern "C" void kernel_launch(void* const* d_in, const int* in_sizes, int n_in,
                              void* d_out, int out_size)
{
    const float* x_q  = (const float*)d_in[0];
    const float* x_kv = (const float*)d_in[1];
    const float* w_q  = (const float*)d_in[3];
    const float* b_q  = (const float*)d_in[4];
    const float* w_k  = (const float*)d_in[5];
    const float* b_k  = (const float*)d_in[6];
    const float* w_v  = (const float*)d_in[7];
    const float* b_v  = (const float*)d_in[8];
    float* out = (float*)d_out;

    __nv_bfloat16 *xqh, *xql, *xkh, *xkl;
    __nv_bfloat16 *wqh, *wql, *wkh, *wkl, *wvh, *wvl;
    __nv_bfloat16 *qhp, *qlp, *khp, *klp, *vhp, *vlp;
    cudaGetSymbolAddress((void**)&xqh, g_xq_hi);
    cudaGetSymbolAddress((void**)&xql, g_xq_lo);
    cudaGetSymbolAddress((void**)&xkh, g_xkv_hi);
    cudaGetSymbolAddress((void**)&xkl, g_xkv_lo);
    cudaGetSymbolAddress((void**)&wqh, g_wq_hi);
    cudaGetSymbolAddress((void**)&wql, g_wq_lo);
    cudaGetSymbolAddress((void**)&wkh, g_wk_hi);
    cudaGetSymbolAddress((void**)&wkl, g_wk_lo);
    cudaGetSymbolAddress((void**)&wvh, g_wv_hi);
    cudaGetSymbolAddress((void**)&wvl, g_wv_lo);
    cudaGetSymbolAddress((void**)&qhp, g_qh);
    cudaGetSymbolAddress((void**)&qlp, g_ql);
    cudaGetSymbolAddress((void**)&khp, g_kh);
    cudaGetSymbolAddress((void**)&klp, g_kl);
    cudaGetSymbolAddress((void**)&vhp, g_vh);
    cudaGetSymbolAddress((void**)&vlp, g_vl);

    cudaFuncSetAttribute(proj_hmma, cudaFuncAttributeMaxDynamicSharedMemorySize, PROJ_SMEM);
    cudaFuncSetAttribute(attn_hmma, cudaFuncAttributeMaxDynamicSharedMemorySize, ATTN_SMEM);

    const int nX4 = MROWS * EMB / 4;
    const int nW4 = NCOLS * EMB / 4;
    split_kernel<<<(nX4 + 255) / 256, 256>>>(x_q,  xqh, xql, nX4);
    split_kernel<<<(nX4 + 255) / 256, 256>>>(x_kv, xkh, xkl, nX4);
    split_kernel<<<(nW4 + 255) / 256, 256>>>(w_q,  wqh, wql, nW4);
    split_kernel<<<(nW4 + 255) / 256, 256>>>(w_k,  wkh, wkl, nW4);
    split_kernel<<<(nW4 + 255) / 256, 256>>>(w_v,  wvh, wvl, nW4);

    dim3 pgrid(NCOLS / 128, MROWS / 128);   // (8, 64)
    // Q scale folds 1/sqrt(64) AND log2(e) for the base-2 softmax
    proj_hmma<<<pgrid, 256, PROJ_SMEM>>>(xqh, xql, wqh, wql, b_q, qhp, qlp, 0.125f * 1.44269504f);
    proj_hmma<<<pgrid, 256, PROJ_SMEM>>>(xkh, xkl, wkh, wkl, b_k, khp, klp, 1.0f);
    proj_hmma<<<pgrid, 256, PROJ_SMEM>>>(xkh, xkl, wvh, wvl, b_v, vhp, vlp, 1.0f);

    dim3 agrid(SEQ / 128, BSZ * NH);        // (16, 64)
    attn_hmma<<<agrid, 256, ATTN_SMEM>>>(qhp, qlp, khp, klp, vhp, vlp, out);
}

// round 12
// speedup vs baseline: 2.1186x; 1.2811x over previous
#include <cuda_runtime.h>
#include <cuda_fp16.h>
#include <cstdint>

#define EMB  1024
#define NH   16
#define DH   64
#define BSZ  4
#define SEQ  2048
#define MROWS (BSZ*SEQ)   // 8192
#define NCOLS (NH*DH)     // 1024

// ---------------- scratch (allocation-guard safe) ----------------
__device__ __half g_xq_h[(size_t)MROWS*EMB];
__device__ __half g_xkv_h[(size_t)MROWS*EMB];
__device__ __half g_wq_hi[(size_t)NCOLS*EMB];
__device__ __half g_wq_lo[(size_t)NCOLS*EMB];
__device__ __half g_wk_hi[(size_t)NCOLS*EMB];
__device__ __half g_wk_lo[(size_t)NCOLS*EMB];
__device__ __half g_wv_hi[(size_t)NCOLS*EMB];
__device__ __half g_wv_lo[(size_t)NCOLS*EMB];

// projected Q (hi only) and K/V (hi+lo), layout [b,h,s,d]
__device__ __half g_qh[(size_t)BSZ*NH*SEQ*DH];
__device__ __half g_ql[(size_t)BSZ*NH*SEQ*DH];   // written by proj, unused (uniform epilogue)
__device__ __half g_kh[(size_t)BSZ*NH*SEQ*DH];
__device__ __half g_kl[(size_t)BSZ*NH*SEQ*DH];
__device__ __half g_vh[(size_t)BSZ*NH*SEQ*DH];
__device__ __half g_vl[(size_t)BSZ*NH*SEQ*DH];

// ---------------- helpers (base sm_103-safe ISA only) ----------------
__device__ __forceinline__ uint32_t smem_u32(const void* p) {
    uint32_t a;
    asm("{ .reg .u64 t; cvta.to.shared.u64 t, %1; cvt.u32.u64 %0, t; }" : "=r"(a) : "l"(p));
    return a;
}
__device__ __forceinline__ void ldsm4(uint32_t* r, uint32_t addr) {
    asm volatile("ldmatrix.sync.aligned.m8n8.x4.shared.b16 {%0,%1,%2,%3}, [%4];"
                 : "=r"(r[0]), "=r"(r[1]), "=r"(r[2]), "=r"(r[3]) : "r"(addr));
}
__device__ __forceinline__ void ldsm4t(uint32_t* r, uint32_t addr) {
    asm volatile("ldmatrix.sync.aligned.m8n8.x4.trans.shared.b16 {%0,%1,%2,%3}, [%4];"
                 : "=r"(r[0]), "=r"(r[1]), "=r"(r[2]), "=r"(r[3]) : "r"(addr));
}
__device__ __forceinline__ void mma_f16(float* c, const uint32_t* a, uint32_t b0, uint32_t b1) {
    asm volatile("mma.sync.aligned.m16n8k16.row.col.f32.f16.f16.f32 "
                 "{%0,%1,%2,%3}, {%4,%5,%6,%7}, {%8,%9}, {%0,%1,%2,%3};"
                 : "+f"(c[0]), "+f"(c[1]), "+f"(c[2]), "+f"(c[3])
                 : "r"(a[0]), "r"(a[1]), "r"(a[2]), "r"(a[3]), "r"(b0), "r"(b1));
}
__device__ __forceinline__ void cp_async16(uint32_t saddr, const void* gptr) {
    asm volatile("cp.async.cg.shared.global [%0], [%1], 16;" :: "r"(saddr), "l"(gptr) : "memory");
}
#define CP_COMMIT() asm volatile("cp.async.commit_group;" ::: "memory")
#define CP_WAIT2()  asm volatile("cp.async.wait_group 2;" ::: "memory")
#define CP_WAIT1()  asm volatile("cp.async.wait_group 1;" ::: "memory")
#define CP_WAIT0()  asm volatile("cp.async.wait_group 0;" ::: "memory")

__device__ __forceinline__ float ex2(float x) {
    float r;
    asm("ex2.approx.f32 %0, %1;" : "=f"(r) : "f"(x));
    return r;
}
__device__ __forceinline__ uint32_t pack_h2(float a, float b) {
    __half2 h = __floats2half2_rn(a, b);
    return *reinterpret_cast<uint32_t*>(&h);
}
// split a float pair into fp16 hi and lo packed words
__device__ __forceinline__ void split2h(float a, float b, uint32_t& hi, uint32_t& lo) {
    __half ha = __float2half_rn(a), hb = __float2half_rn(b);
    __half la = __float2half_rn(a - __half2float(ha));
    __half lb = __float2half_rn(b - __half2float(hb));
    __half2 H = __halves2half2(ha, hb), L = __halves2half2(la, lb);
    hi = *reinterpret_cast<uint32_t*>(&H);
    lo = *reinterpret_cast<uint32_t*>(&L);
}

// ---------------- fp32 -> fp16 (hi only, for X) ----------------
__global__ __launch_bounds__(256) void conv_h(const float* __restrict__ src,
                                              __half* __restrict__ hi, int n4)
{
    int i = blockIdx.x * blockDim.x + threadIdx.x;
    if (i >= n4) return;
    float4 x = ((const float4*)src)[i];
    ((uint32_t*)hi)[i * 2 + 0] = pack_h2(x.x, x.y);
    ((uint32_t*)hi)[i * 2 + 1] = pack_h2(x.z, x.w);
}
// ---------------- fp32 -> fp16 hi/lo (for W) ----------------
__global__ __launch_bounds__(256) void split_hl(const float* __restrict__ src,
                                                __half* __restrict__ hi,
                                                __half* __restrict__ lo, int n4)
{
    int i = blockIdx.x * blockDim.x + threadIdx.x;
    if (i >= n4) return;
    float4 x = ((const float4*)src)[i];
    uint32_t h0, l0, h1, l1;
    split2h(x.x, x.y, h0, l0);
    split2h(x.z, x.w, h1, l1);
    ((uint32_t*)hi)[i * 2 + 0] = h0;
    ((uint32_t*)hi)[i * 2 + 1] = h1;
    ((uint32_t*)lo)[i * 2 + 0] = l0;
    ((uint32_t*)lo)[i * 2 + 1] = l1;
}

// ---------------- HMMA projection GEMM (fp16, 2-pass) ----------------
// C = Xh * (Wh + Wl)^T : passes aH*bH + aH*bL. A stored fp16-only.
#define BK      32
#define SKB     80
#define MAT_B   (128 * SKB)
#define OFF_AH  0
#define OFF_BH  (MAT_B)
#define OFF_BL  (2 * MAT_B)
#define STAGE_B (3 * MAT_B)           // 30720
#define PROJ_SMEM (2 * STAGE_B)       // 61440

__global__ __launch_bounds__(256) void proj_hmma(const __half* __restrict__ Ah,
                                                 const __half* __restrict__ Bhi,
                                                 const __half* __restrict__ Blo,
                                                 const float* __restrict__ bias,
                                                 __half* __restrict__ DstH,
                                                 __half* __restrict__ DstL,
                                                 float scale)
{
    extern __shared__ char smem[];
    const uint32_t sb = smem_u32(smem);
    const int t    = threadIdx.x;
    const int lane = t & 31;
    const int wid  = t >> 5;
    const int wm   = wid & 1;
    const int wn   = wid >> 1;
    const int n0   = blockIdx.x * 128;
    const int m0   = blockIdx.y * 128;

    const int c0r = t >> 2,         c0p = t & 3;
    const int c1r = (t + 256) >> 2, c1p = (t + 256) & 3;

    const uint32_t aRow = (uint32_t)((wm * 64 + (lane & 15)) * SKB + (lane >> 4) * 16);
    const uint32_t bRow = (uint32_t)((wn * 32 + (((lane >> 4) << 3) | (lane & 7))) * SKB
                                     + ((lane >> 3) & 1) * 16);

    float acc[4][4][4] = {};
    const int NSTAGE = EMB / BK;

    auto issue = [&](int s) {
        const int k0 = s * BK;
        const uint32_t buf = sb + (uint32_t)(s & 1) * STAGE_B;
        {
            uint32_t so = (uint32_t)(c0r * SKB + c0p * 16);
            size_t ga = (size_t)(m0 + c0r) * EMB + k0 + c0p * 8;
            size_t gb = (size_t)(n0 + c0r) * EMB + k0 + c0p * 8;
            cp_async16(buf + OFF_AH + so, Ah + ga);
            cp_async16(buf + OFF_BH + so, Bhi + gb);
            cp_async16(buf + OFF_BL + so, Blo + gb);
        }
        {
            uint32_t so = (uint32_t)(c1r * SKB + c1p * 16);
            size_t ga = (size_t)(m0 + c1r) * EMB + k0 + c1p * 8;
            size_t gb = (size_t)(n0 + c1r) * EMB + k0 + c1p * 8;
            cp_async16(buf + OFF_AH + so, Ah + ga);
            cp_async16(buf + OFF_BH + so, Bhi + gb);
            cp_async16(buf + OFF_BL + so, Blo + gb);
        }
        CP_COMMIT();
    };

    issue(0);
    issue(1);

    for (int s = 0; s < NSTAGE; s++) {
        if (s + 1 < NSTAGE) { CP_WAIT1(); } else { CP_WAIT0(); }
        __syncthreads();
        const uint32_t buf = sb + (uint32_t)(s & 1) * STAGE_B;

#pragma unroll
        for (int kc = 0; kc < BK; kc += 16) {
            uint32_t aH[4][4], bH[2][4], bL[2][4];
#pragma unroll
            for (int mt = 0; mt < 4; mt++) {
                uint32_t off = aRow + (uint32_t)(mt * 16 * SKB + kc * 2);
                ldsm4(aH[mt], buf + OFF_AH + off);
            }
#pragma unroll
            for (int g = 0; g < 2; g++) {
                uint32_t off = bRow + (uint32_t)(g * 16 * SKB + kc * 2);
                ldsm4(bH[g], buf + OFF_BH + off);
                ldsm4(bL[g], buf + OFF_BL + off);
            }
#pragma unroll
            for (int mt = 0; mt < 4; mt++)
#pragma unroll
                for (int nt = 0; nt < 4; nt++)
                    mma_f16(acc[mt][nt], aH[mt], bH[nt >> 1][(nt & 1) * 2], bH[nt >> 1][(nt & 1) * 2 + 1]);
#pragma unroll
            for (int mt = 0; mt < 4; mt++)
#pragma unroll
                for (int nt = 0; nt < 4; nt++)
                    mma_f16(acc[mt][nt], aH[mt], bL[nt >> 1][(nt & 1) * 2], bL[nt >> 1][(nt & 1) * 2 + 1]);
        }

        __syncthreads();
        if (s + 2 < NSTAGE) issue(s + 2);
    }

    // epilogue: (acc + bias) * scale -> fp16 hi/lo into [b,h,s,d]
    const int rbase = lane >> 2;
    const int cbase = (lane & 3) * 2;
#pragma unroll
    for (int mt = 0; mt < 4; mt++) {
#pragma unroll
        for (int half_ = 0; half_ < 2; half_++) {
            const int m = m0 + wm * 64 + mt * 16 + rbase + half_ * 8;
            const int b = m >> 11;
            const int sdx = m & (SEQ - 1);
#pragma unroll
            for (int nt = 0; nt < 4; nt++) {
                const int n = n0 + wn * 32 + nt * 8 + cbase;
                const int h = n >> 6;
                const int d = n & 63;
                float fx = (acc[mt][nt][half_ * 2 + 0] + bias[n + 0]) * scale;
                float fy = (acc[mt][nt][half_ * 2 + 1] + bias[n + 1]) * scale;
                uint32_t hw, lw;
                split2h(fx, fy, hw, lw);
                size_t o = (((size_t)(b * NH + h)) * SEQ + sdx) * DH + d;
                *(uint32_t*)(DstH + o) = hw;
                *(uint32_t*)(DstL + o) = lw;
            }
        }
    }
}

// ---------------- HMMA causal flash attention (fp16, 2-pass) ----------------
// S = Qh*(Kh+Kl)^T (Q quantized); O += Ph*(Vh+Vl) (P quantized).
// 4-stage KV ring, one barrier per tile; ex2 softmax (log2e in Q scale).
#define ASTR   144
#define AQ_B   (128 * ASTR)
#define AKV_B  (64 * ASTR)
#define AOFF_KH 0
#define AOFF_KL (AKV_B)
#define AOFF_VH (2 * AKV_B)
#define AOFF_VL (3 * AKV_B)
#define AKV_STAGE (4 * AKV_B)                   // 36864
#define AKV_OFF (AQ_B)
#define ATTN_SMEM (AQ_B + 4 * AKV_STAGE)        // 165888

__global__ __launch_bounds__(256) void attn_hmma(const __half* __restrict__ Qh,
                                                 const __half* __restrict__ Kh,
                                                 const __half* __restrict__ Kl,
                                                 const __half* __restrict__ Vh,
                                                 const __half* __restrict__ Vl,
                                                 float* __restrict__ out)
{
    extern __shared__ char smem[];
    const uint32_t sb = smem_u32(smem);
    const int t    = threadIdx.x;
    const int lane = t & 31;
    const int wid  = t >> 5;
    const int qb   = 15 - (int)blockIdx.x;   // longest-first
    const int bh   = blockIdx.y;
    const int q0   = qb * 128;

    const size_t base = (size_t)bh * SEQ * DH;
    const __half* qh = Qh + base;
    const __half* kh = Kh + base;
    const __half* kl = Kl + base;
    const __half* vh = Vh + base;
    const __half* vl = Vl + base;

    // Q hi tile -> smem (one commit group)
#pragma unroll
    for (int i = 0; i < 4; i++) {
        int id = t + i * 256;
        int row = id >> 3, part = id & 7;
        size_t g = (size_t)(q0 + row) * DH + part * 8;
        uint32_t so = (uint32_t)(row * ASTR + part * 16);
        cp_async16(sb + so, qh + g);
    }
    CP_COMMIT();

    auto issueKV = [&](int kb) {
        const uint32_t buf = sb + AKV_OFF + (uint32_t)(kb & 3) * AKV_STAGE;
        const int k0 = kb * 64;
#pragma unroll
        for (int i = 0; i < 2; i++) {
            int id = t + i * 256;
            int row = id >> 3, part = id & 7;
            size_t g = (size_t)(k0 + row) * DH + part * 8;
            uint32_t so = (uint32_t)(row * ASTR + part * 16);
            cp_async16(buf + AOFF_KH + so, kh + g);
            cp_async16(buf + AOFF_KL + so, kl + g);
            cp_async16(buf + AOFF_VH + so, vh + g);
            cp_async16(buf + AOFF_VL + so, vl + g);
        }
        CP_COMMIT();
    };

    const int nkb = 2 * qb + 2;
    issueKV(0);
    issueKV(1);
    if (nkb > 2) issueKV(2);

    // wait for Q + KV0 (nkb==2 has only 3 groups total)
    if (nkb > 2) { CP_WAIT2(); } else { CP_WAIT1(); }
    __syncthreads();
    uint32_t qhF[4][4];
    {
        const uint32_t aRow = (uint32_t)((wid * 16 + (lane & 15)) * ASTR + (lane >> 4) * 16);
#pragma unroll
        for (int kt = 0; kt < 4; kt++)
            ldsm4(qhF[kt], sb + aRow + kt * 32);
    }

    float m0r = -1e30f, m1r = -1e30f, l0r = 0.f, l1r = 0.f;
    float o[8][4] = {};

    const uint32_t kLane = (uint32_t)(((((lane >> 4) << 3) | (lane & 7)) * ASTR) + ((lane >> 3) & 1) * 16);
    const uint32_t vLane = (uint32_t)(((((lane >> 3) & 1) * 8 + (lane & 7)) * ASTR) + ((lane >> 4) & 1) * 16);

    for (int kb = 0; kb < nkb; kb++) {
        if (kb > 0) {
            const int pending = ((kb + 2 < nkb) ? kb + 2 : nkb - 1) - kb;
            if (pending >= 2)      { CP_WAIT2(); }
            else if (pending == 1) { CP_WAIT1(); }
            else                   { CP_WAIT0(); }
            __syncthreads();   // all warps done with tile kb-1
        }
        if (kb + 3 < nkb) issueKV(kb + 3);

        const uint32_t buf = sb + AKV_OFF + (uint32_t)(kb & 3) * AKV_STAGE;
        const int k0 = kb * 64;

        // ---- S = Qh (Kh + Kl)^T : 2 passes ----
        float s[8][4] = {};
#pragma unroll
        for (int kt = 0; kt < 4; kt++) {
            uint32_t kh4[4][4], kl4[4][4];
#pragma unroll
            for (int g = 0; g < 4; g++) {
                uint32_t off = kLane + (uint32_t)(g * 16 * ASTR + kt * 32);
                ldsm4(kh4[g], buf + AOFF_KH + off);
                ldsm4(kl4[g], buf + AOFF_KL + off);
            }
#pragma unroll
            for (int g = 0; g < 4; g++)
#pragma unroll
                for (int hf = 0; hf < 2; hf++) {
                    int nt = g * 2 + hf;
                    mma_f16(s[nt], qhF[kt], kh4[g][hf * 2], kh4[g][hf * 2 + 1]);
                    mma_f16(s[nt], qhF[kt], kl4[g][hf * 2], kl4[g][hf * 2 + 1]);
                }
        }

        // ---- causal mask ----
        if (k0 + 63 > q0 + wid * 16) {
            const int r0 = q0 + wid * 16 + (lane >> 2);
            const int r1 = r0 + 8;
#pragma unroll
            for (int nt = 0; nt < 8; nt++) {
                const int c = k0 + nt * 8 + (lane & 3) * 2;
                if (c > r0)     s[nt][0] = -1e30f;
                if (c + 1 > r0) s[nt][1] = -1e30f;
                if (c > r1)     s[nt][2] = -1e30f;
                if (c + 1 > r1) s[nt][3] = -1e30f;
            }
        }

        // ---- online softmax (base-2) ----
        float mx0 = s[0][0], mx1 = s[0][2];
#pragma unroll
        for (int nt = 0; nt < 8; nt++) {
            mx0 = fmaxf(mx0, fmaxf(s[nt][0], s[nt][1]));
            mx1 = fmaxf(mx1, fmaxf(s[nt][2], s[nt][3]));
        }
        mx0 = fmaxf(mx0, __shfl_xor_sync(0xffffffff, mx0, 1));
        mx0 = fmaxf(mx0, __shfl_xor_sync(0xffffffff, mx0, 2));
        mx1 = fmaxf(mx1, __shfl_xor_sync(0xffffffff, mx1, 1));
        mx1 = fmaxf(mx1, __shfl_xor_sync(0xffffffff, mx1, 2));
        const float mn0 = fmaxf(m0r, mx0), mn1 = fmaxf(m1r, mx1);
        const float a0 = ex2(m0r - mn0), a1 = ex2(m1r - mn1);
        m0r = mn0; m1r = mn1;
        float sum0 = 0.f, sum1 = 0.f;
#pragma unroll
        for (int nt = 0; nt < 8; nt++) {
            s[nt][0] = ex2(s[nt][0] - mn0); sum0 += s[nt][0];
            s[nt][1] = ex2(s[nt][1] - mn0); sum0 += s[nt][1];
            s[nt][2] = ex2(s[nt][2] - mn1); sum1 += s[nt][2];
            s[nt][3] = ex2(s[nt][3] - mn1); sum1 += s[nt][3];
        }
        sum0 += __shfl_xor_sync(0xffffffff, sum0, 1);
        sum0 += __shfl_xor_sync(0xffffffff, sum0, 2);
        sum1 += __shfl_xor_sync(0xffffffff, sum1, 1);
        sum1 += __shfl_xor_sync(0xffffffff, sum1, 2);
        l0r = l0r * a0 + sum0;
        l1r = l1r * a1 + sum1;
#pragma unroll
        for (int n = 0; n < 8; n++) {
            o[n][0] *= a0; o[n][1] *= a0;
            o[n][2] *= a1; o[n][3] *= a1;
        }

        // ---- O += Ph (Vh + Vl) : 2 passes, P quantized to fp16 ----
#pragma unroll
        for (int kt = 0; kt < 4; kt++) {
            uint32_t ph[4];
            const int nt0 = kt * 2, nt1 = kt * 2 + 1;
            ph[0] = pack_h2(s[nt0][0], s[nt0][1]);
            ph[1] = pack_h2(s[nt0][2], s[nt0][3]);
            ph[2] = pack_h2(s[nt1][0], s[nt1][1]);
            ph[3] = pack_h2(s[nt1][2], s[nt1][3]);
#pragma unroll
            for (int g = 0; g < 4; g++) {
                uint32_t vh4[4], vl4[4];
                uint32_t off = vLane + (uint32_t)(kt * 16 * ASTR + g * 32);
                ldsm4t(vh4, buf + AOFF_VH + off);
                ldsm4t(vl4, buf + AOFF_VL + off);
#pragma unroll
                for (int hf = 0; hf < 2; hf++) {
                    int n = g * 2 + hf;
                    mma_f16(o[n], ph, vh4[hf * 2], vh4[hf * 2 + 1]);
                    mma_f16(o[n], ph, vl4[hf * 2], vl4[hf * 2 + 1]);
                }
            }
        }
    }

    // ---- epilogue ----
    const int b  = bh >> 4;
    const int h  = bh & 15;
    const int r0 = q0 + wid * 16 + (lane >> 2);
    const int r1 = r0 + 8;
    const float i0 = 1.f / l0r, i1 = 1.f / l1r;
#pragma unroll
    for (int n = 0; n < 8; n++) {
        const int d = n * 8 + (lane & 3) * 2;
        *(float2*)(out + ((size_t)(b * SEQ + r0)) * NCOLS + h * DH + d) =
            make_float2(o[n][0] * i0, o[n][1] * i0);
        *(float2*)(out + ((size_t)(b * SEQ + r1)) * NCOLS + h * DH + d) =
            make_float2(o[n][2] * i1, o[n][3] * i1);
    }
}

// ---------------------------------------------------------------------------
extern "C" void kernel_launch(void* const* d_in, const int* in_sizes, int n_in,
                              void* d_out, int out_size)
{
    const float* x_q  = (const float*)d_in[0];
    const float* x_kv = (const float*)d_in[1];
    const float* w_q  = (const float*)d_in[3];
    const float* b_q  = (const float*)d_in[4];
    const float* w_k  = (const float*)d_in[5];
    const float* b_k  = (const float*)d_in[6];
    const float* w_v  = (const float*)d_in[7];
    const float* b_v  = (const float*)d_in[8];
    float* out = (float*)d_out;

    __half *xqh, *xkh;
    __half *wqh, *wql, *wkh, *wkl, *wvh, *wvl;
    __half *qhp, *qlp, *khp, *klp, *vhp, *vlp;
    cudaGetSymbolAddress((void**)&xqh, g_xq_h);
    cudaGetSymbolAddress((void**)&xkh, g_xkv_h);
    cudaGetSymbolAddress((void**)&wqh, g_wq_hi);
    cudaGetSymbolAddress((void**)&wql, g_wq_lo);
    cudaGetSymbolAddress((void**)&wkh, g_wk_hi);
    cudaGetSymbolAddress((void**)&wkl, g_wk_lo);
    cudaGetSymbolAddress((void**)&wvh, g_wv_hi);
    cudaGetSymbolAddress((void**)&wvl, g_wv_lo);
    cudaGetSymbolAddress((void**)&qhp, g_qh);
    cudaGetSymbolAddress((void**)&qlp, g_ql);
    cudaGetSymbolAddress((void**)&khp, g_kh);
    cudaGetSymbolAddress((void**)&klp, g_kl);
    cudaGetSymbolAddress((void**)&vhp, g_vh);
    cudaGetSymbolAddress((void**)&vlp, g_vl);

    cudaFuncSetAttribute(proj_hmma, cudaFuncAttributeMaxDynamicSharedMemorySize, PROJ_SMEM);
    cudaFuncSetAttribute(attn_hmma, cudaFuncAttributeMaxDynamicSharedMemorySize, ATTN_SMEM);

    const int nX4 = MROWS * EMB / 4;
    const int nW4 = NCOLS * EMB / 4;
    conv_h  <<<(nX4 + 255) / 256, 256>>>(x_q,  xqh, nX4);
    conv_h  <<<(nX4 + 255) / 256, 256>>>(x_kv, xkh, nX4);
    split_hl<<<(nW4 + 255) / 256, 256>>>(w_q,  wqh, wql, nW4);
    split_hl<<<(nW4 + 255) / 256, 256>>>(w_k,  wkh, wkl, nW4);
    split_hl<<<(nW4 + 255) / 256, 256>>>(w_v,  wvh, wvl, nW4);

    dim3 pgrid(NCOLS / 128, MROWS / 128);   // (8, 64)
    // Q scale folds 1/sqrt(64) AND log2(e) for the base-2 softmax
    proj_hmma<<<pgrid, 256, PROJ_SMEM>>>(xqh, wqh, wql, b_q, qhp, qlp, 0.125f * 1.44269504f);
    proj_hmma<<<pgrid, 256, PROJ_SMEM>>>(xkh, wkh, wkl, b_k, khp, klp, 1.0f);
    proj_hmma<<<pgrid, 256, PROJ_SMEM>>>(xkh, wvh, wvl, b_v, vhp, vlp, 1.0f);

    dim3 agrid(SEQ / 128, BSZ * NH);        // (16, 64)
    attn_hmma<<<agrid, 256, ATTN_SMEM>>>(qhp, khp, klp, vhp, vlp, out);
}

// round 13
// speedup vs baseline: 2.8973x; 1.3676x over previous
#include <cuda_runtime.h>
#include <cuda_fp16.h>
#include <cstdint>

#define EMB  1024
#define NH   16
#define DH   64
#define BSZ  4
#define SEQ  2048
#define MROWS (BSZ*SEQ)   // 8192
#define NCOLS (NH*DH)     // 1024

// ---------------- scratch (allocation-guard safe) ----------------
__device__ __half g_xq_h[(size_t)MROWS*EMB];
__device__ __half g_xkv_h[(size_t)MROWS*EMB];
__device__ __half g_wq_hi[(size_t)NCOLS*EMB];
__device__ __half g_wq_lo[(size_t)NCOLS*EMB];
__device__ __half g_wk_hi[(size_t)NCOLS*EMB];
__device__ __half g_wk_lo[(size_t)NCOLS*EMB];
__device__ __half g_wv_hi[(size_t)NCOLS*EMB];
__device__ __half g_wv_lo[(size_t)NCOLS*EMB];

// projected Q/K/V (fp16, single precision level), layout [b,h,s,d]
__device__ __half g_qh[(size_t)BSZ*NH*SEQ*DH];
__device__ __half g_kh[(size_t)BSZ*NH*SEQ*DH];
__device__ __half g_vh[(size_t)BSZ*NH*SEQ*DH];

// ---------------- helpers (base sm_103-safe ISA only) ----------------
__device__ __forceinline__ uint32_t smem_u32(const void* p) {
    uint32_t a;
    asm("{ .reg .u64 t; cvta.to.shared.u64 t, %1; cvt.u32.u64 %0, t; }" : "=r"(a) : "l"(p));
    return a;
}
__device__ __forceinline__ void ldsm4(uint32_t* r, uint32_t addr) {
    asm volatile("ldmatrix.sync.aligned.m8n8.x4.shared.b16 {%0,%1,%2,%3}, [%4];"
                 : "=r"(r[0]), "=r"(r[1]), "=r"(r[2]), "=r"(r[3]) : "r"(addr));
}
__device__ __forceinline__ void ldsm4t(uint32_t* r, uint32_t addr) {
    asm volatile("ldmatrix.sync.aligned.m8n8.x4.trans.shared.b16 {%0,%1,%2,%3}, [%4];"
                 : "=r"(r[0]), "=r"(r[1]), "=r"(r[2]), "=r"(r[3]) : "r"(addr));
}
__device__ __forceinline__ void mma_f16(float* c, const uint32_t* a, uint32_t b0, uint32_t b1) {
    asm volatile("mma.sync.aligned.m16n8k16.row.col.f32.f16.f16.f32 "
                 "{%0,%1,%2,%3}, {%4,%5,%6,%7}, {%8,%9}, {%0,%1,%2,%3};"
                 : "+f"(c[0]), "+f"(c[1]), "+f"(c[2]), "+f"(c[3])
                 : "r"(a[0]), "r"(a[1]), "r"(a[2]), "r"(a[3]), "r"(b0), "r"(b1));
}
__device__ __forceinline__ void cp_async16(uint32_t saddr, const void* gptr) {
    asm volatile("cp.async.cg.shared.global [%0], [%1], 16;" :: "r"(saddr), "l"(gptr) : "memory");
}
#define CP_COMMIT() asm volatile("cp.async.commit_group;" ::: "memory")
#define CP_WAIT2()  asm volatile("cp.async.wait_group 2;" ::: "memory")
#define CP_WAIT1()  asm volatile("cp.async.wait_group 1;" ::: "memory")
#define CP_WAIT0()  asm volatile("cp.async.wait_group 0;" ::: "memory")

__device__ __forceinline__ float ex2(float x) {
    float r;
    asm("ex2.approx.f32 %0, %1;" : "=f"(r) : "f"(x));
    return r;
}
__device__ __forceinline__ uint32_t pack_h2(float a, float b) {
    __half2 h = __floats2half2_rn(a, b);
    return *reinterpret_cast<uint32_t*>(&h);
}
__device__ __forceinline__ void split2h(float a, float b, uint32_t& hi, uint32_t& lo) {
    __half ha = __float2half_rn(a), hb = __float2half_rn(b);
    __half la = __float2half_rn(a - __half2float(ha));
    __half lb = __float2half_rn(b - __half2float(hb));
    __half2 H = __halves2half2(ha, hb), L = __halves2half2(la, lb);
    hi = *reinterpret_cast<uint32_t*>(&H);
    lo = *reinterpret_cast<uint32_t*>(&L);
}

// ---------------- fp32 -> fp16 (hi only, for X) ----------------
__global__ __launch_bounds__(256) void conv_h(const float* __restrict__ src,
                                              __half* __restrict__ hi, int n4)
{
    int i = blockIdx.x * blockDim.x + threadIdx.x;
    if (i >= n4) return;
    float4 x = ((const float4*)src)[i];
    ((uint32_t*)hi)[i * 2 + 0] = pack_h2(x.x, x.y);
    ((uint32_t*)hi)[i * 2 + 1] = pack_h2(x.z, x.w);
}
// ---------------- fp32 -> fp16 hi/lo (for W) ----------------
__global__ __launch_bounds__(256) void split_hl(const float* __restrict__ src,
                                                __half* __restrict__ hi,
                                                __half* __restrict__ lo, int n4)
{
    int i = blockIdx.x * blockDim.x + threadIdx.x;
    if (i >= n4) return;
    float4 x = ((const float4*)src)[i];
    uint32_t h0, l0, h1, l1;
    split2h(x.x, x.y, h0, l0);
    split2h(x.z, x.w, h1, l1);
    ((uint32_t*)hi)[i * 2 + 0] = h0;
    ((uint32_t*)hi)[i * 2 + 1] = h1;
    ((uint32_t*)lo)[i * 2 + 0] = l0;
    ((uint32_t*)lo)[i * 2 + 1] = l1;
}

// ---------------- HMMA projection GEMM (fp16, 2-pass, R12 config) ----------------
#define BK      32
#define SKB     80
#define MAT_B   (128 * SKB)
#define OFF_AH  0
#define OFF_BH  (MAT_B)
#define OFF_BL  (2 * MAT_B)
#define STAGE_B (3 * MAT_B)           // 30720
#define PROJ_SMEM (2 * STAGE_B)       // 61440

__global__ __launch_bounds__(256) void proj_hmma(const __half* __restrict__ Ah,
                                                 const __half* __restrict__ Bhi,
                                                 const __half* __restrict__ Blo,
                                                 const float* __restrict__ bias,
                                                 __half* __restrict__ DstH,
                                                 float scale)
{
    extern __shared__ char smem[];
    const uint32_t sb = smem_u32(smem);
    const int t    = threadIdx.x;
    const int lane = t & 31;
    const int wid  = t >> 5;
    const int wm   = wid & 1;
    const int wn   = wid >> 1;
    const int n0   = blockIdx.x * 128;
    const int m0   = blockIdx.y * 128;

    const int c0r = t >> 2,         c0p = t & 3;
    const int c1r = (t + 256) >> 2, c1p = (t + 256) & 3;

    const uint32_t aRow = (uint32_t)((wm * 64 + (lane & 15)) * SKB + (lane >> 4) * 16);
    const uint32_t bRow = (uint32_t)((wn * 32 + (((lane >> 4) << 3) | (lane & 7))) * SKB
                                     + ((lane >> 3) & 1) * 16);

    float acc[4][4][4] = {};
    const int NSTAGE = EMB / BK;

    auto issue = [&](int s) {
        const int k0 = s * BK;
        const uint32_t buf = sb + (uint32_t)(s & 1) * STAGE_B;
        {
            uint32_t so = (uint32_t)(c0r * SKB + c0p * 16);
            size_t ga = (size_t)(m0 + c0r) * EMB + k0 + c0p * 8;
            size_t gb = (size_t)(n0 + c0r) * EMB + k0 + c0p * 8;
            cp_async16(buf + OFF_AH + so, Ah + ga);
            cp_async16(buf + OFF_BH + so, Bhi + gb);
            cp_async16(buf + OFF_BL + so, Blo + gb);
        }
        {
            uint32_t so = (uint32_t)(c1r * SKB + c1p * 16);
            size_t ga = (size_t)(m0 + c1r) * EMB + k0 + c1p * 8;
            size_t gb = (size_t)(n0 + c1r) * EMB + k0 + c1p * 8;
            cp_async16(buf + OFF_AH + so, Ah + ga);
            cp_async16(buf + OFF_BH + so, Bhi + gb);
            cp_async16(buf + OFF_BL + so, Blo + gb);
        }
        CP_COMMIT();
    };

    issue(0);
    issue(1);

    for (int s = 0; s < NSTAGE; s++) {
        if (s + 1 < NSTAGE) { CP_WAIT1(); } else { CP_WAIT0(); }
        __syncthreads();
        const uint32_t buf = sb + (uint32_t)(s & 1) * STAGE_B;

#pragma unroll
        for (int kc = 0; kc < BK; kc += 16) {
            uint32_t aH[4][4], bH[2][4], bL[2][4];
#pragma unroll
            for (int mt = 0; mt < 4; mt++) {
                uint32_t off = aRow + (uint32_t)(mt * 16 * SKB + kc * 2);
                ldsm4(aH[mt], buf + OFF_AH + off);
            }
#pragma unroll
            for (int g = 0; g < 2; g++) {
                uint32_t off = bRow + (uint32_t)(g * 16 * SKB + kc * 2);
                ldsm4(bH[g], buf + OFF_BH + off);
                ldsm4(bL[g], buf + OFF_BL + off);
            }
#pragma unroll
            for (int mt = 0; mt < 4; mt++)
#pragma unroll
                for (int nt = 0; nt < 4; nt++)
                    mma_f16(acc[mt][nt], aH[mt], bH[nt >> 1][(nt & 1) * 2], bH[nt >> 1][(nt & 1) * 2 + 1]);
#pragma unroll
            for (int mt = 0; mt < 4; mt++)
#pragma unroll
                for (int nt = 0; nt < 4; nt++)
                    mma_f16(acc[mt][nt], aH[mt], bL[nt >> 1][(nt & 1) * 2], bL[nt >> 1][(nt & 1) * 2 + 1]);
        }

        __syncthreads();
        if (s + 2 < NSTAGE) issue(s + 2);
    }

    // epilogue: (acc + bias) * scale -> fp16 into [b,h,s,d]
    const int rbase = lane >> 2;
    const int cbase = (lane & 3) * 2;
#pragma unroll
    for (int mt = 0; mt < 4; mt++) {
#pragma unroll
        for (int half_ = 0; half_ < 2; half_++) {
            const int m = m0 + wm * 64 + mt * 16 + rbase + half_ * 8;
            const int b = m >> 11;
            const int sdx = m & (SEQ - 1);
#pragma unroll
            for (int nt = 0; nt < 4; nt++) {
                const int n = n0 + wn * 32 + nt * 8 + cbase;
                const int h = n >> 6;
                const int d = n & 63;
                float fx = (acc[mt][nt][half_ * 2 + 0] + bias[n + 0]) * scale;
                float fy = (acc[mt][nt][half_ * 2 + 1] + bias[n + 1]) * scale;
                size_t o = (((size_t)(b * NH + h)) * SEQ + sdx) * DH + d;
                *(uint32_t*)(DstH + o) = pack_h2(fx, fy);
            }
        }
    }
}

// ---------------- HMMA causal flash attention (fp16, 1-pass) ----------------
// S = Qh*Kh^T; O += Ph*Vh. 4-stage KV ring (18432 B/stage), one barrier/tile,
// ex2 softmax (log2e folded into Q scale). Target 2 CTAs/SM.
#define ASTR   144
#define AQ_B   (128 * ASTR)                     // 18432
#define AKV_B  (64 * ASTR)                      // 9216
#define AOFF_KH 0
#define AOFF_VH (AKV_B)
#define AKV_STAGE (2 * AKV_B)                   // 18432
#define AKV_OFF (AQ_B)
#define ATTN_SMEM (AQ_B + 4 * AKV_STAGE)        // 92160

__global__ __launch_bounds__(256, 2) void attn_hmma(const __half* __restrict__ Qh,
                                                    const __half* __restrict__ Kh,
                                                    const __half* __restrict__ Vh,
                                                    float* __restrict__ out)
{
    extern __shared__ char smem[];
    const uint32_t sb = smem_u32(smem);
    const int t    = threadIdx.x;
    const int lane = t & 31;
    const int wid  = t >> 5;
    const int qb   = 15 - (int)blockIdx.x;   // longest-first
    const int bh   = blockIdx.y;
    const int q0   = qb * 128;

    const size_t base = (size_t)bh * SEQ * DH;
    const __half* qh = Qh + base;
    const __half* kh = Kh + base;
    const __half* vh = Vh + base;

    // Q tile -> smem (one commit group)
#pragma unroll
    for (int i = 0; i < 4; i++) {
        int id = t + i * 256;
        int row = id >> 3, part = id & 7;
        size_t g = (size_t)(q0 + row) * DH + part * 8;
        uint32_t so = (uint32_t)(row * ASTR + part * 16);
        cp_async16(sb + so, qh + g);
    }
    CP_COMMIT();

    auto issueKV = [&](int kb) {
        const uint32_t buf = sb + AKV_OFF + (uint32_t)(kb & 3) * AKV_STAGE;
        const int k0 = kb * 64;
#pragma unroll
        for (int i = 0; i < 2; i++) {
            int id = t + i * 256;
            int row = id >> 3, part = id & 7;
            size_t g = (size_t)(k0 + row) * DH + part * 8;
            uint32_t so = (uint32_t)(row * ASTR + part * 16);
            cp_async16(buf + AOFF_KH + so, kh + g);
            cp_async16(buf + AOFF_VH + so, vh + g);
        }
        CP_COMMIT();
    };

    const int nkb = 2 * qb + 2;
    issueKV(0);
    issueKV(1);
    if (nkb > 2) issueKV(2);

    // wait for Q + KV0 (nkb==2 has only 3 groups total)
    if (nkb > 2) { CP_WAIT2(); } else { CP_WAIT1(); }
    __syncthreads();
    uint32_t qhF[4][4];
    {
        const uint32_t aRow = (uint32_t)((wid * 16 + (lane & 15)) * ASTR + (lane >> 4) * 16);
#pragma unroll
        for (int kt = 0; kt < 4; kt++)
            ldsm4(qhF[kt], sb + aRow + kt * 32);
    }

    float m0r = -1e30f, m1r = -1e30f, l0r = 0.f, l1r = 0.f;
    float o[8][4] = {};

    const uint32_t kLane = (uint32_t)(((((lane >> 4) << 3) | (lane & 7)) * ASTR) + ((lane >> 3) & 1) * 16);
    const uint32_t vLane = (uint32_t)(((((lane >> 3) & 1) * 8 + (lane & 7)) * ASTR) + ((lane >> 4) & 1) * 16);

    for (int kb = 0; kb < nkb; kb++) {
        if (kb > 0) {
            const int pending = ((kb + 2 < nkb) ? kb + 2 : nkb - 1) - kb;
            if (pending >= 2)      { CP_WAIT2(); }
            else if (pending == 1) { CP_WAIT1(); }
            else                   { CP_WAIT0(); }
            __syncthreads();   // all warps done with tile kb-1
        }
        if (kb + 3 < nkb) issueKV(kb + 3);

        const uint32_t buf = sb + AKV_OFF + (uint32_t)(kb & 3) * AKV_STAGE;
        const int k0 = kb * 64;

        // ---- S = Qh Kh^T : 1 pass ----
        float s[8][4] = {};
#pragma unroll
        for (int kt = 0; kt < 4; kt++) {
            uint32_t kh4[4][4];
#pragma unroll
            for (int g = 0; g < 4; g++) {
                uint32_t off = kLane + (uint32_t)(g * 16 * ASTR + kt * 32);
                ldsm4(kh4[g], buf + AOFF_KH + off);
            }
#pragma unroll
            for (int g = 0; g < 4; g++)
#pragma unroll
                for (int hf = 0; hf < 2; hf++) {
                    int nt = g * 2 + hf;
                    mma_f16(s[nt], qhF[kt], kh4[g][hf * 2], kh4[g][hf * 2 + 1]);
                }
        }

        // ---- causal mask ----
        if (k0 + 63 > q0 + wid * 16) {
            const int r0 = q0 + wid * 16 + (lane >> 2);
            const int r1 = r0 + 8;
#pragma unroll
            for (int nt = 0; nt < 8; nt++) {
                const int c = k0 + nt * 8 + (lane & 3) * 2;
                if (c > r0)     s[nt][0] = -1e30f;
                if (c + 1 > r0) s[nt][1] = -1e30f;
                if (c > r1)     s[nt][2] = -1e30f;
                if (c + 1 > r1) s[nt][3] = -1e30f;
            }
        }

        // ---- online softmax (base-2) ----
        float mx0 = s[0][0], mx1 = s[0][2];
#pragma unroll
        for (int nt = 0; nt < 8; nt++) {
            mx0 = fmaxf(mx0, fmaxf(s[nt][0], s[nt][1]));
            mx1 = fmaxf(mx1, fmaxf(s[nt][2], s[nt][3]));
        }
        mx0 = fmaxf(mx0, __shfl_xor_sync(0xffffffff, mx0, 1));
        mx0 = fmaxf(mx0, __shfl_xor_sync(0xffffffff, mx0, 2));
        mx1 = fmaxf(mx1, __shfl_xor_sync(0xffffffff, mx1, 1));
        mx1 = fmaxf(mx1, __shfl_xor_sync(0xffffffff, mx1, 2));
        const float mn0 = fmaxf(m0r, mx0), mn1 = fmaxf(m1r, mx1);
        const float a0 = ex2(m0r - mn0), a1 = ex2(m1r - mn1);
        m0r = mn0; m1r = mn1;
        float sum0 = 0.f, sum1 = 0.f;
#pragma unroll
        for (int nt = 0; nt < 8; nt++) {
            s[nt][0] = ex2(s[nt][0] - mn0); sum0 += s[nt][0];
            s[nt][1] = ex2(s[nt][1] - mn0); sum0 += s[nt][1];
            s[nt][2] = ex2(s[nt][2] - mn1); sum1 += s[nt][2];
            s[nt][3] = ex2(s[nt][3] - mn1); sum1 += s[nt][3];
        }
        sum0 += __shfl_xor_sync(0xffffffff, sum0, 1);
        sum0 += __shfl_xor_sync(0xffffffff, sum0, 2);
        sum1 += __shfl_xor_sync(0xffffffff, sum1, 1);
        sum1 += __shfl_xor_sync(0xffffffff, sum1, 2);
        l0r = l0r * a0 + sum0;
        l1r = l1r * a1 + sum1;
#pragma unroll
        for (int n = 0; n < 8; n++) {
            o[n][0] *= a0; o[n][1] *= a0;
            o[n][2] *= a1; o[n][3] *= a1;
        }

        // ---- O += Ph Vh : 1 pass ----
#pragma unroll
        for (int kt = 0; kt < 4; kt++) {
            uint32_t ph[4];
            const int nt0 = kt * 2, nt1 = kt * 2 + 1;
            ph[0] = pack_h2(s[nt0][0], s[nt0][1]);
            ph[1] = pack_h2(s[nt0][2], s[nt0][3]);
            ph[2] = pack_h2(s[nt1][0], s[nt1][1]);
            ph[3] = pack_h2(s[nt1][2], s[nt1][3]);
#pragma unroll
            for (int g = 0; g < 4; g++) {
                uint32_t vh4[4];
                uint32_t off = vLane + (uint32_t)(kt * 16 * ASTR + g * 32);
                ldsm4t(vh4, buf + AOFF_VH + off);
#pragma unroll
                for (int hf = 0; hf < 2; hf++) {
                    int n = g * 2 + hf;
                    mma_f16(o[n], ph, vh4[hf * 2], vh4[hf * 2 + 1]);
                }
            }
        }
    }

    // ---- epilogue ----
    const int b  = bh >> 4;
    const int h  = bh & 15;
    const int r0 = q0 + wid * 16 + (lane >> 2);
    const int r1 = r0 + 8;
    const float i0 = 1.f / l0r, i1 = 1.f / l1r;
#pragma unroll
    for (int n = 0; n < 8; n++) {
        const int d = n * 8 + (lane & 3) * 2;
        *(float2*)(out + ((size_t)(b * SEQ + r0)) * NCOLS + h * DH + d) =
            make_float2(o[n][0] * i0, o[n][1] * i0);
        *(float2*)(out + ((size_t)(b * SEQ + r1)) * NCOLS + h * DH + d) =
            make_float2(o[n][2] * i1, o[n][3] * i1);
    }
}

// ---------------------------------------------------------------------------
extern "C" void kernel_launch(void* const* d_in, const int* in_sizes, int n_in,
                              void* d_out, int out_size)
{
    const float* x_q  = (const float*)d_in[0];
    const float* x_kv = (const float*)d_in[1];
    const float* w_q  = (const float*)d_in[3];
    const float* b_q  = (const float*)d_in[4];
    const float* w_k  = (const float*)d_in[5];
    const float* b_k  = (const float*)d_in[6];
    const float* w_v  = (const float*)d_in[7];
    const float* b_v  = (const float*)d_in[8];
    float* out = (float*)d_out;

    __half *xqh, *xkh;
    __half *wqh, *wql, *wkh, *wkl, *wvh, *wvl;
    __half *qhp, *khp, *vhp;
    cudaGetSymbolAddress((void**)&xqh, g_xq_h);
    cudaGetSymbolAddress((void**)&xkh, g_xkv_h);
    cudaGetSymbolAddress((void**)&wqh, g_wq_hi);
    cudaGetSymbolAddress((void**)&wql, g_wq_lo);
    cudaGetSymbolAddress((void**)&wkh, g_wk_hi);
    cudaGetSymbolAddress((void**)&wkl, g_wk_lo);
    cudaGetSymbolAddress((void**)&wvh, g_wv_hi);
    cudaGetSymbolAddress((void**)&wvl, g_wv_lo);
    cudaGetSymbolAddress((void**)&qhp, g_qh);
    cudaGetSymbolAddress((void**)&khp, g_kh);
    cudaGetSymbolAddress((void**)&vhp, g_vh);

    cudaFuncSetAttribute(proj_hmma, cudaFuncAttributeMaxDynamicSharedMemorySize, PROJ_SMEM);
    cudaFuncSetAttribute(attn_hmma, cudaFuncAttributeMaxDynamicSharedMemorySize, ATTN_SMEM);

    const int nX4 = MROWS * EMB / 4;
    const int nW4 = NCOLS * EMB / 4;
    conv_h  <<<(nX4 + 255) / 256, 256>>>(x_q,  xqh, nX4);
    conv_h  <<<(nX4 + 255) / 256, 256>>>(x_kv, xkh, nX4);
    split_hl<<<(nW4 + 255) / 256, 256>>>(w_q,  wqh, wql, nW4);
    split_hl<<<(nW4 + 255) / 256, 256>>>(w_k,  wkh, wkl, nW4);
    split_hl<<<(nW4 + 255) / 256, 256>>>(w_v,  wvh, wvl, nW4);

    dim3 pgrid(NCOLS / 128, MROWS / 128);   // (8, 64)
    // Q scale folds 1/sqrt(64) AND log2(e) for the base-2 softmax
    proj_hmma<<<pgrid, 256, PROJ_SMEM>>>(xqh, wqh, wql, b_q, qhp, 0.125f * 1.44269504f);
    proj_hmma<<<pgrid, 256, PROJ_SMEM>>>(xkh, wkh, wkl, b_k, khp, 1.0f);
    proj_hmma<<<pgrid, 256, PROJ_SMEM>>>(xkh, wvh, wvl, b_v, vhp, 1.0f);

    dim3 agrid(SEQ / 128, BSZ * NH);        // (16, 64)
    attn_hmma<<<agrid, 256, ATTN_SMEM>>>(qhp, khp, vhp, out);
}

// round 14
// speedup vs baseline: 3.8088x; 1.3146x over previous
#include <cuda_runtime.h>
#include <cuda_fp16.h>
#include <cstdint>

#define EMB  1024
#define NH   16
#define DH   64
#define BSZ  4
#define SEQ  2048
#define MROWS (BSZ*SEQ)   // 8192
#define NCOLS (NH*DH)     // 1024

// ---------------- scratch (allocation-guard safe) ----------------
__device__ __half g_xq_h[(size_t)MROWS*EMB];
__device__ __half g_xkv_h[(size_t)MROWS*EMB];
__device__ __half g_wq_h[(size_t)NCOLS*EMB];
__device__ __half g_wk_h[(size_t)NCOLS*EMB];
__device__ __half g_wv_h[(size_t)NCOLS*EMB];

// projected Q/K/V (fp16), layout [b,h,s,d]
__device__ __half g_qh[(size_t)BSZ*NH*SEQ*DH];
__device__ __half g_kh[(size_t)BSZ*NH*SEQ*DH];
__device__ __half g_vh[(size_t)BSZ*NH*SEQ*DH];

// ---------------- helpers (base sm_103-safe ISA only) ----------------
__device__ __forceinline__ uint32_t smem_u32(const void* p) {
    uint32_t a;
    asm("{ .reg .u64 t; cvta.to.shared.u64 t, %1; cvt.u32.u64 %0, t; }" : "=r"(a) : "l"(p));
    return a;
}
__device__ __forceinline__ void ldsm4(uint32_t* r, uint32_t addr) {
    asm volatile("ldmatrix.sync.aligned.m8n8.x4.shared.b16 {%0,%1,%2,%3}, [%4];"
                 : "=r"(r[0]), "=r"(r[1]), "=r"(r[2]), "=r"(r[3]) : "r"(addr));
}
__device__ __forceinline__ void ldsm4t(uint32_t* r, uint32_t addr) {
    asm volatile("ldmatrix.sync.aligned.m8n8.x4.trans.shared.b16 {%0,%1,%2,%3}, [%4];"
                 : "=r"(r[0]), "=r"(r[1]), "=r"(r[2]), "=r"(r[3]) : "r"(addr));
}
__device__ __forceinline__ void mma_f16(float* c, const uint32_t* a, uint32_t b0, uint32_t b1) {
    asm volatile("mma.sync.aligned.m16n8k16.row.col.f32.f16.f16.f32 "
                 "{%0,%1,%2,%3}, {%4,%5,%6,%7}, {%8,%9}, {%0,%1,%2,%3};"
                 : "+f"(c[0]), "+f"(c[1]), "+f"(c[2]), "+f"(c[3])
                 : "r"(a[0]), "r"(a[1]), "r"(a[2]), "r"(a[3]), "r"(b0), "r"(b1));
}
__device__ __forceinline__ void cp_async16(uint32_t saddr, const void* gptr) {
    asm volatile("cp.async.cg.shared.global [%0], [%1], 16;" :: "r"(saddr), "l"(gptr) : "memory");
}
#define CP_COMMIT() asm volatile("cp.async.commit_group;" ::: "memory")
#define CP_WAIT2()  asm volatile("cp.async.wait_group 2;" ::: "memory")
#define CP_WAIT1()  asm volatile("cp.async.wait_group 1;" ::: "memory")
#define CP_WAIT0()  asm volatile("cp.async.wait_group 0;" ::: "memory")

__device__ __forceinline__ float ex2(float x) {
    float r;
    asm("ex2.approx.f32 %0, %1;" : "=f"(r) : "f"(x));
    return r;
}
__device__ __forceinline__ uint32_t pack_h2(float a, float b) {
    __half2 h = __floats2half2_rn(a, b);
    return *reinterpret_cast<uint32_t*>(&h);
}

// ---------------- fp32 -> fp16 ----------------
__global__ __launch_bounds__(256) void conv_h(const float* __restrict__ src,
                                              __half* __restrict__ hi, int n4)
{
    int i = blockIdx.x * blockDim.x + threadIdx.x;
    if (i >= n4) return;
    float4 x = ((const float4*)src)[i];
    ((uint32_t*)hi)[i * 2 + 0] = pack_h2(x.x, x.y);
    ((uint32_t*)hi)[i * 2 + 1] = pack_h2(x.z, x.w);
}

// ---------------- HMMA projection GEMM (fp16, 1-pass) ----------------
// C = Xh * Wh^T, fp32 accumulate. 2-stage cp.async, 2 CTAs/SM target.
#define BK      32
#define SKB     80
#define MAT_B   (128 * SKB)
#define OFF_AH  0
#define OFF_BH  (MAT_B)
#define STAGE_B (2 * MAT_B)           // 20480
#define PROJ_SMEM (2 * STAGE_B)       // 40960

__global__ __launch_bounds__(256, 2) void proj_hmma(const __half* __restrict__ Ah,
                                                    const __half* __restrict__ Bh,
                                                    const float* __restrict__ bias,
                                                    __half* __restrict__ DstH,
                                                    float scale)
{
    extern __shared__ char smem[];
    const uint32_t sb = smem_u32(smem);
    const int t    = threadIdx.x;
    const int lane = t & 31;
    const int wid  = t >> 5;
    const int wm   = wid & 1;
    const int wn   = wid >> 1;
    const int n0   = blockIdx.x * 128;
    const int m0   = blockIdx.y * 128;

    const int c0r = t >> 2,         c0p = t & 3;
    const int c1r = (t + 256) >> 2, c1p = (t + 256) & 3;

    const uint32_t aRow = (uint32_t)((wm * 64 + (lane & 15)) * SKB + (lane >> 4) * 16);
    const uint32_t bRow = (uint32_t)((wn * 32 + (((lane >> 4) << 3) | (lane & 7))) * SKB
                                     + ((lane >> 3) & 1) * 16);

    float acc[4][4][4] = {};
    const int NSTAGE = EMB / BK;

    auto issue = [&](int s) {
        const int k0 = s * BK;
        const uint32_t buf = sb + (uint32_t)(s & 1) * STAGE_B;
        {
            uint32_t so = (uint32_t)(c0r * SKB + c0p * 16);
            cp_async16(buf + OFF_AH + so, Ah + (size_t)(m0 + c0r) * EMB + k0 + c0p * 8);
            cp_async16(buf + OFF_BH + so, Bh + (size_t)(n0 + c0r) * EMB + k0 + c0p * 8);
        }
        {
            uint32_t so = (uint32_t)(c1r * SKB + c1p * 16);
            cp_async16(buf + OFF_AH + so, Ah + (size_t)(m0 + c1r) * EMB + k0 + c1p * 8);
            cp_async16(buf + OFF_BH + so, Bh + (size_t)(n0 + c1r) * EMB + k0 + c1p * 8);
        }
        CP_COMMIT();
    };

    issue(0);
    issue(1);

    for (int s = 0; s < NSTAGE; s++) {
        if (s + 1 < NSTAGE) { CP_WAIT1(); } else { CP_WAIT0(); }
        __syncthreads();
        const uint32_t buf = sb + (uint32_t)(s & 1) * STAGE_B;

#pragma unroll
        for (int kc = 0; kc < BK; kc += 16) {
            uint32_t aH[4][4], bH[2][4];
#pragma unroll
            for (int mt = 0; mt < 4; mt++) {
                uint32_t off = aRow + (uint32_t)(mt * 16 * SKB + kc * 2);
                ldsm4(aH[mt], buf + OFF_AH + off);
            }
#pragma unroll
            for (int g = 0; g < 2; g++) {
                uint32_t off = bRow + (uint32_t)(g * 16 * SKB + kc * 2);
                ldsm4(bH[g], buf + OFF_BH + off);
            }
#pragma unroll
            for (int mt = 0; mt < 4; mt++)
#pragma unroll
                for (int nt = 0; nt < 4; nt++)
                    mma_f16(acc[mt][nt], aH[mt], bH[nt >> 1][(nt & 1) * 2], bH[nt >> 1][(nt & 1) * 2 + 1]);
        }

        __syncthreads();
        if (s + 2 < NSTAGE) issue(s + 2);
    }

    // epilogue: (acc + bias) * scale -> fp16 into [b,h,s,d]
    const int rbase = lane >> 2;
    const int cbase = (lane & 3) * 2;
#pragma unroll
    for (int mt = 0; mt < 4; mt++) {
#pragma unroll
        for (int half_ = 0; half_ < 2; half_++) {
            const int m = m0 + wm * 64 + mt * 16 + rbase + half_ * 8;
            const int b = m >> 11;
            const int sdx = m & (SEQ - 1);
#pragma unroll
            for (int nt = 0; nt < 4; nt++) {
                const int n = n0 + wn * 32 + nt * 8 + cbase;
                const int h = n >> 6;
                const int d = n & 63;
                float fx = (acc[mt][nt][half_ * 2 + 0] + bias[n + 0]) * scale;
                float fy = (acc[mt][nt][half_ * 2 + 1] + bias[n + 1]) * scale;
                size_t o = (((size_t)(b * NH + h)) * SEQ + sdx) * DH + d;
                *(uint32_t*)(DstH + o) = pack_h2(fx, fy);
            }
        }
    }
}

// ---------------- HMMA causal flash attention (fp16, 1-pass; R13 config) ----------------
#define ASTR   144
#define AQ_B   (128 * ASTR)                     // 18432
#define AKV_B  (64 * ASTR)                      // 9216
#define AOFF_KH 0
#define AOFF_VH (AKV_B)
#define AKV_STAGE (2 * AKV_B)                   // 18432
#define AKV_OFF (AQ_B)
#define ATTN_SMEM (AQ_B + 4 * AKV_STAGE)        // 92160

__global__ __launch_bounds__(256, 2) void attn_hmma(const __half* __restrict__ Qh,
                                                    const __half* __restrict__ Kh,
                                                    const __half* __restrict__ Vh,
                                                    float* __restrict__ out)
{
    extern __shared__ char smem[];
    const uint32_t sb = smem_u32(smem);
    const int t    = threadIdx.x;
    const int lane = t & 31;
    const int wid  = t >> 5;
    const int qb   = 15 - (int)blockIdx.x;   // longest-first
    const int bh   = blockIdx.y;
    const int q0   = qb * 128;

    const size_t base = (size_t)bh * SEQ * DH;
    const __half* qh = Qh + base;
    const __half* kh = Kh + base;
    const __half* vh = Vh + base;

    // Q tile -> smem (one commit group)
#pragma unroll
    for (int i = 0; i < 4; i++) {
        int id = t + i * 256;
        int row = id >> 3, part = id & 7;
        size_t g = (size_t)(q0 + row) * DH + part * 8;
        uint32_t so = (uint32_t)(row * ASTR + part * 16);
        cp_async16(sb + so, qh + g);
    }
    CP_COMMIT();

    auto issueKV = [&](int kb) {
        const uint32_t buf = sb + AKV_OFF + (uint32_t)(kb & 3) * AKV_STAGE;
        const int k0 = kb * 64;
#pragma unroll
        for (int i = 0; i < 2; i++) {
            int id = t + i * 256;
            int row = id >> 3, part = id & 7;
            size_t g = (size_t)(k0 + row) * DH + part * 8;
            uint32_t so = (uint32_t)(row * ASTR + part * 16);
            cp_async16(buf + AOFF_KH + so, kh + g);
            cp_async16(buf + AOFF_VH + so, vh + g);
        }
        CP_COMMIT();
    };

    const int nkb = 2 * qb + 2;
    issueKV(0);
    issueKV(1);
    if (nkb > 2) issueKV(2);

    // wait for Q + KV0 (nkb==2 has only 3 groups total)
    if (nkb > 2) { CP_WAIT2(); } else { CP_WAIT1(); }
    __syncthreads();
    uint32_t qhF[4][4];
    {
        const uint32_t aRow = (uint32_t)((wid * 16 + (lane & 15)) * ASTR + (lane >> 4) * 16);
#pragma unroll
        for (int kt = 0; kt < 4; kt++)
            ldsm4(qhF[kt], sb + aRow + kt * 32);
    }

    float m0r = -1e30f, m1r = -1e30f, l0r = 0.f, l1r = 0.f;
    float o[8][4] = {};

    const uint32_t kLane = (uint32_t)(((((lane >> 4) << 3) | (lane & 7)) * ASTR) + ((lane >> 3) & 1) * 16);
    const uint32_t vLane = (uint32_t)(((((lane >> 3) & 1) * 8 + (lane & 7)) * ASTR) + ((lane >> 4) & 1) * 16);

    for (int kb = 0; kb < nkb; kb++) {
        if (kb > 0) {
            const int pending = ((kb + 2 < nkb) ? kb + 2 : nkb - 1) - kb;
            if (pending >= 2)      { CP_WAIT2(); }
            else if (pending == 1) { CP_WAIT1(); }
            else                   { CP_WAIT0(); }
            __syncthreads();   // all warps done with tile kb-1
        }
        if (kb + 3 < nkb) issueKV(kb + 3);

        const uint32_t buf = sb + AKV_OFF + (uint32_t)(kb & 3) * AKV_STAGE;
        const int k0 = kb * 64;

        // ---- S = Qh Kh^T : 1 pass ----
        float s[8][4] = {};
#pragma unroll
        for (int kt = 0; kt < 4; kt++) {
            uint32_t kh4[4][4];
#pragma unroll
            for (int g = 0; g < 4; g++) {
                uint32_t off = kLane + (uint32_t)(g * 16 * ASTR + kt * 32);
                ldsm4(kh4[g], buf + AOFF_KH + off);
            }
#pragma unroll
            for (int g = 0; g < 4; g++)
#pragma unroll
                for (int hf = 0; hf < 2; hf++) {
                    int nt = g * 2 + hf;
                    mma_f16(s[nt], qhF[kt], kh4[g][hf * 2], kh4[g][hf * 2 + 1]);
                }
        }

        // ---- causal mask ----
        if (k0 + 63 > q0 + wid * 16) {
            const int r0 = q0 + wid * 16 + (lane >> 2);
            const int r1 = r0 + 8;
#pragma unroll
            for (int nt = 0; nt < 8; nt++) {
                const int c = k0 + nt * 8 + (lane & 3) * 2;
                if (c > r0)     s[nt][0] = -1e30f;
                if (c + 1 > r0) s[nt][1] = -1e30f;
                if (c > r1)     s[nt][2] = -1e30f;
                if (c + 1 > r1) s[nt][3] = -1e30f;
            }
        }

        // ---- online softmax (base-2) ----
        float mx0 = s[0][0], mx1 = s[0][2];
#pragma unroll
        for (int nt = 0; nt < 8; nt++) {
            mx0 = fmaxf(mx0, fmaxf(s[nt][0], s[nt][1]));
            mx1 = fmaxf(mx1, fmaxf(s[nt][2], s[nt][3]));
        }
        mx0 = fmaxf(mx0, __shfl_xor_sync(0xffffffff, mx0, 1));
        mx0 = fmaxf(mx0, __shfl_xor_sync(0xffffffff, mx0, 2));
        mx1 = fmaxf(mx1, __shfl_xor_sync(0xffffffff, mx1, 1));
        mx1 = fmaxf(mx1, __shfl_xor_sync(0xffffffff, mx1, 2));
        const float mn0 = fmaxf(m0r, mx0), mn1 = fmaxf(m1r, mx1);
        const float a0 = ex2(m0r - mn0), a1 = ex2(m1r - mn1);
        m0r = mn0; m1r = mn1;
        float sum0 = 0.f, sum1 = 0.f;
#pragma unroll
        for (int nt = 0; nt < 8; nt++) {
            s[nt][0] = ex2(s[nt][0] - mn0); sum0 += s[nt][0];
            s[nt][1] = ex2(s[nt][1] - mn0); sum0 += s[nt][1];
            s[nt][2] = ex2(s[nt][2] - mn1); sum1 += s[nt][2];
            s[nt][3] = ex2(s[nt][3] - mn1); sum1 += s[nt][3];
        }
        sum0 += __shfl_xor_sync(0xffffffff, sum0, 1);
        sum0 += __shfl_xor_sync(0xffffffff, sum0, 2);
        sum1 += __shfl_xor_sync(0xffffffff, sum1, 1);
        sum1 += __shfl_xor_sync(0xffffffff, sum1, 2);
        l0r = l0r * a0 + sum0;
        l1r = l1r * a1 + sum1;
#pragma unroll
        for (int n = 0; n < 8; n++) {
            o[n][0] *= a0; o[n][1] *= a0;
            o[n][2] *= a1; o[n][3] *= a1;
        }

        // ---- O += Ph Vh : 1 pass ----
#pragma unroll
        for (int kt = 0; kt < 4; kt++) {
            uint32_t ph[4];
            const int nt0 = kt * 2, nt1 = kt * 2 + 1;
            ph[0] = pack_h2(s[nt0][0], s[nt0][1]);
            ph[1] = pack_h2(s[nt0][2], s[nt0][3]);
            ph[2] = pack_h2(s[nt1][0], s[nt1][1]);
            ph[3] = pack_h2(s[nt1][2], s[nt1][3]);
#pragma unroll
            for (int g = 0; g < 4; g++) {
                uint32_t vh4[4];
                uint32_t off = vLane + (uint32_t)(kt * 16 * ASTR + g * 32);
                ldsm4t(vh4, buf + AOFF_VH + off);
#pragma unroll
                for (int hf = 0; hf < 2; hf++) {
                    int n = g * 2 + hf;
                    mma_f16(o[n], ph, vh4[hf * 2], vh4[hf * 2 + 1]);
                }
            }
        }
    }

    // ---- epilogue ----
    const int b  = bh >> 4;
    const int h  = bh & 15;
    const int r0 = q0 + wid * 16 + (lane >> 2);
    const int r1 = r0 + 8;
    const float i0 = 1.f / l0r, i1 = 1.f / l1r;
#pragma unroll
    for (int n = 0; n < 8; n++) {
        const int d = n * 8 + (lane & 3) * 2;
        *(float2*)(out + ((size_t)(b * SEQ + r0)) * NCOLS + h * DH + d) =
            make_float2(o[n][0] * i0, o[n][1] * i0);
        *(float2*)(out + ((size_t)(b * SEQ + r1)) * NCOLS + h * DH + d) =
            make_float2(o[n][2] * i1, o[n][3] * i1);
    }
}

// ---------------------------------------------------------------------------
extern "C" void kernel_launch(void* const* d_in, const int* in_sizes, int n_in,
                              void* d_out, int out_size)
{
    const float* x_q  = (const float*)d_in[0];
    const float* x_kv = (const float*)d_in[1];
    const float* w_q  = (const float*)d_in[3];
    const float* b_q  = (const float*)d_in[4];
    const float* w_k  = (const float*)d_in[5];
    const float* b_k  = (const float*)d_in[6];
    const float* w_v  = (const float*)d_in[7];
    const float* b_v  = (const float*)d_in[8];
    float* out = (float*)d_out;

    __half *xqh, *xkh, *wqh, *wkh, *wvh, *qhp, *khp, *vhp;
    cudaGetSymbolAddress((void**)&xqh, g_xq_h);
    cudaGetSymbolAddress((void**)&xkh, g_xkv_h);
    cudaGetSymbolAddress((void**)&wqh, g_wq_h);
    cudaGetSymbolAddress((void**)&wkh, g_wk_h);
    cudaGetSymbolAddress((void**)&wvh, g_wv_h);
    cudaGetSymbolAddress((void**)&qhp, g_qh);
    cudaGetSymbolAddress((void**)&khp, g_kh);
    cudaGetSymbolAddress((void**)&vhp, g_vh);

    cudaFuncSetAttribute(proj_hmma, cudaFuncAttributeMaxDynamicSharedMemorySize, PROJ_SMEM);
    cudaFuncSetAttribute(attn_hmma, cudaFuncAttributeMaxDynamicSharedMemorySize, ATTN_SMEM);

    const int nX4 = MROWS * EMB / 4;
    const int nW4 = NCOLS * EMB / 4;
    conv_h<<<(nX4 + 255) / 256, 256>>>(x_q,  xqh, nX4);
    conv_h<<<(nX4 + 255) / 256, 256>>>(x_kv, xkh, nX4);
    conv_h<<<(nW4 + 255) / 256, 256>>>(w_q,  wqh, nW4);
    conv_h<<<(nW4 + 255) / 256, 256>>>(w_k,  wkh, nW4);
    conv_h<<<(nW4 + 255) / 256, 256>>>(w_v,  wvh, nW4);

    dim3 pgrid(NCOLS / 128, MROWS / 128);   // (8, 64)
    // Q scale folds 1/sqrt(64) AND log2(e) for the base-2 softmax
    proj_hmma<<<pgrid, 256, PROJ_SMEM>>>(xqh, wqh, b_q, qhp, 0.125f * 1.44269504f);
    proj_hmma<<<pgrid, 256, PROJ_SMEM>>>(xkh, wkh, b_k, khp, 1.0f);
    proj_hmma<<<pgrid, 256, PROJ_SMEM>>>(xkh, wvh, b_v, vhp, 1.0f);

    dim3 agrid(SEQ / 128, BSZ * NH);        // (16, 64)
    attn_hmma<<<agrid, 256, ATTN_SMEM>>>(qhp, khp, vhp, out);
}

// round 15
// speedup vs baseline: 4.1662x; 1.0938x over previous
#include <cuda_runtime.h>
#include <cuda_fp16.h>
#include <cstdint>

#define EMB  1024
#define NH   16
#define DH   64
#define BSZ  4
#define SEQ  2048
#define MROWS (BSZ*SEQ)   // 8192
#define NCOLS (NH*DH)     // 1024

// ---------------- scratch (allocation-guard safe) ----------------
__device__ __half g_xq_h[(size_t)MROWS*EMB];
__device__ __half g_xkv_h[(size_t)MROWS*EMB];
__device__ __half g_wq_h[(size_t)NCOLS*EMB];
__device__ __half g_wk_h[(size_t)NCOLS*EMB];
__device__ __half g_wv_h[(size_t)NCOLS*EMB];

// projected Q/K/V (fp16), layout [b,h,s,d]
__device__ __half g_qh[(size_t)BSZ*NH*SEQ*DH];
__device__ __half g_kh[(size_t)BSZ*NH*SEQ*DH];
__device__ __half g_vh[(size_t)BSZ*NH*SEQ*DH];

// ---------------- helpers (base sm_103-safe ISA only) ----------------
__device__ __forceinline__ uint32_t smem_u32(const void* p) {
    uint32_t a;
    asm("{ .reg .u64 t; cvta.to.shared.u64 t, %1; cvt.u32.u64 %0, t; }" : "=r"(a) : "l"(p));
    return a;
}
__device__ __forceinline__ void ldsm4(uint32_t* r, uint32_t addr) {
    asm volatile("ldmatrix.sync.aligned.m8n8.x4.shared.b16 {%0,%1,%2,%3}, [%4];"
                 : "=r"(r[0]), "=r"(r[1]), "=r"(r[2]), "=r"(r[3]) : "r"(addr));
}
__device__ __forceinline__ void ldsm4t(uint32_t* r, uint32_t addr) {
    asm volatile("ldmatrix.sync.aligned.m8n8.x4.trans.shared.b16 {%0,%1,%2,%3}, [%4];"
                 : "=r"(r[0]), "=r"(r[1]), "=r"(r[2]), "=r"(r[3]) : "r"(addr));
}
__device__ __forceinline__ void mma_f16(float* c, const uint32_t* a, uint32_t b0, uint32_t b1) {
    asm volatile("mma.sync.aligned.m16n8k16.row.col.f32.f16.f16.f32 "
                 "{%0,%1,%2,%3}, {%4,%5,%6,%7}, {%8,%9}, {%0,%1,%2,%3};"
                 : "+f"(c[0]), "+f"(c[1]), "+f"(c[2]), "+f"(c[3])
                 : "r"(a[0]), "r"(a[1]), "r"(a[2]), "r"(a[3]), "r"(b0), "r"(b1));
}
__device__ __forceinline__ void cp_async16(uint32_t saddr, const void* gptr) {
    asm volatile("cp.async.cg.shared.global [%0], [%1], 16;" :: "r"(saddr), "l"(gptr) : "memory");
}
#define CP_COMMIT() asm volatile("cp.async.commit_group;" ::: "memory")
#define CP_WAIT2()  asm volatile("cp.async.wait_group 2;" ::: "memory")
#define CP_WAIT1()  asm volatile("cp.async.wait_group 1;" ::: "memory")
#define CP_WAIT0()  asm volatile("cp.async.wait_group 0;" ::: "memory")

__device__ __forceinline__ float ex2(float x) {
    float r;
    asm("ex2.approx.f32 %0, %1;" : "=f"(r) : "f"(x));
    return r;
}
__device__ __forceinline__ uint32_t pack_h2(float a, float b) {
    __half2 h = __floats2half2_rn(a, b);
    return *reinterpret_cast<uint32_t*>(&h);
}

// ---------------- fp32 -> fp16 (X inputs, 2 tensors via grid.y) ----------------
__global__ __launch_bounds__(256) void conv_x(const float* __restrict__ s0,
                                              const float* __restrict__ s1,
                                              __half* __restrict__ d0,
                                              __half* __restrict__ d1, int n4)
{
    int i = blockIdx.x * blockDim.x + threadIdx.x;
    if (i >= n4) return;
    const float* src = blockIdx.y ? s1 : s0;
    __half* dst      = blockIdx.y ? d1 : d0;
    float4 x = ((const float4*)src)[i];
    ((uint32_t*)dst)[i * 2 + 0] = pack_h2(x.x, x.y);
    ((uint32_t*)dst)[i * 2 + 1] = pack_h2(x.z, x.w);
}
// ---------------- fp32 -> fp16 (3 weight tensors via grid.y) ----------------
__global__ __launch_bounds__(256) void conv_w(const float* __restrict__ s0,
                                              const float* __restrict__ s1,
                                              const float* __restrict__ s2,
                                              __half* __restrict__ d0,
                                              __half* __restrict__ d1,
                                              __half* __restrict__ d2, int n4)
{
    int i = blockIdx.x * blockDim.x + threadIdx.x;
    if (i >= n4) return;
    const float* src = blockIdx.y == 0 ? s0 : (blockIdx.y == 1 ? s1 : s2);
    __half* dst      = blockIdx.y == 0 ? d0 : (blockIdx.y == 1 ? d1 : d2);
    float4 x = ((const float4*)src)[i];
    ((uint32_t*)dst)[i * 2 + 0] = pack_h2(x.x, x.y);
    ((uint32_t*)dst)[i * 2 + 1] = pack_h2(x.z, x.w);
}

// ---------------- fused HMMA projection GEMM (fp16, 1-pass, 3-stage) ----------------
// blockIdx.z selects {Q, K, V}. C = Xh * Wh^T, fp32 acc, 2 CTAs/SM.
#define BK      32
#define SKB     80
#define MAT_B   (128 * SKB)
#define OFF_AH  0
#define OFF_BH  (MAT_B)
#define STAGE_B (2 * MAT_B)           // 20480
#define PROJ_SMEM (3 * STAGE_B)       // 61440

__global__ __launch_bounds__(256, 2) void proj_hmma(const __half* __restrict__ Xq,
                                                    const __half* __restrict__ Xkv,
                                                    const __half* __restrict__ Wq,
                                                    const __half* __restrict__ Wk,
                                                    const __half* __restrict__ Wv,
                                                    const float* __restrict__ Bq,
                                                    const float* __restrict__ Bk,
                                                    const float* __restrict__ Bv,
                                                    __half* __restrict__ Dq,
                                                    __half* __restrict__ Dk,
                                                    __half* __restrict__ Dv)
{
    extern __shared__ char smem[];
    const uint32_t sb = smem_u32(smem);
    const int z    = blockIdx.z;
    const __half* Ah   = (z == 0) ? Xq : Xkv;
    const __half* Bh   = (z == 0) ? Wq : (z == 1 ? Wk : Wv);
    const float*  bias = (z == 0) ? Bq : (z == 1 ? Bk : Bv);
    __half*       DstH = (z == 0) ? Dq : (z == 1 ? Dk : Dv);
    const float scale  = (z == 0) ? 0.125f * 1.44269504f : 1.0f;

    const int t    = threadIdx.x;
    const int lane = t & 31;
    const int wid  = t >> 5;
    const int wm   = wid & 1;
    const int wn   = wid >> 1;
    const int n0   = blockIdx.x * 128;
    const int m0   = blockIdx.y * 128;

    const int c0r = t >> 2,         c0p = t & 3;
    const int c1r = (t + 256) >> 2, c1p = (t + 256) & 3;

    const uint32_t aRow = (uint32_t)((wm * 64 + (lane & 15)) * SKB + (lane >> 4) * 16);
    const uint32_t bRow = (uint32_t)((wn * 32 + (((lane >> 4) << 3) | (lane & 7))) * SKB
                                     + ((lane >> 3) & 1) * 16);

    float acc[4][4][4] = {};
    const int NSTAGE = EMB / BK;   // 32

    auto issue = [&](int s) {
        const int k0 = s * BK;
        const uint32_t buf = sb + (uint32_t)(s % 3) * STAGE_B;
        {
            uint32_t so = (uint32_t)(c0r * SKB + c0p * 16);
            cp_async16(buf + OFF_AH + so, Ah + (size_t)(m0 + c0r) * EMB + k0 + c0p * 8);
            cp_async16(buf + OFF_BH + so, Bh + (size_t)(n0 + c0r) * EMB + k0 + c0p * 8);
        }
        {
            uint32_t so = (uint32_t)(c1r * SKB + c1p * 16);
            cp_async16(buf + OFF_AH + so, Ah + (size_t)(m0 + c1r) * EMB + k0 + c1p * 8);
            cp_async16(buf + OFF_BH + so, Bh + (size_t)(n0 + c1r) * EMB + k0 + c1p * 8);
        }
        CP_COMMIT();
    };

    issue(0);
    issue(1);
    issue(2);

    for (int s = 0; s < NSTAGE; s++) {
        // pending groups after this wait must exclude stage s
        const int last = (s + 2 < NSTAGE) ? s + 2 : NSTAGE - 1;
        const int pending = last - s;
        if (pending >= 2)      { CP_WAIT2(); }
        else if (pending == 1) { CP_WAIT1(); }
        else                   { CP_WAIT0(); }
        __syncthreads();
        const uint32_t buf = sb + (uint32_t)(s % 3) * STAGE_B;

#pragma unroll
        for (int kc = 0; kc < BK; kc += 16) {
            uint32_t aH[4][4], bH[2][4];
#pragma unroll
            for (int mt = 0; mt < 4; mt++) {
                uint32_t off = aRow + (uint32_t)(mt * 16 * SKB + kc * 2);
                ldsm4(aH[mt], buf + OFF_AH + off);
            }
#pragma unroll
            for (int g = 0; g < 2; g++) {
                uint32_t off = bRow + (uint32_t)(g * 16 * SKB + kc * 2);
                ldsm4(bH[g], buf + OFF_BH + off);
            }
#pragma unroll
            for (int mt = 0; mt < 4; mt++)
#pragma unroll
                for (int nt = 0; nt < 4; nt++)
                    mma_f16(acc[mt][nt], aH[mt], bH[nt >> 1][(nt & 1) * 2], bH[nt >> 1][(nt & 1) * 2 + 1]);
        }

        __syncthreads();                 // all reads of buffer s%3 done
        if (s + 3 < NSTAGE) issue(s + 3); // overwrites buffer (s+3)%3 == s%3: safe
    }

    // epilogue: (acc + bias) * scale -> fp16 into [b,h,s,d]
    const int rbase = lane >> 2;
    const int cbase = (lane & 3) * 2;
#pragma unroll
    for (int mt = 0; mt < 4; mt++) {
#pragma unroll
        for (int half_ = 0; half_ < 2; half_++) {
            const int m = m0 + wm * 64 + mt * 16 + rbase + half_ * 8;
            const int b = m >> 11;
            const int sdx = m & (SEQ - 1);
#pragma unroll
            for (int nt = 0; nt < 4; nt++) {
                const int n = n0 + wn * 32 + nt * 8 + cbase;
                const int h = n >> 6;
                const int d = n & 63;
                float fx = (acc[mt][nt][half_ * 2 + 0] + bias[n + 0]) * scale;
                float fy = (acc[mt][nt][half_ * 2 + 1] + bias[n + 1]) * scale;
                size_t o = (((size_t)(b * NH + h)) * SEQ + sdx) * DH + d;
                *(uint32_t*)(DstH + o) = pack_h2(fx, fy);
            }
        }
    }
}

// ---------------- HMMA causal flash attention (fp16, 1-pass; R13 config) ----------------
#define ASTR   144
#define AQ_B   (128 * ASTR)                     // 18432
#define AKV_B  (64 * ASTR)                      // 9216
#define AOFF_KH 0
#define AOFF_VH (AKV_B)
#define AKV_STAGE (2 * AKV_B)                   // 18432
#define AKV_OFF (AQ_B)
#define ATTN_SMEM (AQ_B + 4 * AKV_STAGE)        // 92160

__global__ __launch_bounds__(256, 2) void attn_hmma(const __half* __restrict__ Qh,
                                                    const __half* __restrict__ Kh,
                                                    const __half* __restrict__ Vh,
                                                    float* __restrict__ out)
{
    extern __shared__ char smem[];
    const uint32_t sb = smem_u32(smem);
    const int t    = threadIdx.x;
    const int lane = t & 31;
    const int wid  = t >> 5;
    const int qb   = 15 - (int)blockIdx.x;   // longest-first
    const int bh   = blockIdx.y;
    const int q0   = qb * 128;

    const size_t base = (size_t)bh * SEQ * DH;
    const __half* qh = Qh + base;
    const __half* kh = Kh + base;
    const __half* vh = Vh + base;

#pragma unroll
    for (int i = 0; i < 4; i++) {
        int id = t + i * 256;
        int row = id >> 3, part = id & 7;
        size_t g = (size_t)(q0 + row) * DH + part * 8;
        uint32_t so = (uint32_t)(row * ASTR + part * 16);
        cp_async16(sb + so, qh + g);
    }
    CP_COMMIT();

    auto issueKV = [&](int kb) {
        const uint32_t buf = sb + AKV_OFF + (uint32_t)(kb & 3) * AKV_STAGE;
        const int k0 = kb * 64;
#pragma unroll
        for (int i = 0; i < 2; i++) {
            int id = t + i * 256;
            int row = id >> 3, part = id & 7;
            size_t g = (size_t)(k0 + row) * DH + part * 8;
            uint32_t so = (uint32_t)(row * ASTR + part * 16);
            cp_async16(buf + AOFF_KH + so, kh + g);
            cp_async16(buf + AOFF_VH + so, vh + g);
        }
        CP_COMMIT();
    };

    const int nkb = 2 * qb + 2;
    issueKV(0);
    issueKV(1);
    if (nkb > 2) issueKV(2);

    if (nkb > 2) { CP_WAIT2(); } else { CP_WAIT1(); }
    __syncthreads();
    uint32_t qhF[4][4];
    {
        const uint32_t aRow = (uint32_t)((wid * 16 + (lane & 15)) * ASTR + (lane >> 4) * 16);
#pragma unroll
        for (int kt = 0; kt < 4; kt++)
            ldsm4(qhF[kt], sb + aRow + kt * 32);
    }

    float m0r = -1e30f, m1r = -1e30f, l0r = 0.f, l1r = 0.f;
    float o[8][4] = {};

    const uint32_t kLane = (uint32_t)(((((lane >> 4) << 3) | (lane & 7)) * ASTR) + ((lane >> 3) & 1) * 16);
    const uint32_t vLane = (uint32_t)(((((lane >> 3) & 1) * 8 + (lane & 7)) * ASTR) + ((lane >> 4) & 1) * 16);

    for (int kb = 0; kb < nkb; kb++) {
        if (kb > 0) {
            const int pending = ((kb + 2 < nkb) ? kb + 2 : nkb - 1) - kb;
            if (pending >= 2)      { CP_WAIT2(); }
            else if (pending == 1) { CP_WAIT1(); }
            else                   { CP_WAIT0(); }
            __syncthreads();
        }
        if (kb + 3 < nkb) issueKV(kb + 3);

        const uint32_t buf = sb + AKV_OFF + (uint32_t)(kb & 3) * AKV_STAGE;
        const int k0 = kb * 64;

        float s[8][4] = {};
#pragma unroll
        for (int kt = 0; kt < 4; kt++) {
            uint32_t kh4[4][4];
#pragma unroll
            for (int g = 0; g < 4; g++) {
                uint32_t off = kLane + (uint32_t)(g * 16 * ASTR + kt * 32);
                ldsm4(kh4[g], buf + AOFF_KH + off);
            }
#pragma unroll
            for (int g = 0; g < 4; g++)
#pragma unroll
                for (int hf = 0; hf < 2; hf++) {
                    int nt = g * 2 + hf;
                    mma_f16(s[nt], qhF[kt], kh4[g][hf * 2], kh4[g][hf * 2 + 1]);
                }
        }

        if (k0 + 63 > q0 + wid * 16) {
            const int r0 = q0 + wid * 16 + (lane >> 2);
            const int r1 = r0 + 8;
#pragma unroll
            for (int nt = 0; nt < 8; nt++) {
                const int c = k0 + nt * 8 + (lane & 3) * 2;
                if (c > r0)     s[nt][0] = -1e30f;
                if (c + 1 > r0) s[nt][1] = -1e30f;
                if (c > r1)     s[nt][2] = -1e30f;
                if (c + 1 > r1) s[nt][3] = -1e30f;
            }
        }

        float mx0 = s[0][0], mx1 = s[0][2];
#pragma unroll
        for (int nt = 0; nt < 8; nt++) {
            mx0 = fmaxf(mx0, fmaxf(s[nt][0], s[nt][1]));
            mx1 = fmaxf(mx1, fmaxf(s[nt][2], s[nt][3]));
        }
        mx0 = fmaxf(mx0, __shfl_xor_sync(0xffffffff, mx0, 1));
        mx0 = fmaxf(mx0, __shfl_xor_sync(0xffffffff, mx0, 2));
        mx1 = fmaxf(mx1, __shfl_xor_sync(0xffffffff, mx1, 1));
        mx1 = fmaxf(mx1, __shfl_xor_sync(0xffffffff, mx1, 2));
        const float mn0 = fmaxf(m0r, mx0), mn1 = fmaxf(m1r, mx1);
        const float a0 = ex2(m0r - mn0), a1 = ex2(m1r - mn1);
        m0r = mn0; m1r = mn1;
        float sum0 = 0.f, sum1 = 0.f;
#pragma unroll
        for (int nt = 0; nt < 8; nt++) {
            s[nt][0] = ex2(s[nt][0] - mn0); sum0 += s[nt][0];
            s[nt][1] = ex2(s[nt][1] - mn0); sum0 += s[nt][1];
            s[nt][2] = ex2(s[nt][2] - mn1); sum1 += s[nt][2];
            s[nt][3] = ex2(s[nt][3] - mn1); sum1 += s[nt][3];
        }
        sum0 += __shfl_xor_sync(0xffffffff, sum0, 1);
        sum0 += __shfl_xor_sync(0xffffffff, sum0, 2);
        sum1 += __shfl_xor_sync(0xffffffff, sum1, 1);
        sum1 += __shfl_xor_sync(0xffffffff, sum1, 2);
        l0r = l0r * a0 + sum0;
        l1r = l1r * a1 + sum1;
#pragma unroll
        for (int n = 0; n < 8; n++) {
            o[n][0] *= a0; o[n][1] *= a0;
            o[n][2] *= a1; o[n][3] *= a1;
        }

#pragma unroll
        for (int kt = 0; kt < 4; kt++) {
            uint32_t ph[4];
            const int nt0 = kt * 2, nt1 = kt * 2 + 1;
            ph[0] = pack_h2(s[nt0][0], s[nt0][1]);
            ph[1] = pack_h2(s[nt0][2], s[nt0][3]);
            ph[2] = pack_h2(s[nt1][0], s[nt1][1]);
            ph[3] = pack_h2(s[nt1][2], s[nt1][3]);
#pragma unroll
            for (int g = 0; g < 4; g++) {
                uint32_t vh4[4];
                uint32_t off = vLane + (uint32_t)(kt * 16 * ASTR + g * 32);
                ldsm4t(vh4, buf + AOFF_VH + off);
#pragma unroll
                for (int hf = 0; hf < 2; hf++) {
                    int n = g * 2 + hf;
                    mma_f16(o[n], ph, vh4[hf * 2], vh4[hf * 2 + 1]);
                }
            }
        }
    }

    const int b  = bh >> 4;
    const int h  = bh & 15;
    const int r0 = q0 + wid * 16 + (lane >> 2);
    const int r1 = r0 + 8;
    const float i0 = 1.f / l0r, i1 = 1.f / l1r;
#pragma unroll
    for (int n = 0; n < 8; n++) {
        const int d = n * 8 + (lane & 3) * 2;
        *(float2*)(out + ((size_t)(b * SEQ + r0)) * NCOLS + h * DH + d) =
            make_float2(o[n][0] * i0, o[n][1] * i0);
        *(float2*)(out + ((size_t)(b * SEQ + r1)) * NCOLS + h * DH + d) =
            make_float2(o[n][2] * i1, o[n][3] * i1);
    }
}

// ---------------------------------------------------------------------------
extern "C" void kernel_launch(void* const* d_in, const int* in_sizes, int n_in,
                              void* d_out, int out_size)
{
    const float* x_q  = (const float*)d_in[0];
    const float* x_kv = (const float*)d_in[1];
    const float* w_q  = (const float*)d_in[3];
    const float* b_q  = (const float*)d_in[4];
    const float* w_k  = (const float*)d_in[5];
    const float* b_k  = (const float*)d_in[6];
    const float* w_v  = (const float*)d_in[7];
    const float* b_v  = (const float*)d_in[8];
    float* out = (float*)d_out;

    __half *xqh, *xkh, *wqh, *wkh, *wvh, *qhp, *khp, *vhp;
    cudaGetSymbolAddress((void**)&xqh, g_xq_h);
    cudaGetSymbolAddress((void**)&xkh, g_xkv_h);
    cudaGetSymbolAddress((void**)&wqh, g_wq_h);
    cudaGetSymbolAddress((void**)&wkh, g_wk_h);
    cudaGetSymbolAddress((void**)&wvh, g_wv_h);
    cudaGetSymbolAddress((void**)&qhp, g_qh);
    cudaGetSymbolAddress((void**)&khp, g_kh);
    cudaGetSymbolAddress((void**)&vhp, g_vh);

    cudaFuncSetAttribute(proj_hmma, cudaFuncAttributeMaxDynamicSharedMemorySize, PROJ_SMEM);
    cudaFuncSetAttribute(attn_hmma, cudaFuncAttributeMaxDynamicSharedMemorySize, ATTN_SMEM);

    const int nX4 = MROWS * EMB / 4;    // 2M
    const int nW4 = NCOLS * EMB / 4;    // 256K
    dim3 xg((nX4 + 255) / 256, 2);
    conv_x<<<xg, 256>>>(x_q, x_kv, xqh, xkh, nX4);
    dim3 wg((nW4 + 255) / 256, 3);
    conv_w<<<wg, 256>>>(w_q, w_k, w_v, wqh, wkh, wvh, nW4);

    dim3 pgrid(NCOLS / 128, MROWS / 128, 3);   // (8, 64, 3) fused Q/K/V
    proj_hmma<<<pgrid, 256, PROJ_SMEM>>>(xqh, xkh, wqh, wkh, wvh,
                                         b_q, b_k, b_v, qhp, khp, vhp);

    dim3 agrid(SEQ / 128, BSZ * NH);           // (16, 64)
    attn_hmma<<<agrid, 256, ATTN_SMEM>>>(qhp, khp, vhp, out);
}

// round 16
// speedup vs baseline: 4.3379x; 1.0412x over previous
#include <cuda_runtime.h>
#include <cuda_fp16.h>
#include <cstdint>

#define EMB  1024
#define NH   16
#define DH   64
#define BSZ  4
#define SEQ  2048
#define MROWS (BSZ*SEQ)   // 8192
#define NCOLS (NH*DH)     // 1024

// ---------------- scratch (allocation-guard safe) ----------------
__device__ __half g_xq_h[(size_t)MROWS*EMB];
__device__ __half g_xkv_h[(size_t)MROWS*EMB];
__device__ __half g_wq_h[(size_t)NCOLS*EMB];
__device__ __half g_wk_h[(size_t)NCOLS*EMB];
__device__ __half g_wv_h[(size_t)NCOLS*EMB];

// projected Q/K/V (fp16), layout [b,h,s,d]
__device__ __half g_qh[(size_t)BSZ*NH*SEQ*DH];
__device__ __half g_kh[(size_t)BSZ*NH*SEQ*DH];
__device__ __half g_vh[(size_t)BSZ*NH*SEQ*DH];

// ---------------- helpers (base sm_103-safe ISA only) ----------------
__device__ __forceinline__ uint32_t smem_u32(const void* p) {
    uint32_t a;
    asm("{ .reg .u64 t; cvta.to.shared.u64 t, %1; cvt.u32.u64 %0, t; }" : "=r"(a) : "l"(p));
    return a;
}
__device__ __forceinline__ void ldsm4(uint32_t* r, uint32_t addr) {
    asm volatile("ldmatrix.sync.aligned.m8n8.x4.shared.b16 {%0,%1,%2,%3}, [%4];"
                 : "=r"(r[0]), "=r"(r[1]), "=r"(r[2]), "=r"(r[3]) : "r"(addr));
}
__device__ __forceinline__ void ldsm4t(uint32_t* r, uint32_t addr) {
    asm volatile("ldmatrix.sync.aligned.m8n8.x4.trans.shared.b16 {%0,%1,%2,%3}, [%4];"
                 : "=r"(r[0]), "=r"(r[1]), "=r"(r[2]), "=r"(r[3]) : "r"(addr));
}
__device__ __forceinline__ void mma_f16(float* c, const uint32_t* a, uint32_t b0, uint32_t b1) {
    asm volatile("mma.sync.aligned.m16n8k16.row.col.f32.f16.f16.f32 "
                 "{%0,%1,%2,%3}, {%4,%5,%6,%7}, {%8,%9}, {%0,%1,%2,%3};"
                 : "+f"(c[0]), "+f"(c[1]), "+f"(c[2]), "+f"(c[3])
                 : "r"(a[0]), "r"(a[1]), "r"(a[2]), "r"(a[3]), "r"(b0), "r"(b1));
}
__device__ __forceinline__ void cp_async16(uint32_t saddr, const void* gptr) {
    asm volatile("cp.async.cg.shared.global [%0], [%1], 16;" :: "r"(saddr), "l"(gptr) : "memory");
}
#define CP_COMMIT() asm volatile("cp.async.commit_group;" ::: "memory")
#define CP_WAIT2()  asm volatile("cp.async.wait_group 2;" ::: "memory")
#define CP_WAIT1()  asm volatile("cp.async.wait_group 1;" ::: "memory")
#define CP_WAIT0()  asm volatile("cp.async.wait_group 0;" ::: "memory")

__device__ __forceinline__ float ex2(float x) {
    float r;
    asm("ex2.approx.f32 %0, %1;" : "=f"(r) : "f"(x));
    return r;
}
__device__ __forceinline__ uint32_t h2ex2(uint32_t x) {   // dual fp16 exp2
    uint32_t r;
    asm("ex2.approx.f16x2 %0, %1;" : "=r"(r) : "r"(x));
    return r;
}
__device__ __forceinline__ uint32_t pack_h2(float a, float b) {
    __half2 h = __floats2half2_rn(a, b);
    return *reinterpret_cast<uint32_t*>(&h);
}
#define ONES_H2 0x3C003C00u   // fp16 {1.0, 1.0}

// ---------------- fp32 -> fp16 converters ----------------
__global__ __launch_bounds__(256) void conv_x(const float* __restrict__ s0,
                                              const float* __restrict__ s1,
                                              __half* __restrict__ d0,
                                              __half* __restrict__ d1, int n4)
{
    int i = blockIdx.x * blockDim.x + threadIdx.x;
    if (i >= n4) return;
    const float* src = blockIdx.y ? s1 : s0;
    __half* dst      = blockIdx.y ? d1 : d0;
    float4 x = ((const float4*)src)[i];
    ((uint32_t*)dst)[i * 2 + 0] = pack_h2(x.x, x.y);
    ((uint32_t*)dst)[i * 2 + 1] = pack_h2(x.z, x.w);
}
__global__ __launch_bounds__(256) void conv_w(const float* __restrict__ s0,
                                              const float* __restrict__ s1,
                                              const float* __restrict__ s2,
                                              __half* __restrict__ d0,
                                              __half* __restrict__ d1,
                                              __half* __restrict__ d2, int n4)
{
    int i = blockIdx.x * blockDim.x + threadIdx.x;
    if (i >= n4) return;
    const float* src = blockIdx.y == 0 ? s0 : (blockIdx.y == 1 ? s1 : s2);
    __half* dst      = blockIdx.y == 0 ? d0 : (blockIdx.y == 1 ? d1 : d2);
    float4 x = ((const float4*)src)[i];
    ((uint32_t*)dst)[i * 2 + 0] = pack_h2(x.x, x.y);
    ((uint32_t*)dst)[i * 2 + 1] = pack_h2(x.z, x.w);
}

// ---------------- fused HMMA projection GEMM (R15 config) ----------------
#define BK      32
#define SKB     80
#define MAT_B   (128 * SKB)
#define OFF_AH  0
#define OFF_BH  (MAT_B)
#define STAGE_B (2 * MAT_B)           // 20480
#define PROJ_SMEM (3 * STAGE_B)       // 61440

__global__ __launch_bounds__(256, 2) void proj_hmma(const __half* __restrict__ Xq,
                                                    const __half* __restrict__ Xkv,
                                                    const __half* __restrict__ Wq,
                                                    const __half* __restrict__ Wk,
                                                    const __half* __restrict__ Wv,
                                                    const float* __restrict__ Bq,
                                                    const float* __restrict__ Bk,
                                                    const float* __restrict__ Bv,
                                                    __half* __restrict__ Dq,
                                                    __half* __restrict__ Dk,
                                                    __half* __restrict__ Dv)
{
    extern __shared__ char smem[];
    const uint32_t sb = smem_u32(smem);
    const int z    = blockIdx.z;
    const __half* Ah   = (z == 0) ? Xq : Xkv;
    const __half* Bh   = (z == 0) ? Wq : (z == 1 ? Wk : Wv);
    const float*  bias = (z == 0) ? Bq : (z == 1 ? Bk : Bv);
    __half*       DstH = (z == 0) ? Dq : (z == 1 ? Dk : Dv);
    const float scale  = (z == 0) ? 0.125f * 1.44269504f : 1.0f;

    const int t    = threadIdx.x;
    const int lane = t & 31;
    const int wid  = t >> 5;
    const int wm   = wid & 1;
    const int wn   = wid >> 1;
    const int n0   = blockIdx.x * 128;
    const int m0   = blockIdx.y * 128;

    const int c0r = t >> 2,         c0p = t & 3;
    const int c1r = (t + 256) >> 2, c1p = (t + 256) & 3;

    const uint32_t aRow = (uint32_t)((wm * 64 + (lane & 15)) * SKB + (lane >> 4) * 16);
    const uint32_t bRow = (uint32_t)((wn * 32 + (((lane >> 4) << 3) | (lane & 7))) * SKB
                                     + ((lane >> 3) & 1) * 16);

    float acc[4][4][4] = {};
    const int NSTAGE = EMB / BK;

    auto issue = [&](int s) {
        const int k0 = s * BK;
        const uint32_t buf = sb + (uint32_t)(s % 3) * STAGE_B;
        {
            uint32_t so = (uint32_t)(c0r * SKB + c0p * 16);
            cp_async16(buf + OFF_AH + so, Ah + (size_t)(m0 + c0r) * EMB + k0 + c0p * 8);
            cp_async16(buf + OFF_BH + so, Bh + (size_t)(n0 + c0r) * EMB + k0 + c0p * 8);
        }
        {
            uint32_t so = (uint32_t)(c1r * SKB + c1p * 16);
            cp_async16(buf + OFF_AH + so, Ah + (size_t)(m0 + c1r) * EMB + k0 + c1p * 8);
            cp_async16(buf + OFF_BH + so, Bh + (size_t)(n0 + c1r) * EMB + k0 + c1p * 8);
        }
        CP_COMMIT();
    };

    issue(0);
    issue(1);
    issue(2);

    for (int s = 0; s < NSTAGE; s++) {
        const int last = (s + 2 < NSTAGE) ? s + 2 : NSTAGE - 1;
        const int pending = last - s;
        if (pending >= 2)      { CP_WAIT2(); }
        else if (pending == 1) { CP_WAIT1(); }
        else                   { CP_WAIT0(); }
        __syncthreads();
        const uint32_t buf = sb + (uint32_t)(s % 3) * STAGE_B;

#pragma unroll
        for (int kc = 0; kc < BK; kc += 16) {
            uint32_t aH[4][4], bH[2][4];
#pragma unroll
            for (int mt = 0; mt < 4; mt++) {
                uint32_t off = aRow + (uint32_t)(mt * 16 * SKB + kc * 2);
                ldsm4(aH[mt], buf + OFF_AH + off);
            }
#pragma unroll
            for (int g = 0; g < 2; g++) {
                uint32_t off = bRow + (uint32_t)(g * 16 * SKB + kc * 2);
                ldsm4(bH[g], buf + OFF_BH + off);
            }
#pragma unroll
            for (int mt = 0; mt < 4; mt++)
#pragma unroll
                for (int nt = 0; nt < 4; nt++)
                    mma_f16(acc[mt][nt], aH[mt], bH[nt >> 1][(nt & 1) * 2], bH[nt >> 1][(nt & 1) * 2 + 1]);
        }

        __syncthreads();
        if (s + 3 < NSTAGE) issue(s + 3);
    }

    const int rbase = lane >> 2;
    const int cbase = (lane & 3) * 2;
#pragma unroll
    for (int mt = 0; mt < 4; mt++) {
#pragma unroll
        for (int half_ = 0; half_ < 2; half_++) {
            const int m = m0 + wm * 64 + mt * 16 + rbase + half_ * 8;
            const int b = m >> 11;
            const int sdx = m & (SEQ - 1);
#pragma unroll
            for (int nt = 0; nt < 4; nt++) {
                const int n = n0 + wn * 32 + nt * 8 + cbase;
                const int h = n >> 6;
                const int d = n & 63;
                float fx = (acc[mt][nt][half_ * 2 + 0] + bias[n + 0]) * scale;
                float fy = (acc[mt][nt][half_ * 2 + 1] + bias[n + 1]) * scale;
                size_t o = (((size_t)(b * NH + h)) * SEQ + sdx) * DH + d;
                *(uint32_t*)(DstH + o) = pack_h2(fx, fy);
            }
        }
    }
}

// ---------------- HMMA causal flash attention ----------------
// fp16 1-pass; row sums via ones-column MMA; P built with ex2.f16x2.
#define ASTR   144
#define AQ_B   (128 * ASTR)
#define AKV_B  (64 * ASTR)
#define AOFF_KH 0
#define AOFF_VH (AKV_B)
#define AKV_STAGE (2 * AKV_B)
#define AKV_OFF (AQ_B)
#define ATTN_SMEM (AQ_B + 4 * AKV_STAGE)        // 92160

__global__ __launch_bounds__(256, 2) void attn_hmma(const __half* __restrict__ Qh,
                                                    const __half* __restrict__ Kh,
                                                    const __half* __restrict__ Vh,
                                                    float* __restrict__ out)
{
    extern __shared__ char smem[];
    const uint32_t sb = smem_u32(smem);
    const int t    = threadIdx.x;
    const int lane = t & 31;
    const int wid  = t >> 5;
    const int qb   = 15 - (int)blockIdx.x;   // longest-first
    const int bh   = blockIdx.y;
    const int q0   = qb * 128;

    const size_t base = (size_t)bh * SEQ * DH;
    const __half* qh = Qh + base;
    const __half* kh = Kh + base;
    const __half* vh = Vh + base;

#pragma unroll
    for (int i = 0; i < 4; i++) {
        int id = t + i * 256;
        int row = id >> 3, part = id & 7;
        size_t g = (size_t)(q0 + row) * DH + part * 8;
        uint32_t so = (uint32_t)(row * ASTR + part * 16);
        cp_async16(sb + so, qh + g);
    }
    CP_COMMIT();

    auto issueKV = [&](int kb) {
        const uint32_t buf = sb + AKV_OFF + (uint32_t)(kb & 3) * AKV_STAGE;
        const int k0 = kb * 64;
#pragma unroll
        for (int i = 0; i < 2; i++) {
            int id = t + i * 256;
            int row = id >> 3, part = id & 7;
            size_t g = (size_t)(k0 + row) * DH + part * 8;
            uint32_t so = (uint32_t)(row * ASTR + part * 16);
            cp_async16(buf + AOFF_KH + so, kh + g);
            cp_async16(buf + AOFF_VH + so, vh + g);
        }
        CP_COMMIT();
    };

    const int nkb = 2 * qb + 2;
    issueKV(0);
    issueKV(1);
    if (nkb > 2) issueKV(2);

    if (nkb > 2) { CP_WAIT2(); } else { CP_WAIT1(); }
    __syncthreads();
    uint32_t qhF[4][4];
    {
        const uint32_t aRow = (uint32_t)((wid * 16 + (lane & 15)) * ASTR + (lane >> 4) * 16);
#pragma unroll
        for (int kt = 0; kt < 4; kt++)
            ldsm4(qhF[kt], sb + aRow + kt * 32);
    }

    float m0r = -1e30f, m1r = -1e30f;
    float o[8][4] = {};
    float ol[4] = {};   // row-sum accumulator (ones-column MMA); l0 = ol[0], l1 = ol[2]

    const uint32_t kLane = (uint32_t)(((((lane >> 4) << 3) | (lane & 7)) * ASTR) + ((lane >> 3) & 1) * 16);
    const uint32_t vLane = (uint32_t)(((((lane >> 3) & 1) * 8 + (lane & 7)) * ASTR) + ((lane >> 4) & 1) * 16);

    for (int kb = 0; kb < nkb; kb++) {
        if (kb > 0) {
            const int pending = ((kb + 2 < nkb) ? kb + 2 : nkb - 1) - kb;
            if (pending >= 2)      { CP_WAIT2(); }
            else if (pending == 1) { CP_WAIT1(); }
            else                   { CP_WAIT0(); }
            __syncthreads();
        }
        if (kb + 3 < nkb) issueKV(kb + 3);

        const uint32_t buf = sb + AKV_OFF + (uint32_t)(kb & 3) * AKV_STAGE;
        const int k0 = kb * 64;

        // ---- S = Qh Kh^T ----
        float s[8][4] = {};
#pragma unroll
        for (int kt = 0; kt < 4; kt++) {
            uint32_t kh4[4][4];
#pragma unroll
            for (int g = 0; g < 4; g++) {
                uint32_t off = kLane + (uint32_t)(g * 16 * ASTR + kt * 32);
                ldsm4(kh4[g], buf + AOFF_KH + off);
            }
#pragma unroll
            for (int g = 0; g < 4; g++)
#pragma unroll
                for (int hf = 0; hf < 2; hf++) {
                    int nt = g * 2 + hf;
                    mma_f16(s[nt], qhF[kt], kh4[g][hf * 2], kh4[g][hf * 2 + 1]);
                }
        }

        // ---- causal mask ----
        if (k0 + 63 > q0 + wid * 16) {
            const int r0 = q0 + wid * 16 + (lane >> 2);
            const int r1 = r0 + 8;
#pragma unroll
            for (int nt = 0; nt < 8; nt++) {
                const int c = k0 + nt * 8 + (lane & 3) * 2;
                if (c > r0)     s[nt][0] = -1e30f;
                if (c + 1 > r0) s[nt][1] = -1e30f;
                if (c > r1)     s[nt][2] = -1e30f;
                if (c + 1 > r1) s[nt][3] = -1e30f;
            }
        }

        // ---- max reduce (f32) ----
        float mx0 = s[0][0], mx1 = s[0][2];
#pragma unroll
        for (int nt = 0; nt < 8; nt++) {
            mx0 = fmaxf(mx0, fmaxf(s[nt][0], s[nt][1]));
            mx1 = fmaxf(mx1, fmaxf(s[nt][2], s[nt][3]));
        }
        mx0 = fmaxf(mx0, __shfl_xor_sync(0xffffffff, mx0, 1));
        mx0 = fmaxf(mx0, __shfl_xor_sync(0xffffffff, mx0, 2));
        mx1 = fmaxf(mx1, __shfl_xor_sync(0xffffffff, mx1, 1));
        mx1 = fmaxf(mx1, __shfl_xor_sync(0xffffffff, mx1, 2));
        const float mn0 = fmaxf(m0r, mx0), mn1 = fmaxf(m1r, mx1);
        const float a0 = ex2(m0r - mn0), a1 = ex2(m1r - mn1);
        m0r = mn0; m1r = mn1;

        // ---- P = 2^(s-m) built directly as fp16x2 fragments ----
        uint32_t pf[8][2];
#pragma unroll
        for (int nt = 0; nt < 8; nt++) {
            pf[nt][0] = h2ex2(pack_h2(s[nt][0] - mn0, s[nt][1] - mn0));
            pf[nt][1] = h2ex2(pack_h2(s[nt][2] - mn1, s[nt][3] - mn1));
        }

        // ---- rescale o and l by alpha ----
#pragma unroll
        for (int n = 0; n < 8; n++) {
            o[n][0] *= a0; o[n][1] *= a0;
            o[n][2] *= a1; o[n][3] *= a1;
        }
        ol[0] *= a0; ol[1] *= a0; ol[2] *= a1; ol[3] *= a1;

        // ---- O += P V ; l += P * ones ----
#pragma unroll
        for (int kt = 0; kt < 4; kt++) {
            uint32_t ph[4];
            ph[0] = pf[kt * 2][0];
            ph[1] = pf[kt * 2][1];
            ph[2] = pf[kt * 2 + 1][0];
            ph[3] = pf[kt * 2 + 1][1];
            mma_f16(ol, ph, ONES_H2, ONES_H2);   // row sums on the tensor pipe
#pragma unroll
            for (int g = 0; g < 4; g++) {
                uint32_t vh4[4];
                uint32_t off = vLane + (uint32_t)(kt * 16 * ASTR + g * 32);
                ldsm4t(vh4, buf + AOFF_VH + off);
#pragma unroll
                for (int hf = 0; hf < 2; hf++) {
                    int n = g * 2 + hf;
                    mma_f16(o[n], ph, vh4[hf * 2], vh4[hf * 2 + 1]);
                }
            }
        }
    }

    // ---- epilogue ----
    const int b  = bh >> 4;
    const int h  = bh & 15;
    const int r0 = q0 + wid * 16 + (lane >> 2);
    const int r1 = r0 + 8;
    const float i0 = 1.f / ol[0], i1 = 1.f / ol[2];
#pragma unroll
    for (int n = 0; n < 8; n++) {
        const int d = n * 8 + (lane & 3) * 2;
        *(float2*)(out + ((size_t)(b * SEQ + r0)) * NCOLS + h * DH + d) =
            make_float2(o[n][0] * i0, o[n][1] * i0);
        *(float2*)(out + ((size_t)(b * SEQ + r1)) * NCOLS + h * DH + d) =
            make_float2(o[n][2] * i1, o[n][3] * i1);
    }
}

// ---------------------------------------------------------------------------
extern "C" void kernel_launch(void* const* d_in, const int* in_sizes, int n_in,
                              void* d_out, int out_size)
{
    const float* x_q  = (const float*)d_in[0];
    const float* x_kv = (const float*)d_in[1];
    const float* w_q  = (const float*)d_in[3];
    const float* b_q  = (const float*)d_in[4];
    const float* w_k  = (const float*)d_in[5];
    const float* b_k  = (const float*)d_in[6];
    const float* w_v  = (const float*)d_in[7];
    const float* b_v  = (const float*)d_in[8];
    float* out = (float*)d_out;

    __half *xqh, *xkh, *wqh, *wkh, *wvh, *qhp, *khp, *vhp;
    cudaGetSymbolAddress((void**)&xqh, g_xq_h);
    cudaGetSymbolAddress((void**)&xkh, g_xkv_h);
    cudaGetSymbolAddress((void**)&wqh, g_wq_h);
    cudaGetSymbolAddress((void**)&wkh, g_wk_h);
    cudaGetSymbolAddress((void**)&wvh, g_wv_h);
    cudaGetSymbolAddress((void**)&qhp, g_qh);
    cudaGetSymbolAddress((void**)&khp, g_kh);
    cudaGetSymbolAddress((void**)&vhp, g_vh);

    cudaFuncSetAttribute(proj_hmma, cudaFuncAttributeMaxDynamicSharedMemorySize, PROJ_SMEM);
    cudaFuncSetAttribute(attn_hmma, cudaFuncAttributeMaxDynamicSharedMemorySize, ATTN_SMEM);

    const int nX4 = MROWS * EMB / 4;
    const int nW4 = NCOLS * EMB / 4;
    dim3 xg((nX4 + 255) / 256, 2);
    conv_x<<<xg, 256>>>(x_q, x_kv, xqh, xkh, nX4);
    dim3 wg((nW4 + 255) / 256, 3);
    conv_w<<<wg, 256>>>(w_q, w_k, w_v, wqh, wkh, wvh, nW4);

    dim3 pgrid(NCOLS / 128, MROWS / 128, 3);   // fused Q/K/V
    proj_hmma<<<pgrid, 256, PROJ_SMEM>>>(xqh, xkh, wqh, wkh, wvh,
                                         b_q, b_k, b_v, qhp, khp, vhp);

    dim3 agrid(SEQ / 128, BSZ * NH);
    attn_hmma<<<agrid, 256, ATTN_SMEM>>>(qhp, khp, vhp, out);
}

// round 17
// speedup vs baseline: 4.4143x; 1.0176x over previous
#include <cuda_runtime.h>
#include <cuda_fp16.h>
#include <cstdint>

#define EMB  1024
#define NH   16
#define DH   64
#define BSZ  4
#define SEQ  2048
#define MROWS (BSZ*SEQ)   // 8192
#define NCOLS (NH*DH)     // 1024

// ---------------- scratch (allocation-guard safe) ----------------
__device__ __half g_xq_h[(size_t)MROWS*EMB];
__device__ __half g_xkv_h[(size_t)MROWS*EMB];
__device__ __half g_wq_h[(size_t)NCOLS*EMB];
__device__ __half g_wk_h[(size_t)NCOLS*EMB];
__device__ __half g_wv_h[(size_t)NCOLS*EMB];

// projected Q/K/V (fp16), layout [b,h,s,d]
__device__ __half g_qh[(size_t)BSZ*NH*SEQ*DH];
__device__ __half g_kh[(size_t)BSZ*NH*SEQ*DH];
__device__ __half g_vh[(size_t)BSZ*NH*SEQ*DH];

// ---------------- helpers (base sm_103-safe ISA only) ----------------
__device__ __forceinline__ uint32_t smem_u32(const void* p) {
    uint32_t a;
    asm("{ .reg .u64 t; cvta.to.shared.u64 t, %1; cvt.u32.u64 %0, t; }" : "=r"(a) : "l"(p));
    return a;
}
__device__ __forceinline__ void ldsm4(uint32_t* r, uint32_t addr) {
    asm volatile("ldmatrix.sync.aligned.m8n8.x4.shared.b16 {%0,%1,%2,%3}, [%4];"
                 : "=r"(r[0]), "=r"(r[1]), "=r"(r[2]), "=r"(r[3]) : "r"(addr));
}
__device__ __forceinline__ void ldsm4t(uint32_t* r, uint32_t addr) {
    asm volatile("ldmatrix.sync.aligned.m8n8.x4.trans.shared.b16 {%0,%1,%2,%3}, [%4];"
                 : "=r"(r[0]), "=r"(r[1]), "=r"(r[2]), "=r"(r[3]) : "r"(addr));
}
__device__ __forceinline__ void mma_f16(float* c, const uint32_t* a, uint32_t b0, uint32_t b1) {
    asm volatile("mma.sync.aligned.m16n8k16.row.col.f32.f16.f16.f32 "
                 "{%0,%1,%2,%3}, {%4,%5,%6,%7}, {%8,%9}, {%0,%1,%2,%3};"
                 : "+f"(c[0]), "+f"(c[1]), "+f"(c[2]), "+f"(c[3])
                 : "r"(a[0]), "r"(a[1]), "r"(a[2]), "r"(a[3]), "r"(b0), "r"(b1));
}
__device__ __forceinline__ void cp_async16(uint32_t saddr, const void* gptr) {
    asm volatile("cp.async.cg.shared.global [%0], [%1], 16;" :: "r"(saddr), "l"(gptr) : "memory");
}
#define CP_COMMIT() asm volatile("cp.async.commit_group;" ::: "memory")
#define CP_WAIT2()  asm volatile("cp.async.wait_group 2;" ::: "memory")
#define CP_WAIT1()  asm volatile("cp.async.wait_group 1;" ::: "memory")
#define CP_WAIT0()  asm volatile("cp.async.wait_group 0;" ::: "memory")

__device__ __forceinline__ float ex2(float x) {
    float r;
    asm("ex2.approx.f32 %0, %1;" : "=f"(r) : "f"(x));
    return r;
}
__device__ __forceinline__ uint32_t h2ex2(uint32_t x) {   // dual fp16 exp2
    uint32_t r;
    asm("ex2.approx.f16x2 %0, %1;" : "=r"(r) : "r"(x));
    return r;
}
__device__ __forceinline__ uint32_t pack_h2(float a, float b) {
    __half2 h = __floats2half2_rn(a, b);
    return *reinterpret_cast<uint32_t*>(&h);
}
#define ONES_H2 0x3C003C00u   // fp16 {1.0, 1.0}

// ---------------- fp32 -> fp16 converters ----------------
__global__ __launch_bounds__(256) void conv_x(const float* __restrict__ s0,
                                              const float* __restrict__ s1,
                                              __half* __restrict__ d0,
                                              __half* __restrict__ d1, int n4)
{
    int i = blockIdx.x * blockDim.x + threadIdx.x;
    if (i >= n4) return;
    const float* src = blockIdx.y ? s1 : s0;
    __half* dst      = blockIdx.y ? d1 : d0;
    float4 x = ((const float4*)src)[i];
    ((uint32_t*)dst)[i * 2 + 0] = pack_h2(x.x, x.y);
    ((uint32_t*)dst)[i * 2 + 1] = pack_h2(x.z, x.w);
}
__global__ __launch_bounds__(256) void conv_w(const float* __restrict__ s0,
                                              const float* __restrict__ s1,
                                              const float* __restrict__ s2,
                                              __half* __restrict__ d0,
                                              __half* __restrict__ d1,
                                              __half* __restrict__ d2, int n4)
{
    int i = blockIdx.x * blockDim.x + threadIdx.x;
    if (i >= n4) return;
    const float* src = blockIdx.y == 0 ? s0 : (blockIdx.y == 1 ? s1 : s2);
    __half* dst      = blockIdx.y == 0 ? d0 : (blockIdx.y == 1 ? d1 : d2);
    float4 x = ((const float4*)src)[i];
    ((uint32_t*)dst)[i * 2 + 0] = pack_h2(x.x, x.y);
    ((uint32_t*)dst)[i * 2 + 1] = pack_h2(x.z, x.w);
}

// ---------------- fused HMMA projection GEMM ----------------
// fp16 1-pass, 4-buffer cp.async ring, ONE barrier per K-stage.
#define BK      32
#define SKB     80
#define MAT_B   (128 * SKB)
#define OFF_AH  0
#define OFF_BH  (MAT_B)
#define STAGE_B (2 * MAT_B)           // 20480
#define PROJ_SMEM (4 * STAGE_B)       // 81920; x2 CTAs = 163840 < 228K

__global__ __launch_bounds__(256, 2) void proj_hmma(const __half* __restrict__ Xq,
                                                    const __half* __restrict__ Xkv,
                                                    const __half* __restrict__ Wq,
                                                    const __half* __restrict__ Wk,
                                                    const __half* __restrict__ Wv,
                                                    const float* __restrict__ Bq,
                                                    const float* __restrict__ Bk,
                                                    const float* __restrict__ Bv,
                                                    __half* __restrict__ Dq,
                                                    __half* __restrict__ Dk,
                                                    __half* __restrict__ Dv)
{
    extern __shared__ char smem[];
    const uint32_t sb = smem_u32(smem);
    const int z    = blockIdx.z;
    const __half* Ah   = (z == 0) ? Xq : Xkv;
    const __half* Bh   = (z == 0) ? Wq : (z == 1 ? Wk : Wv);
    const float*  bias = (z == 0) ? Bq : (z == 1 ? Bk : Bv);
    __half*       DstH = (z == 0) ? Dq : (z == 1 ? Dk : Dv);
    const float scale  = (z == 0) ? 0.125f * 1.44269504f : 1.0f;

    const int t    = threadIdx.x;
    const int lane = t & 31;
    const int wid  = t >> 5;
    const int wm   = wid & 1;
    const int wn   = wid >> 1;
    const int n0   = blockIdx.x * 128;
    const int m0   = blockIdx.y * 128;

    const int c0r = t >> 2,         c0p = t & 3;
    const int c1r = (t + 256) >> 2, c1p = (t + 256) & 3;

    const uint32_t aRow = (uint32_t)((wm * 64 + (lane & 15)) * SKB + (lane >> 4) * 16);
    const uint32_t bRow = (uint32_t)((wn * 32 + (((lane >> 4) << 3) | (lane & 7))) * SKB
                                     + ((lane >> 3) & 1) * 16);

    float acc[4][4][4] = {};
    const int NSTAGE = EMB / BK;   // 32

    auto issue = [&](int s) {
        const int k0 = s * BK;
        const uint32_t buf = sb + (uint32_t)(s & 3) * STAGE_B;
        {
            uint32_t so = (uint32_t)(c0r * SKB + c0p * 16);
            cp_async16(buf + OFF_AH + so, Ah + (size_t)(m0 + c0r) * EMB + k0 + c0p * 8);
            cp_async16(buf + OFF_BH + so, Bh + (size_t)(n0 + c0r) * EMB + k0 + c0p * 8);
        }
        {
            uint32_t so = (uint32_t)(c1r * SKB + c1p * 16);
            cp_async16(buf + OFF_AH + so, Ah + (size_t)(m0 + c1r) * EMB + k0 + c1p * 8);
            cp_async16(buf + OFF_BH + so, Bh + (size_t)(n0 + c1r) * EMB + k0 + c1p * 8);
        }
        CP_COMMIT();
    };

    issue(0);
    issue(1);
    issue(2);

    for (int s = 0; s < NSTAGE; s++) {
        // groups issued so far reach index min(s+2, NSTAGE-1)
        const int last = (s + 2 < NSTAGE) ? s + 2 : NSTAGE - 1;
        const int pending = last - s;
        if (pending >= 2)      { CP_WAIT2(); }
        else if (pending == 1) { CP_WAIT1(); }
        else                   { CP_WAIT0(); }
        __syncthreads();   // stage s visible; all warps finished stage s-1
        // buffer (s+3)&3 == (s-1)&3, drained by the barrier above
        if (s + 3 < NSTAGE) issue(s + 3);

        const uint32_t buf = sb + (uint32_t)(s & 3) * STAGE_B;
#pragma unroll
        for (int kc = 0; kc < BK; kc += 16) {
            uint32_t aH[4][4], bH[2][4];
#pragma unroll
            for (int mt = 0; mt < 4; mt++) {
                uint32_t off = aRow + (uint32_t)(mt * 16 * SKB + kc * 2);
                ldsm4(aH[mt], buf + OFF_AH + off);
            }
#pragma unroll
            for (int g = 0; g < 2; g++) {
                uint32_t off = bRow + (uint32_t)(g * 16 * SKB + kc * 2);
                ldsm4(bH[g], buf + OFF_BH + off);
            }
#pragma unroll
            for (int mt = 0; mt < 4; mt++)
#pragma unroll
                for (int nt = 0; nt < 4; nt++)
                    mma_f16(acc[mt][nt], aH[mt], bH[nt >> 1][(nt & 1) * 2], bH[nt >> 1][(nt & 1) * 2 + 1]);
        }
        // no bottom barrier: 4-buffer ring + top barrier covers reuse
    }

    const int rbase = lane >> 2;
    const int cbase = (lane & 3) * 2;
#pragma unroll
    for (int mt = 0; mt < 4; mt++) {
#pragma unroll
        for (int half_ = 0; half_ < 2; half_++) {
            const int m = m0 + wm * 64 + mt * 16 + rbase + half_ * 8;
            const int b = m >> 11;
            const int sdx = m & (SEQ - 1);
#pragma unroll
            for (int nt = 0; nt < 4; nt++) {
                const int n = n0 + wn * 32 + nt * 8 + cbase;
                const int h = n >> 6;
                const int d = n & 63;
                float fx = (acc[mt][nt][half_ * 2 + 0] + bias[n + 0]) * scale;
                float fy = (acc[mt][nt][half_ * 2 + 1] + bias[n + 1]) * scale;
                size_t o = (((size_t)(b * NH + h)) * SEQ + sdx) * DH + d;
                *(uint32_t*)(DstH + o) = pack_h2(fx, fy);
            }
        }
    }
}

// ---------------- HMMA causal flash attention (R16 config, unchanged) ----------------
#define ASTR   144
#define AQ_B   (128 * ASTR)
#define AKV_B  (64 * ASTR)
#define AOFF_KH 0
#define AOFF_VH (AKV_B)
#define AKV_STAGE (2 * AKV_B)
#define AKV_OFF (AQ_B)
#define ATTN_SMEM (AQ_B + 4 * AKV_STAGE)        // 92160

__global__ __launch_bounds__(256, 2) void attn_hmma(const __half* __restrict__ Qh,
                                                    const __half* __restrict__ Kh,
                                                    const __half* __restrict__ Vh,
                                                    float* __restrict__ out)
{
    extern __shared__ char smem[];
    const uint32_t sb = smem_u32(smem);
    const int t    = threadIdx.x;
    const int lane = t & 31;
    const int wid  = t >> 5;
    const int qb   = 15 - (int)blockIdx.x;   // longest-first
    const int bh   = blockIdx.y;
    const int q0   = qb * 128;

    const size_t base = (size_t)bh * SEQ * DH;
    const __half* qh = Qh + base;
    const __half* kh = Kh + base;
    const __half* vh = Vh + base;

#pragma unroll
    for (int i = 0; i < 4; i++) {
        int id = t + i * 256;
        int row = id >> 3, part = id & 7;
        size_t g = (size_t)(q0 + row) * DH + part * 8;
        uint32_t so = (uint32_t)(row * ASTR + part * 16);
        cp_async16(sb + so, qh + g);
    }
    CP_COMMIT();

    auto issueKV = [&](int kb) {
        const uint32_t buf = sb + AKV_OFF + (uint32_t)(kb & 3) * AKV_STAGE;
        const int k0 = kb * 64;
#pragma unroll
        for (int i = 0; i < 2; i++) {
            int id = t + i * 256;
            int row = id >> 3, part = id & 7;
            size_t g = (size_t)(k0 + row) * DH + part * 8;
            uint32_t so = (uint32_t)(row * ASTR + part * 16);
            cp_async16(buf + AOFF_KH + so, kh + g);
            cp_async16(buf + AOFF_VH + so, vh + g);
        }
        CP_COMMIT();
    };

    const int nkb = 2 * qb + 2;
    issueKV(0);
    issueKV(1);
    if (nkb > 2) issueKV(2);

    if (nkb > 2) { CP_WAIT2(); } else { CP_WAIT1(); }
    __syncthreads();
    uint32_t qhF[4][4];
    {
        const uint32_t aRow = (uint32_t)((wid * 16 + (lane & 15)) * ASTR + (lane >> 4) * 16);
#pragma unroll
        for (int kt = 0; kt < 4; kt++)
            ldsm4(qhF[kt], sb + aRow + kt * 32);
    }

    float m0r = -1e30f, m1r = -1e30f;
    float o[8][4] = {};
    float ol[4] = {};

    const uint32_t kLane = (uint32_t)(((((lane >> 4) << 3) | (lane & 7)) * ASTR) + ((lane >> 3) & 1) * 16);
    const uint32_t vLane = (uint32_t)(((((lane >> 3) & 1) * 8 + (lane & 7)) * ASTR) + ((lane >> 4) & 1) * 16);

    for (int kb = 0; kb < nkb; kb++) {
        if (kb > 0) {
            const int pending = ((kb + 2 < nkb) ? kb + 2 : nkb - 1) - kb;
            if (pending >= 2)      { CP_WAIT2(); }
            else if (pending == 1) { CP_WAIT1(); }
            else                   { CP_WAIT0(); }
            __syncthreads();
        }
        if (kb + 3 < nkb) issueKV(kb + 3);

        const uint32_t buf = sb + AKV_OFF + (uint32_t)(kb & 3) * AKV_STAGE;
        const int k0 = kb * 64;

        float s[8][4] = {};
#pragma unroll
        for (int kt = 0; kt < 4; kt++) {
            uint32_t kh4[4][4];
#pragma unroll
            for (int g = 0; g < 4; g++) {
                uint32_t off = kLane + (uint32_t)(g * 16 * ASTR + kt * 32);
                ldsm4(kh4[g], buf + AOFF_KH + off);
            }
#pragma unroll
            for (int g = 0; g < 4; g++)
#pragma unroll
                for (int hf = 0; hf < 2; hf++) {
                    int nt = g * 2 + hf;
                    mma_f16(s[nt], qhF[kt], kh4[g][hf * 2], kh4[g][hf * 2 + 1]);
                }
        }

        if (k0 + 63 > q0 + wid * 16) {
            const int r0 = q0 + wid * 16 + (lane >> 2);
            const int r1 = r0 + 8;
#pragma unroll
            for (int nt = 0; nt < 8; nt++) {
                const int c = k0 + nt * 8 + (lane & 3) * 2;
                if (c > r0)     s[nt][0] = -1e30f;
                if (c + 1 > r0) s[nt][1] = -1e30f;
                if (c > r1)     s[nt][2] = -1e30f;
                if (c + 1 > r1) s[nt][3] = -1e30f;
            }
        }

        float mx0 = s[0][0], mx1 = s[0][2];
#pragma unroll
        for (int nt = 0; nt < 8; nt++) {
            mx0 = fmaxf(mx0, fmaxf(s[nt][0], s[nt][1]));
            mx1 = fmaxf(mx1, fmaxf(s[nt][2], s[nt][3]));
        }
        mx0 = fmaxf(mx0, __shfl_xor_sync(0xffffffff, mx0, 1));
        mx0 = fmaxf(mx0, __shfl_xor_sync(0xffffffff, mx0, 2));
        mx1 = fmaxf(mx1, __shfl_xor_sync(0xffffffff, mx1, 1));
        mx1 = fmaxf(mx1, __shfl_xor_sync(0xffffffff, mx1, 2));
        const float mn0 = fmaxf(m0r, mx0), mn1 = fmaxf(m1r, mx1);
        const float a0 = ex2(m0r - mn0), a1 = ex2(m1r - mn1);
        m0r = mn0; m1r = mn1;

        uint32_t pf[8][2];
#pragma unroll
        for (int nt = 0; nt < 8; nt++) {
            pf[nt][0] = h2ex2(pack_h2(s[nt][0] - mn0, s[nt][1] - mn0));
            pf[nt][1] = h2ex2(pack_h2(s[nt][2] - mn1, s[nt][3] - mn1));
        }

#pragma unroll
        for (int n = 0; n < 8; n++) {
            o[n][0] *= a0; o[n][1] *= a0;
            o[n][2] *= a1; o[n][3] *= a1;
        }
        ol[0] *= a0; ol[1] *= a0; ol[2] *= a1; ol[3] *= a1;

#pragma unroll
        for (int kt = 0; kt < 4; kt++) {
            uint32_t ph[4];
            ph[0] = pf[kt * 2][0];
            ph[1] = pf[kt * 2][1];
            ph[2] = pf[kt * 2 + 1][0];
            ph[3] = pf[kt * 2 + 1][1];
            mma_f16(ol, ph, ONES_H2, ONES_H2);
#pragma unroll
            for (int g = 0; g < 4; g++) {
                uint32_t vh4[4];
                uint32_t off = vLane + (uint32_t)(kt * 16 * ASTR + g * 32);
                ldsm4t(vh4, buf + AOFF_VH + off);
#pragma unroll
                for (int hf = 0; hf < 2; hf++) {
                    int n = g * 2 + hf;
                    mma_f16(o[n], ph, vh4[hf * 2], vh4[hf * 2 + 1]);
                }
            }
        }
    }

    const int b  = bh >> 4;
    const int h  = bh & 15;
    const int r0 = q0 + wid * 16 + (lane >> 2);
    const int r1 = r0 + 8;
    const float i0 = 1.f / ol[0], i1 = 1.f / ol[2];
#pragma unroll
    for (int n = 0; n < 8; n++) {
        const int d = n * 8 + (lane & 3) * 2;
        *(float2*)(out + ((size_t)(b * SEQ + r0)) * NCOLS + h * DH + d) =
            make_float2(o[n][0] * i0, o[n][1] * i0);
        *(float2*)(out + ((size_t)(b * SEQ + r1)) * NCOLS + h * DH + d) =
            make_float2(o[n][2] * i1, o[n][3] * i1);
    }
}

// ---------------------------------------------------------------------------
extern "C" void kernel_launch(void* const* d_in, const int* in_sizes, int n_in,
                              void* d_out, int out_size)
{
    const float* x_q  = (const float*)d_in[0];
    const float* x_kv = (const float*)d_in[1];
    const float* w_q  = (const float*)d_in[3];
    const float* b_q  = (const float*)d_in[4];
    const float* w_k  = (const float*)d_in[5];
    const float* b_k  = (const float*)d_in[6];
    const float* w_v  = (const float*)d_in[7];
    const float* b_v  = (const float*)d_in[8];
    float* out = (float*)d_out;

    __half *xqh, *xkh, *wqh, *wkh, *wvh, *qhp, *khp, *vhp;
    cudaGetSymbolAddress((void**)&xqh, g_xq_h);
    cudaGetSymbolAddress((void**)&xkh, g_xkv_h);
    cudaGetSymbolAddress((void**)&wqh, g_wq_h);
    cudaGetSymbolAddress((void**)&wkh, g_wk_h);
    cudaGetSymbolAddress((void**)&wvh, g_wv_h);
    cudaGetSymbolAddress((void**)&qhp, g_qh);
    cudaGetSymbolAddress((void**)&khp, g_kh);
    cudaGetSymbolAddress((void**)&vhp, g_vh);

    cudaFuncSetAttribute(proj_hmma, cudaFuncAttributeMaxDynamicSharedMemorySize, PROJ_SMEM);
    cudaFuncSetAttribute(attn_hmma, cudaFuncAttributeMaxDynamicSharedMemorySize, ATTN_SMEM);

    const int nX4 = MROWS * EMB / 4;
    const int nW4 = NCOLS * EMB / 4;
    dim3 xg((nX4 + 255) / 256, 2);
    conv_x<<<xg, 256>>>(x_q, x_kv, xqh, xkh, nX4);
    dim3 wg((nW4 + 255) / 256, 3);
    conv_w<<<wg, 256>>>(w_q, w_k, w_v, wqh, wkh, wvh, nW4);

    dim3 pgrid(NCOLS / 128, MROWS / 128, 3);   // fused Q/K/V
    proj_hmma<<<pgrid, 256, PROJ_SMEM>>>(xqh, xkh, wqh, wkh, wvh,
                                         b_q, b_k, b_v, qhp, khp, vhp);

    dim3 agrid(SEQ / 128, BSZ * NH);
    attn_hmma<<<agrid, 256, ATTN_SMEM>>>(qhp, khp, vhp, out);
}